// round 8
// baseline (speedup 1.0000x reference)
#include <cuda_runtime.h>
#include <math.h>

#define BB 2
#define CC 64
#define HH 192
#define WWD 192
#define HWP 36864
#define NHD 4
#define DDIM 16
#define NSS 144
#define NHSS 12
#define SHH 16
#define NW2 97
#define HW2 18624
#define CH2 128
#define THETA 0.7f
#define ATTNSCALE 0.25f
#define BNINV 0.9999950000374997f

// ---------------- scratch ----------------
static __device__ float g_tabc[HH*HH];
static __device__ float g_tabs[HH*HH];
static __device__ float g_cdsum[CC*CC];
static __device__ float g_contrast[BB*CC*HWP];
static __device__ float g_cent[BB*2*CC*NSS];
static __device__ float g_asum[BB*NSS];
static __device__ float g_aff[BB*9*HWP];
static __device__ float g_xn[BB*CC*HWP];     // after k_xattn: reused as xc-relu output
static __device__ float g_q[BB*CC*HWP];
static __device__ float g_k[BB*CC*HWP];
static __device__ float g_v[BB*CC*HWP];
static __device__ float g_lepe[BB*CC*HWP];
static __device__ float g_stoken[BB*NSS*CC];
static __device__ float g_stok[BB*CC*NSS];
static __device__ float g_sout[BB*CC*NSS];
static __device__ float g_x2[BB*CC*HWP];
static __device__ float g_fw[BB*CC*HH*NW2*2];
static __device__ float g_frb[BB*CH2*HW2];
static __device__ float g_frb2[BB*CH2*HW2];
static __device__ float g_fd[BB*CH2*HW2];
static __device__ float g_gh[BB*CC*HH*NW2*2];

// ---------------- twiddle table ----------------
__global__ void k_tab() {
    int t = blockIdx.x * blockDim.x + threadIdx.x;
    if (t >= HH*HH) return;
    int i = t / HH, j = t % HH;
    int r = (i * j) % HH;
    float s, c;
    sincospif(-(float)r / 96.0f, &s, &c);
    g_tabc[t] = c;
    g_tabs[t] = s;
}

__global__ void k_cdsum(const float* __restrict__ cdw) {
    int t = blockIdx.x * blockDim.x + threadIdx.x;
    if (t >= CC*CC) return;
    float s = 0.f;
    #pragma unroll
    for (int k = 0; k < 9; k++) s += cdw[t*9 + k];
    g_cdsum[t] = s;
}

// ---------------- contrast: 16 output channels per block ----------------
__global__ void __launch_bounds__(256) k_contrast(const float* __restrict__ x,
                                                  const float* __restrict__ cdw) {
    int blk = blockIdx.x;
    int chunk = blk % 144;
    int og = (blk / 144) % 4;
    int b  = blk / (144 * 4);
    __shared__ float ws[CC][10][16];
    for (int i = threadIdx.x; i < CC*10*16; i += 256) {
        int o = i % 16;
        int tap = (i / 16) % 10;
        int ci = i / 160;
        int oo = og*16 + o;
        ws[ci][tap][o] = (tap < 9) ? cdw[((size_t)oo*CC + ci)*9 + tap]
                                   : -THETA * g_cdsum[oo*CC + ci];
    }
    __syncthreads();
    int p = chunk * 256 + threadIdx.x;
    int h = p / WWD, w = p % WWD;
    float acc[16];
    #pragma unroll
    for (int o = 0; o < 16; o++) acc[o] = 0.f;
    const float* xb = x + (size_t)b * CC * HWP;
    for (int ci = 0; ci < CC; ci++) {
        const float* xc = xb + (size_t)ci * HWP;
        float xv[10];
        #pragma unroll
        for (int ky = 0; ky < 3; ky++) {
            int hh = h + ky - 1;
            #pragma unroll
            for (int kx = 0; kx < 3; kx++) {
                int ww = w + kx - 1;
                xv[ky*3+kx] = ((unsigned)hh < HH && (unsigned)ww < WWD) ? xc[hh*WWD + ww] : 0.f;
            }
        }
        xv[9] = xv[4];
        #pragma unroll
        for (int tap = 0; tap < 10; tap++) {
            float v = xv[tap];
            const float4* wp = (const float4*)&ws[ci][tap][0];
            #pragma unroll
            for (int q = 0; q < 4; q++) {
                float4 w4 = wp[q];
                acc[q*4+0] += v * w4.x;
                acc[q*4+1] += v * w4.y;
                acc[q*4+2] += v * w4.z;
                acc[q*4+3] += v * w4.w;
            }
        }
    }
    #pragma unroll
    for (int o = 0; o < 16; o++)
        g_contrast[((size_t)b*CC + og*16 + o)*HWP + p] = acc[o];
}

// ---------------- cent init ----------------
__global__ void k_centinit(const float* __restrict__ x) {
    int t = blockIdx.x * 256 + threadIdx.x;
    if (t >= BB*2*CC*NSS) return;
    int s  = t % NSS;
    int ch = (t / NSS) % (2*CC);
    int b  = t / (NSS * 2 * CC);
    const float* src = (ch < CC) ? (x + ((size_t)b*CC + ch)*HWP)
                                 : (g_contrast + ((size_t)b*CC + (ch-CC))*HWP);
    int r0 = s / NHSS, c0 = s % NHSS;
    float acc = 0.f;
    for (int i = 0; i < SHH; i++) {
        const float* row = src + (r0*SHH + i)*WWD + c0*SHH;
        #pragma unroll
        for (int j = 0; j < SHH; j++) acc += row[j];
    }
    g_cent[t] = acc * (1.0f/256.0f);
}

// ---------------- distances + softmax -> aff ----------------
__global__ void k_dist(const float* __restrict__ x) {
    int t = blockIdx.x * 256 + threadIdx.x;
    if (t >= BB*HWP) return;
    int p = t % HWP, b = t / HWP;
    int h = p / WWD, w = p % WWD;
    int r = h / SHH, c = w / SHH;
    float d[9];
    int   cs[9];
    int   val[9];
    #pragma unroll
    for (int j = 0; j < 9; j++) {
        int dy = j/3 - 1, dx = j%3 - 1;
        int rr = r + dy, cc2 = c + dx;
        val[j] = (rr >= 0 && rr < NHSS && cc2 >= 0 && cc2 < NHSS);
        cs[j]  = val[j] ? rr*NHSS + cc2 : 0;
        d[j]   = 0.f;
    }
    const float* cb = g_cent + (size_t)b * 2 * CC * NSS;
    for (int ch = 0; ch < 2*CC; ch++) {
        float pix = (ch < CC) ? x[((size_t)b*CC + ch)*HWP + p]
                              : g_contrast[((size_t)b*CC + ch - CC)*HWP + p];
        float wgt = (ch < CC) ? 1.0f : 10.0f;
        const float* cr = cb + (size_t)ch * NSS;
        #pragma unroll
        for (int j = 0; j < 9; j++) {
            float df = pix - cr[cs[j]];
            d[j] += wgt * df * df;
        }
    }
    float m = 3.0e38f;
    #pragma unroll
    for (int j = 0; j < 9; j++) if (val[j] && d[j] < m) m = d[j];
    float e[9], sum = 0.f;
    #pragma unroll
    for (int j = 0; j < 9; j++) {
        e[j] = val[j] ? __expf(m - d[j]) : 0.f;
        sum += e[j];
    }
    float inv = 1.0f / sum;
    #pragma unroll
    for (int j = 0; j < 9; j++)
        g_aff[((size_t)b*9 + j)*HWP + p] = e[j] * inv;
}

// ---------------- asum ----------------
__global__ void k_asum() {
    int t = blockIdx.x * 128 + threadIdx.x;
    if (t >= BB*NSS) return;
    int s = t % NSS, b = t / NSS;
    int r0 = s / NHSS, c0 = s % NHSS;
    float acc = 0.f;
    for (int dy = -1; dy <= 1; dy++) {
        int r = r0 - dy;
        if ((unsigned)r >= NHSS) continue;
        for (int dx = -1; dx <= 1; dx++) {
            int c = c0 - dx;
            if ((unsigned)c >= NHSS) continue;
            int j = (dy+1)*3 + (dx+1);
            const float* ab = g_aff + ((size_t)b*9 + j)*HWP;
            for (int i = 0; i < SHH; i++) {
                const float* row = ab + (r*SHH + i)*WWD + c*SHH;
                #pragma unroll
                for (int jj = 0; jj < SHH; jj++) acc += row[jj];
            }
        }
    }
    g_asum[t] = acc;
}

// ---------------- cent update ----------------
__global__ void k_centupd(const float* __restrict__ x) {
    int t = blockIdx.x * 256 + threadIdx.x;
    if (t >= BB*2*CC*NSS) return;
    int s  = t % NSS;
    int ch = (t / NSS) % (2*CC);
    int b  = t / (NSS * 2 * CC);
    const float* src = (ch < CC) ? (x + ((size_t)b*CC + ch)*HWP)
                                 : (g_contrast + ((size_t)b*CC + (ch-CC))*HWP);
    int r0 = s / NHSS, c0 = s % NHSS;
    float acc = 0.f;
    for (int dy = -1; dy <= 1; dy++) {
        int r = r0 - dy;
        if ((unsigned)r >= NHSS) continue;
        for (int dx = -1; dx <= 1; dx++) {
            int c = c0 - dx;
            if ((unsigned)c >= NHSS) continue;
            int j = (dy+1)*3 + (dx+1);
            const float* ab = g_aff + ((size_t)b*9 + j)*HWP;
            for (int i = 0; i < SHH; i++) {
                int base = (r*SHH + i)*WWD + c*SHH;
                #pragma unroll
                for (int jj = 0; jj < SHH; jj++)
                    acc += ab[base + jj] * src[base + jj];
            }
        }
    }
    g_cent[t] = acc / (g_asum[(size_t)b*NSS + s] + 1e-16f);
}

// ---------------- LayerNorm ----------------
__global__ void k_lnorm(const float* __restrict__ x, const float* __restrict__ g,
                        const float* __restrict__ bta) {
    int t = blockIdx.x * 256 + threadIdx.x;
    if (t >= BB*HWP) return;
    int p = t % HWP, b = t / HWP;
    const float* xb = x + (size_t)b*CC*HWP + p;
    float sum = 0.f, sq = 0.f;
    for (int ch = 0; ch < CC; ch++) {
        float v = xb[(size_t)ch*HWP];
        sum += v; sq += v*v;
    }
    float mu = sum * (1.0f/CC);
    float var = sq * (1.0f/CC) - mu*mu;
    float rstd = rsqrtf(var + 1e-6f);
    float* ob = g_xn + (size_t)b*CC*HWP + p;
    for (int ch = 0; ch < CC; ch++) {
        float v = xb[(size_t)ch*HWP];
        ob[(size_t)ch*HWP] = (v - mu) * rstd * g[ch] + bta[ch];
    }
}

// ---------------- stoken gather ----------------
__global__ void k_stoken() {
    int t = blockIdx.x * 256 + threadIdx.x;
    if (t >= BB*NSS*CC) return;
    int ch = t % CC;
    int s  = (t / CC) % NSS;
    int b  = t / (CC * NSS);
    const float* src = g_xn + ((size_t)b*CC + ch)*HWP;
    int r0 = s / NHSS, c0 = s % NHSS;
    float acc = 0.f;
    for (int dy = -1; dy <= 1; dy++) {
        int r = r0 - dy;
        if ((unsigned)r >= NHSS) continue;
        for (int dx = -1; dx <= 1; dx++) {
            int c = c0 - dx;
            if ((unsigned)c >= NHSS) continue;
            int j = (dy+1)*3 + (dx+1);
            const float* ab = g_aff + ((size_t)b*9 + j)*HWP;
            for (int i = 0; i < SHH; i++) {
                int base = (r*SHH + i)*WWD + c*SHH;
                #pragma unroll
                for (int jj = 0; jj < SHH; jj++)
                    acc += ab[base + jj] * src[base + jj];
            }
        }
    }
    g_stoken[((size_t)b*NSS + s)*CC + ch] = acc / (g_asum[(size_t)b*NSS + s] + 1e-16f);
}

// ---------------- stok = stoken @ sp_w^T ----------------
__global__ void k_stokmm(const float* __restrict__ spw) {
    int t = blockIdx.x * 256 + threadIdx.x;
    if (t >= BB*CC*NSS) return;
    int s = t % NSS;
    int o = (t / NSS) % CC;
    int b = t / (NSS * CC);
    const float* st = g_stoken + ((size_t)b*NSS + s)*CC;
    const float* w  = spw + o*CC;
    float acc = 0.f;
    #pragma unroll 8
    for (int c = 0; c < CC; c++) acc += w[c] * st[c];
    g_stok[((size_t)b*CC + o)*NSS + s] = acc;
}

// ---------------- q/k/v: 32 outputs per block ----------------
__global__ void __launch_bounds__(256) k_qkv(const float* __restrict__ qw,
                                             const float* __restrict__ kw,
                                             const float* __restrict__ vw) {
    int blk = blockIdx.x;
    int chunk = blk % 144;
    int og = (blk / 144) % 6;
    int b  = blk / (144 * 6);
    __shared__ float ws[CC][32];
    for (int i = threadIdx.x; i < CC*32; i += 256) {
        int o = i % 32, ci = i / 32;
        int oo = og*32 + o;
        const float* wsrc = (oo < 64) ? (qw + oo*CC)
                          : (oo < 128 ? kw + (oo-64)*CC : vw + (oo-128)*CC);
        ws[ci][o] = wsrc[ci];
    }
    __syncthreads();
    int p = chunk * 256 + threadIdx.x;
    const float* xb = g_xn + (size_t)b*CC*HWP + p;
    float acc[32];
    #pragma unroll
    for (int o = 0; o < 32; o++) acc[o] = 0.f;
    for (int ci = 0; ci < CC; ci++) {
        float v = xb[(size_t)ci*HWP];
        const float4* wp = (const float4*)&ws[ci][0];
        #pragma unroll
        for (int q = 0; q < 8; q++) {
            float4 w4 = wp[q];
            acc[q*4+0] += v * w4.x;
            acc[q*4+1] += v * w4.y;
            acc[q*4+2] += v * w4.z;
            acc[q*4+3] += v * w4.w;
        }
    }
    #pragma unroll
    for (int o = 0; o < 32; o++) {
        int oo = og*32 + o;
        float* dst = (oo < 64) ? (g_q + ((size_t)b*64 + oo)*HWP)
                   : (oo < 128 ? (g_k + ((size_t)b*64 + oo-64)*HWP)
                               : (g_v + ((size_t)b*64 + oo-128)*HWP));
        dst[p] = acc[o];
    }
}

// ---------------- lepe: coalesced Tflat write (thread = 16 channels of one pixel) ----------------
__global__ void __launch_bounds__(256) k_lepe(const float* __restrict__ lw,
                                              const float* __restrict__ lb) {
    __shared__ float ws[CC*9];
    __shared__ float bs[CC];
    for (int i = threadIdx.x; i < CC*9; i += 256) ws[i] = lw[i];
    if (threadIdx.x < CC) bs[threadIdx.x] = lb[threadIdx.x];
    __syncthreads();
    int blk = blockIdx.x;
    int pblk = blk % 576;
    int b = blk / 576;
    int cg = threadIdx.x & 3;
    int pl = threadIdx.x >> 2;
    int p = pblk * 64 + pl;
    int h = p / WWD, w = p % WWD;
    int off[9];
    bool vld[9];
    #pragma unroll
    for (int tap = 0; tap < 9; tap++) {
        int ky = tap/3 - 1, kx = tap%3 - 1;
        int hh = h + ky, ww = w + kx;
        vld[tap] = ((unsigned)hh < HH) && ((unsigned)ww < WWD);
        off[tap] = hh*WWD + ww;
    }
    const float* vb = g_v + (size_t)b*CC*HWP;
    float o[16];
    #pragma unroll
    for (int j = 0; j < 16; j++) {
        int c = cg*16 + j;
        const float* vc = vb + (size_t)c*HWP;
        float acc = bs[c];
        #pragma unroll
        for (int tap = 0; tap < 9; tap++)
            if (vld[tap]) acc += vc[off[tap]] * ws[c*9 + tap];
        o[j] = acc;
    }
    float4* dst = (float4*)(g_lepe + (size_t)b*CC*HWP + (size_t)p*CC + cg*16);
    #pragma unroll
    for (int q = 0; q < 4; q++)
        dst[q] = make_float4(o[q*4], o[q*4+1], o[q*4+2], o[q*4+3]);
}

// ---------------- s_attn: no-max softmax, STILE=8 ----------------
#define STILE 8
__global__ void __launch_bounds__(256) k_sattn() {
    int blk = blockIdx.x;
    int sg = blk % (NSS/STILE);
    int hh = (blk / (NSS/STILE)) % NHD;
    int b  = blk / ((NSS/STILE) * NHD);
    int s0 = sg * STILE;
    int tid = threadIdx.x;
    __shared__ float stks[STILE][DDIM];
    if (tid < STILE*DDIM) {
        int si = tid / DDIM, d = tid % DDIM;
        stks[si][d] = g_stok[((size_t)(b*NHD + hh)*DDIM + d)*NSS + s0 + si];
    }
    __syncthreads();
    float l[STILE], acc[STILE][DDIM];
    #pragma unroll
    for (int si = 0; si < STILE; si++) {
        l[si] = 0.f;
        #pragma unroll
        for (int d = 0; d < DDIM; d++) acc[si][d] = 0.f;
    }
    const float* kb = g_k + (size_t)(b*NHD + hh)*DDIM*HWP;
    const float* vb = g_v + (size_t)(b*NHD + hh)*DDIM*HWP;
    for (int p = tid; p < HWP; p += 256) {
        float kd[DDIM], vd[DDIM];
        #pragma unroll
        for (int d = 0; d < DDIM; d++) kd[d] = kb[(size_t)d*HWP + p];
        #pragma unroll
        for (int d = 0; d < DDIM; d++) vd[d] = vb[(size_t)d*HWP + p];
        #pragma unroll
        for (int si = 0; si < STILE; si++) {
            float lg = 0.f;
            #pragma unroll
            for (int d = 0; d < DDIM; d++) lg += kd[d] * stks[si][d];
            float e = __expf(lg * ATTNSCALE);
            l[si] += e;
            #pragma unroll
            for (int d = 0; d < DDIM; d++) acc[si][d] += e * vd[d];
        }
    }
    __shared__ float rl[256], ra[DDIM*256];
    for (int si = 0; si < STILE; si++) {
        rl[tid] = l[si];
        #pragma unroll
        for (int d = 0; d < DDIM; d++) ra[d*256 + tid] = acc[si][d];
        __syncthreads();
        for (int str = 128; str > 0; str >>= 1) {
            if (tid < str) {
                rl[tid] += rl[tid + str];
                #pragma unroll
                for (int d = 0; d < DDIM; d++)
                    ra[d*256 + tid] += ra[d*256 + tid + str];
            }
            __syncthreads();
        }
        if (tid < DDIM)
            g_sout[((size_t)(b*NHD + hh)*DDIM + tid)*NSS + s0 + si] = ra[tid*256] / rl[0];
        __syncthreads();
    }
}

// ---------------- x_attn single-pass + x2 = x + x_out + lepe ----------------
__global__ void __launch_bounds__(256) k_xattn(const float* __restrict__ x) {
    int blk = blockIdx.x;
    int chunk = blk % 144;
    int hh = (blk / 144) % NHD;
    int b  = blk / (144 * NHD);
    int tid = threadIdx.x;
    __shared__ float st[DDIM*NSS];
    __shared__ float so[DDIM*NSS];
    size_t base = (size_t)(b*NHD + hh)*DDIM*NSS;
    for (int i = tid; i < DDIM*NSS; i += 256) {
        st[i] = g_stok[base + i];
        so[i] = g_sout[base + i];
    }
    __syncthreads();
    int p = chunk * 256 + tid;
    float qd[DDIM];
    #pragma unroll
    for (int d = 0; d < DDIM; d++)
        qd[d] = g_q[((size_t)(b*NHD + hh)*DDIM + d)*HWP + p];
    float l = 0.f;
    float acc[DDIM];
    #pragma unroll
    for (int d = 0; d < DDIM; d++) acc[d] = 0.f;
    for (int s = 0; s < NSS; s++) {
        float lg = 0.f;
        #pragma unroll
        for (int d = 0; d < DDIM; d++) lg += qd[d] * st[d*NSS + s];
        float e = __expf(lg * ATTNSCALE);
        l += e;
        #pragma unroll
        for (int d = 0; d < DDIM; d++) acc[d] += e * so[d*NSS + s];
    }
    float invl = 1.0f / l;
    #pragma unroll
    for (int d = 0; d < DDIM; d++) {
        int cch = hh*DDIM + d;
        size_t o = ((size_t)b*CC + cch)*HWP + p;
        g_x2[o] = x[o] + acc[d]*invl + g_lepe[o];
    }
}

// ---------------- xc branch: 32 outputs per block, relu'd into g_xn ----------------
__global__ void __launch_bounds__(256) k_xc(const float* __restrict__ xcw,
                                            const float* __restrict__ xcb,
                                            const float* __restrict__ bn2g,
                                            const float* __restrict__ bn2b) {
    int blk = blockIdx.x;
    int chunk = blk % 144;
    int og = (blk / 144) % 2;
    int b  = blk / (144 * 2);
    __shared__ float ws[CC][32];
    for (int i = threadIdx.x; i < CC*32; i += 256) {
        int o = i % 32, ci = i / 32;
        ws[ci][o] = xcw[(size_t)(og*32 + o)*CC + ci];
    }
    __syncthreads();
    int p = chunk * 256 + threadIdx.x;
    const float* xb = g_x2 + (size_t)b*CC*HWP + p;
    float acc[32];
    #pragma unroll
    for (int o = 0; o < 32; o++) acc[o] = 0.f;
    for (int ci = 0; ci < CC; ci++) {
        float v = xb[(size_t)ci*HWP];
        const float4* wp = (const float4*)&ws[ci][0];
        #pragma unroll
        for (int q = 0; q < 8; q++) {
            float4 w4 = wp[q];
            acc[q*4+0] += v * w4.x;
            acc[q*4+1] += v * w4.y;
            acc[q*4+2] += v * w4.z;
            acc[q*4+3] += v * w4.w;
        }
    }
    #pragma unroll
    for (int o = 0; o < 32; o++) {
        int oo = og*32 + o;
        float xa = (acc[o] + xcb[oo]) * (BNINV * bn2g[oo]) + bn2b[oo];
        g_xn[((size_t)b*CC + oo)*HWP + p] = fmaxf(xa, 0.0f);
    }
}

// ---------------- W-dim rfft, 16 rows per block ----------------
__global__ void k_fftw() {
    int blk = blockIdx.x;
    int hg = blk % 12;
    int c  = (blk / 12) % CC;
    int b  = blk / (12 * CC);
    int h0 = hg * 16;
    __shared__ float rows[16][WWD];
    for (int i = threadIdx.x; i < 16*WWD; i += 128)
        rows[i/WWD][i%WWD] = g_x2[((size_t)b*CC + c)*HWP + (size_t)(h0 + i/WWD)*WWD + i%WWD];
    __syncthreads();
    int k = threadIdx.x;
    if (k >= NW2) return;
    float re[16], im[16];
    #pragma unroll
    for (int r = 0; r < 16; r++) { re[r] = 0.f; im[r] = 0.f; }
    for (int w = 0; w < WWD; w++) {
        float tc = g_tabc[w*HH + k], ts = g_tabs[w*HH + k];
        #pragma unroll
        for (int r = 0; r < 16; r++) {
            float v = rows[r][w];
            re[r] += v * tc;
            im[r] += v * ts;
        }
    }
    #pragma unroll
    for (int r = 0; r < 16; r++) {
        size_t o = (((size_t)(b*CC + c)*HH + h0 + r)*NW2 + k)*2;
        g_fw[o] = re[r]; g_fw[o+1] = im[r];
    }
}

// ---------------- H-dim FFT, even/odd DIT split + BN -> frb ----------------
__global__ void k_ffth(const float* __restrict__ bng, const float* __restrict__ bnb) {
    int blk = blockIdx.x;
    int kg = blk % 13;
    int c  = (blk / 13) % CC;
    int b  = blk / (13 * CC);
    int k0 = kg * 8;
    int t = threadIdx.x; // 0..191
    int isO = (t >= 96);
    int u = isO ? t - 96 : t;
    float re[8], im[8];
    #pragma unroll
    for (int kk = 0; kk < 8; kk++) { re[kk] = 0.f; im[kk] = 0.f; }
    __shared__ float2 stage[32*8];
    for (int hc = 0; hc < 6; hc++) {
        for (int i = threadIdx.x; i < 32*8; i += 192) {
            int hh2 = hc*32 + i/8, kk = i % 8;
            float2 v = make_float2(0.f, 0.f);
            if (k0 + kk < NW2) {
                size_t o = (((size_t)(b*CC + c)*HH + hh2)*NW2 + k0 + kk)*2;
                v.x = g_fw[o]; v.y = g_fw[o+1];
            }
            stage[i] = v;
        }
        __syncthreads();
        for (int hi = isO ? 1 : 0; hi < 32; hi += 2) {
            int h = hc*32 + hi;
            int trow = isO ? (h - 1) : h;
            float tc = g_tabc[trow*HH + u], ts = g_tabs[trow*HH + u];
            #pragma unroll
            for (int kk = 0; kk < 8; kk++) {
                float2 f = stage[hi*8 + kk];
                re[kk] += f.x*tc - f.y*ts;
                im[kk] += f.x*ts + f.y*tc;
            }
        }
        __syncthreads();
    }
    __shared__ float2 EO[192][8];
    #pragma unroll
    for (int kk = 0; kk < 8; kk++) EO[t][kk] = make_float2(re[kk], im[kk]);
    __syncthreads();
    float wc = g_tabc[HH + u], wsn = g_tabs[HH + u];
    float sgn = isO ? -1.f : 1.f;
    const float sc = 1.0f / 192.0f;
    int chR = 2*c, chI = 2*c + 1;
    float gr = BNINV * bng[chR], br = bnb[chR];
    float gi = BNINV * bng[chI], bi = bnb[chI];
    int m = t;
    for (int kk = 0; kk < 8; kk++) {
        int k = k0 + kk;
        if (k >= NW2) break;
        float2 E = EO[u][kk], O = EO[96 + u][kk];
        float orx = O.x*wc - O.y*wsn;
        float ory = O.x*wsn + O.y*wc;
        float Xr = E.x + sgn*orx;
        float Xi = E.y + sgn*ory;
        g_frb[((size_t)(b*CH2 + chR)*HH + m)*NW2 + k] = Xr*sc*gr + br;
        g_frb[((size_t)(b*CH2 + chI)*HH + m)*NW2 + k] = Xi*sc*gi + bi;
    }
}

// ---------------- fpe: depthwise 3x3 + residual ----------------
__global__ void k_fpe(const float* __restrict__ fw, const float* __restrict__ fb) {
    int t = blockIdx.x * 256 + threadIdx.x;
    if (t >= BB*CH2*HW2) return;
    int k  = t % NW2;
    int m  = (t / NW2) % HH;
    int ch = (t / HW2) % CH2;
    const float* base = g_frb + (size_t)(t / HW2) * HW2;
    float acc = fb[ch];
    #pragma unroll
    for (int ky = -1; ky <= 1; ky++) {
        int mm = m + ky;
        if ((unsigned)mm >= HH) continue;
        #pragma unroll
        for (int kx = -1; kx <= 1; kx++) {
            int kk2 = k + kx;
            if ((unsigned)kk2 >= NW2) continue;
            acc += base[mm*NW2 + kk2] * fw[ch*9 + (ky+1)*3 + (kx+1)];
        }
    }
    g_frb2[t] = acc + base[m*NW2 + k];
}

// ---------------- fdc: 32 outputs per block + GELU ----------------
__global__ void __launch_bounds__(256) k_fdc(const float* __restrict__ fw,
                                             const float* __restrict__ fb) {
    int blk = blockIdx.x;
    int chunk = blk % 73;
    int og = (blk / 73) % 4;
    int b  = blk / (73 * 4);
    __shared__ float ws[CH2][32];
    for (int i = threadIdx.x; i < CH2*32; i += 256) {
        int o = i % 32, ci = i / 32;
        ws[ci][o] = fw[(size_t)(og*32 + o)*CH2 + ci];
    }
    __syncthreads();
    int p = chunk * 256 + threadIdx.x;
    if (p >= HW2) return;
    const float* xb = g_frb2 + (size_t)b*CH2*HW2 + p;
    float acc[32];
    #pragma unroll
    for (int o = 0; o < 32; o++) acc[o] = fb[og*32 + o];
    for (int ci = 0; ci < CH2; ci++) {
        float v = xb[(size_t)ci*HW2];
        const float4* wp = (const float4*)&ws[ci][0];
        #pragma unroll
        for (int q = 0; q < 8; q++) {
            float4 w4 = wp[q];
            acc[q*4+0] += v * w4.x;
            acc[q*4+1] += v * w4.y;
            acc[q*4+2] += v * w4.z;
            acc[q*4+3] += v * w4.w;
        }
    }
    #pragma unroll
    for (int o = 0; o < 32; o++) {
        float a = acc[o];
        float gl = 0.5f * a * (1.0f + erff(a * 0.70710678118654752f));
        g_fd[((size_t)b*CH2 + og*32 + o)*HW2 + p] = gl;
    }
}

// ---------------- inverse H-dim FFT, even/odd DIT split ----------------
__global__ void k_invh() {
    int blk = blockIdx.x;
    int kg = blk % 13;
    int c  = (blk / 13) % CC;
    int b  = blk / (13 * CC);
    int k0 = kg * 8;
    int t = threadIdx.x;
    int isO = (t >= 96);
    int u = isO ? t - 96 : t;
    float re[8], im[8];
    #pragma unroll
    for (int kk = 0; kk < 8; kk++) { re[kk] = 0.f; im[kk] = 0.f; }
    const float* fR = g_fd + (size_t)(b*CH2 + 2*c)*HW2;
    const float* fI = g_fd + (size_t)(b*CH2 + 2*c + 1)*HW2;
    __shared__ float2 stage[32*8];
    for (int mc = 0; mc < 6; mc++) {
        for (int i = threadIdx.x; i < 32*8; i += 192) {
            int mm = mc*32 + i/8, kk = i % 8;
            float2 v = make_float2(0.f, 0.f);
            if (k0 + kk < NW2) {
                v.x = fR[mm*NW2 + k0 + kk];
                v.y = fI[mm*NW2 + k0 + kk];
            }
            stage[i] = v;
        }
        __syncthreads();
        for (int mi = isO ? 1 : 0; mi < 32; mi += 2) {
            int mm = mc*32 + mi;
            int trow = isO ? (mm - 1) : mm;
            float tc = g_tabc[trow*HH + u], ts = g_tabs[trow*HH + u];
            #pragma unroll
            for (int kk = 0; kk < 8; kk++) {
                float2 f = stage[mi*8 + kk];
                re[kk] += f.x*tc + f.y*ts;
                im[kk] += f.y*tc - f.x*ts;
            }
        }
        __syncthreads();
    }
    __shared__ float2 AB[192][8];
    #pragma unroll
    for (int kk = 0; kk < 8; kk++) AB[t][kk] = make_float2(re[kk], im[kk]);
    __syncthreads();
    float wc = g_tabc[HH + u], wsn = g_tabs[HH + u];
    float sgn = isO ? -1.f : 1.f;
    int h = t;
    for (int kk = 0; kk < 8; kk++) {
        int k = k0 + kk;
        if (k >= NW2) break;
        float2 A = AB[u][kk], Bv = AB[96 + u][kk];
        float brx = Bv.x*wc + Bv.y*wsn;
        float bry = Bv.y*wc - Bv.x*wsn;
        size_t o = (((size_t)(b*CC + c)*HH + h)*NW2 + k)*2;
        g_gh[o]   = A.x + sgn*brx;
        g_gh[o+1] = A.y + sgn*bry;
    }
}

// ---------------- irfft over W + add xc (precomputed) ----------------
__global__ void k_final(float* __restrict__ out) {
    int blk = blockIdx.x;
    int hg = blk % 24;
    int c  = (blk / 24) % CC;
    int b  = blk / (24 * CC);
    int h0 = hg * 8;
    __shared__ float ghr[8][NW2];
    __shared__ float ghi[8][NW2];
    for (int i = threadIdx.x; i < 8*NW2; i += 192) {
        int r = i / NW2, k = i % NW2;
        size_t o = (((size_t)(b*CC + c)*HH + h0 + r)*NW2 + k)*2;
        ghr[r][k] = g_gh[o];
        ghi[r][k] = g_gh[o+1];
    }
    __syncthreads();
    int w = threadIdx.x;
    float acc[8];
    #pragma unroll
    for (int r = 0; r < 8; r++) acc[r] = 0.f;
    for (int k = 1; k < 96; k++) {
        float tc = g_tabc[k*HH + w], ts = g_tabs[k*HH + w];
        #pragma unroll
        for (int r = 0; r < 8; r++)
            acc[r] += ghr[r][k]*tc + ghi[r][k]*ts;
    }
    float par = (w & 1) ? -1.0f : 1.0f;
    const float* xcb2 = g_xn + ((size_t)b*CC + c)*HWP + (size_t)h0*WWD + w;
    #pragma unroll
    for (int r = 0; r < 8; r++) {
        float of = (ghr[r][0] + ghr[r][96]*par + 2.0f*acc[r]) * (1.0f/192.0f);
        out[((size_t)b*CC + c)*HWP + (size_t)(h0 + r)*WWD + w] = xcb2[r*WWD] + of;
    }
}

// ---------------- launch ----------------
extern "C" void kernel_launch(void* const* d_in, const int* in_sizes, int n_in,
                              void* d_out, int out_size) {
    const float* x    = (const float*)d_in[0];
    const float* cdw  = (const float*)d_in[1];
    const float* lng  = (const float*)d_in[2];
    const float* lnb  = (const float*)d_in[3];
    const float* qw   = (const float*)d_in[4];
    const float* kw   = (const float*)d_in[5];
    const float* vw   = (const float*)d_in[6];
    const float* spw  = (const float*)d_in[7];
    const float* lw   = (const float*)d_in[8];
    const float* lb   = (const float*)d_in[9];
    const float* bng  = (const float*)d_in[10];
    const float* bnb  = (const float*)d_in[11];
    const float* fpew = (const float*)d_in[12];
    const float* fpeb = (const float*)d_in[13];
    const float* fdcw = (const float*)d_in[16];
    const float* fdcb = (const float*)d_in[17];
    const float* xcw  = (const float*)d_in[18];
    const float* xcb  = (const float*)d_in[19];
    const float* bn2g = (const float*)d_in[20];
    const float* bn2b = (const float*)d_in[21];
    float* out = (float*)d_out;

    k_tab<<<144, 256>>>();
    k_cdsum<<<16, 256>>>(cdw);
    k_contrast<<<BB*4*144, 256>>>(x, cdw);
    k_centinit<<<144, 256>>>(x);
    k_dist<<<288, 256>>>(x);
    k_asum<<<3, 128>>>();
    k_centupd<<<144, 256>>>(x);
    k_dist<<<288, 256>>>(x);
    k_asum<<<3, 128>>>();
    k_lnorm<<<288, 256>>>(x, lng, lnb);
    k_stoken<<<72, 256>>>();
    k_stokmm<<<72, 256>>>(spw);
    k_qkv<<<BB*6*144, 256>>>(qw, kw, vw);
    k_lepe<<<BB*576, 256>>>(lw, lb);
    k_sattn<<<BB*NHD*(NSS/STILE), 256>>>();
    k_xattn<<<BB*NHD*144, 256>>>(x);
    k_xc<<<BB*2*144, 256>>>(xcw, xcb, bn2g, bn2b);
    k_fftw<<<BB*CC*12, 128>>>();
    k_ffth<<<BB*CC*13, 192>>>(bng, bnb);
    k_fpe<<<(BB*CH2*HW2 + 255)/256, 256>>>(fpew, fpeb);
    k_fdc<<<BB*4*73, 256>>>(fdcw, fdcb);
    k_invh<<<BB*CC*13, 192>>>();
    k_final<<<BB*CC*24, 192>>>(out);
}

// round 10
// speedup vs baseline: 1.0764x; 1.0764x over previous
#include <cuda_runtime.h>
#include <math.h>

#define BB 2
#define CC 64
#define HH 192
#define WWD 192
#define HWP 36864
#define NHD 4
#define DDIM 16
#define NSS 144
#define NHSS 12
#define SHH 16
#define NW2 97
#define HW2 18624
#define CH2 128
#define THETA 0.7f
#define ATTNSCALE 0.25f
#define BNINV 0.9999950000374997f

typedef unsigned long long u64;
__device__ __forceinline__ u64 pk2(float lo, float hi) {
    u64 r; asm("mov.b64 %0,{%1,%2};" : "=l"(r) : "f"(lo), "f"(hi)); return r;
}
__device__ __forceinline__ float2 upk2(u64 v) {
    float2 f; asm("mov.b64 {%0,%1},%2;" : "=f"(f.x), "=f"(f.y) : "l"(v)); return f;
}
__device__ __forceinline__ u64 ffma2(u64 a, u64 b, u64 c) {
    u64 d; asm("fma.rn.f32x2 %0,%1,%2,%3;" : "=l"(d) : "l"(a), "l"(b), "l"(c)); return d;
}

// ---------------- scratch ----------------
static __device__ float g_tabc[HH*HH];
static __device__ float g_tabs[HH*HH];
static __device__ float g_cdsum[CC*CC];
static __device__ float g_contrast[BB*CC*HWP];
static __device__ float g_cent[BB*2*CC*NSS];
static __device__ float g_asum[BB*NSS];
static __device__ float g_aff[BB*9*HWP];
static __device__ float g_xn[BB*CC*HWP];     // after k_xattn: reused as xc-relu output
static __device__ float g_q[BB*CC*HWP];
static __device__ float g_k[BB*CC*HWP];
static __device__ float g_v[BB*CC*HWP];
static __device__ float g_lepe[BB*CC*HWP];
static __device__ float g_stoken[BB*NSS*CC];
static __device__ float g_stok[BB*CC*NSS];
static __device__ float g_sout[BB*CC*NSS];
static __device__ float g_x2[BB*CC*HWP];
static __device__ float g_fw[BB*CC*HH*NW2*2];
static __device__ float g_frb[BB*CH2*HW2];
static __device__ float g_frb2[BB*CH2*HW2];
static __device__ float g_fd[BB*CH2*HW2];
static __device__ float g_gh[BB*CC*HH*NW2*2];

// ---------------- twiddle table ----------------
__global__ void k_tab() {
    int t = blockIdx.x * blockDim.x + threadIdx.x;
    if (t >= HH*HH) return;
    int i = t / HH, j = t % HH;
    int r = (i * j) % HH;
    float s, c;
    sincospif(-(float)r / 96.0f, &s, &c);
    g_tabc[t] = c;
    g_tabs[t] = s;
}

__global__ void k_cdsum(const float* __restrict__ cdw) {
    int t = blockIdx.x * blockDim.x + threadIdx.x;
    if (t >= CC*CC) return;
    float s = 0.f;
    #pragma unroll
    for (int k = 0; k < 9; k++) s += cdw[t*9 + k];
    g_cdsum[t] = s;
}

// ---------------- contrast: 16 outs/block, packed f32x2 ----------------
__global__ void __launch_bounds__(256) k_contrast(const float* __restrict__ x,
                                                  const float* __restrict__ cdw) {
    int blk = blockIdx.x;
    int chunk = blk % 144;
    int og = (blk / 144) % 4;
    int b  = blk / (144 * 4);
    __shared__ float ws[CC][10][16];
    for (int i = threadIdx.x; i < CC*10*16; i += 256) {
        int o = i % 16;
        int tap = (i / 16) % 10;
        int ci = i / 160;
        int oo = og*16 + o;
        ws[ci][tap][o] = (tap < 9) ? cdw[((size_t)oo*CC + ci)*9 + tap]
                                   : -THETA * g_cdsum[oo*CC + ci];
    }
    __syncthreads();
    int p = chunk * 256 + threadIdx.x;
    int h = p / WWD, w = p % WWD;
    u64 a2[8];
    #pragma unroll
    for (int j = 0; j < 8; j++) a2[j] = 0ull;
    const float* xb = x + (size_t)b * CC * HWP;
    for (int ci = 0; ci < CC; ci++) {
        const float* xc = xb + (size_t)ci * HWP;
        float xv[10];
        #pragma unroll
        for (int ky = 0; ky < 3; ky++) {
            int hh = h + ky - 1;
            #pragma unroll
            for (int kx = 0; kx < 3; kx++) {
                int ww = w + kx - 1;
                xv[ky*3+kx] = ((unsigned)hh < HH && (unsigned)ww < WWD) ? xc[hh*WWD + ww] : 0.f;
            }
        }
        xv[9] = xv[4];
        #pragma unroll
        for (int tap = 0; tap < 10; tap++) {
            u64 vv = pk2(xv[tap], xv[tap]);
            const u64* wp = (const u64*)&ws[ci][tap][0];
            #pragma unroll
            for (int j = 0; j < 8; j++) a2[j] = ffma2(vv, wp[j], a2[j]);
        }
    }
    #pragma unroll
    for (int j = 0; j < 8; j++) {
        float2 f = upk2(a2[j]);
        g_contrast[((size_t)b*CC + og*16 + 2*j  )*HWP + p] = f.x;
        g_contrast[((size_t)b*CC + og*16 + 2*j+1)*HWP + p] = f.y;
    }
}

// ---------------- cent init ----------------
__global__ void k_centinit(const float* __restrict__ x) {
    int t = blockIdx.x * 256 + threadIdx.x;
    if (t >= BB*2*CC*NSS) return;
    int s  = t % NSS;
    int ch = (t / NSS) % (2*CC);
    int b  = t / (NSS * 2 * CC);
    const float* src = (ch < CC) ? (x + ((size_t)b*CC + ch)*HWP)
                                 : (g_contrast + ((size_t)b*CC + (ch-CC))*HWP);
    int r0 = s / NHSS, c0 = s % NHSS;
    float acc = 0.f;
    for (int i = 0; i < SHH; i++) {
        const float* row = src + (r0*SHH + i)*WWD + c0*SHH;
        #pragma unroll
        for (int j = 0; j < SHH; j++) acc += row[j];
    }
    g_cent[t] = acc * (1.0f/256.0f);
}

// ---------------- distances + softmax -> aff ----------------
__global__ void k_dist(const float* __restrict__ x) {
    int t = blockIdx.x * 256 + threadIdx.x;
    if (t >= BB*HWP) return;
    int p = t % HWP, b = t / HWP;
    int h = p / WWD, w = p % WWD;
    int r = h / SHH, c = w / SHH;
    float d[9];
    int   cs[9];
    int   val[9];
    #pragma unroll
    for (int j = 0; j < 9; j++) {
        int dy = j/3 - 1, dx = j%3 - 1;
        int rr = r + dy, cc2 = c + dx;
        val[j] = (rr >= 0 && rr < NHSS && cc2 >= 0 && cc2 < NHSS);
        cs[j]  = val[j] ? rr*NHSS + cc2 : 0;
        d[j]   = 0.f;
    }
    const float* cb = g_cent + (size_t)b * 2 * CC * NSS;
    for (int ch = 0; ch < 2*CC; ch++) {
        float pix = (ch < CC) ? x[((size_t)b*CC + ch)*HWP + p]
                              : g_contrast[((size_t)b*CC + ch - CC)*HWP + p];
        float wgt = (ch < CC) ? 1.0f : 10.0f;
        const float* cr = cb + (size_t)ch * NSS;
        #pragma unroll
        for (int j = 0; j < 9; j++) {
            float df = pix - cr[cs[j]];
            d[j] += wgt * df * df;
        }
    }
    float m = 3.0e38f;
    #pragma unroll
    for (int j = 0; j < 9; j++) if (val[j] && d[j] < m) m = d[j];
    float e[9], sum = 0.f;
    #pragma unroll
    for (int j = 0; j < 9; j++) {
        e[j] = val[j] ? __expf(m - d[j]) : 0.f;
        sum += e[j];
    }
    float inv = 1.0f / sum;
    #pragma unroll
    for (int j = 0; j < 9; j++)
        g_aff[((size_t)b*9 + j)*HWP + p] = e[j] * inv;
}

// ---------------- asum ----------------
__global__ void k_asum() {
    int t = blockIdx.x * 128 + threadIdx.x;
    if (t >= BB*NSS) return;
    int s = t % NSS, b = t / NSS;
    int r0 = s / NHSS, c0 = s % NHSS;
    float acc = 0.f;
    for (int dy = -1; dy <= 1; dy++) {
        int r = r0 - dy;
        if ((unsigned)r >= NHSS) continue;
        for (int dx = -1; dx <= 1; dx++) {
            int c = c0 - dx;
            if ((unsigned)c >= NHSS) continue;
            int j = (dy+1)*3 + (dx+1);
            const float* ab = g_aff + ((size_t)b*9 + j)*HWP;
            for (int i = 0; i < SHH; i++) {
                const float* row = ab + (r*SHH + i)*WWD + c*SHH;
                #pragma unroll
                for (int jj = 0; jj < SHH; jj++) acc += row[jj];
            }
        }
    }
    g_asum[t] = acc;
}

// ---------------- cent update ----------------
__global__ void k_centupd(const float* __restrict__ x) {
    int t = blockIdx.x * 256 + threadIdx.x;
    if (t >= BB*2*CC*NSS) return;
    int s  = t % NSS;
    int ch = (t / NSS) % (2*CC);
    int b  = t / (NSS * 2 * CC);
    const float* src = (ch < CC) ? (x + ((size_t)b*CC + ch)*HWP)
                                 : (g_contrast + ((size_t)b*CC + (ch-CC))*HWP);
    int r0 = s / NHSS, c0 = s % NHSS;
    float acc = 0.f;
    for (int dy = -1; dy <= 1; dy++) {
        int r = r0 - dy;
        if ((unsigned)r >= NHSS) continue;
        for (int dx = -1; dx <= 1; dx++) {
            int c = c0 - dx;
            if ((unsigned)c >= NHSS) continue;
            int j = (dy+1)*3 + (dx+1);
            const float* ab = g_aff + ((size_t)b*9 + j)*HWP;
            for (int i = 0; i < SHH; i++) {
                int base = (r*SHH + i)*WWD + c*SHH;
                #pragma unroll
                for (int jj = 0; jj < SHH; jj++)
                    acc += ab[base + jj] * src[base + jj];
            }
        }
    }
    g_cent[t] = acc / (g_asum[(size_t)b*NSS + s] + 1e-16f);
}

// ---------------- LayerNorm ----------------
__global__ void k_lnorm(const float* __restrict__ x, const float* __restrict__ g,
                        const float* __restrict__ bta) {
    int t = blockIdx.x * 256 + threadIdx.x;
    if (t >= BB*HWP) return;
    int p = t % HWP, b = t / HWP;
    const float* xb = x + (size_t)b*CC*HWP + p;
    float sum = 0.f, sq = 0.f;
    for (int ch = 0; ch < CC; ch++) {
        float v = xb[(size_t)ch*HWP];
        sum += v; sq += v*v;
    }
    float mu = sum * (1.0f/CC);
    float var = sq * (1.0f/CC) - mu*mu;
    float rstd = rsqrtf(var + 1e-6f);
    float* ob = g_xn + (size_t)b*CC*HWP + p;
    for (int ch = 0; ch < CC; ch++) {
        float v = xb[(size_t)ch*HWP];
        ob[(size_t)ch*HWP] = (v - mu) * rstd * g[ch] + bta[ch];
    }
}

// ---------------- stoken gather ----------------
__global__ void k_stoken() {
    int t = blockIdx.x * 256 + threadIdx.x;
    if (t >= BB*NSS*CC) return;
    int ch = t % CC;
    int s  = (t / CC) % NSS;
    int b  = t / (CC * NSS);
    const float* src = g_xn + ((size_t)b*CC + ch)*HWP;
    int r0 = s / NHSS, c0 = s % NHSS;
    float acc = 0.f;
    for (int dy = -1; dy <= 1; dy++) {
        int r = r0 - dy;
        if ((unsigned)r >= NHSS) continue;
        for (int dx = -1; dx <= 1; dx++) {
            int c = c0 - dx;
            if ((unsigned)c >= NHSS) continue;
            int j = (dy+1)*3 + (dx+1);
            const float* ab = g_aff + ((size_t)b*9 + j)*HWP;
            for (int i = 0; i < SHH; i++) {
                int base = (r*SHH + i)*WWD + c*SHH;
                #pragma unroll
                for (int jj = 0; jj < SHH; jj++)
                    acc += ab[base + jj] * src[base + jj];
            }
        }
    }
    g_stoken[((size_t)b*NSS + s)*CC + ch] = acc / (g_asum[(size_t)b*NSS + s] + 1e-16f);
}

// ---------------- stok = stoken @ sp_w^T ----------------
__global__ void k_stokmm(const float* __restrict__ spw) {
    int t = blockIdx.x * 256 + threadIdx.x;
    if (t >= BB*CC*NSS) return;
    int s = t % NSS;
    int o = (t / NSS) % CC;
    int b = t / (NSS * CC);
    const float* st = g_stoken + ((size_t)b*NSS + s)*CC;
    const float* w  = spw + o*CC;
    float acc = 0.f;
    #pragma unroll 8
    for (int c = 0; c < CC; c++) acc += w[c] * st[c];
    g_stok[((size_t)b*CC + o)*NSS + s] = acc;
}

// ---------------- q/k/v: 32 outs/block, packed ----------------
__global__ void __launch_bounds__(256) k_qkv(const float* __restrict__ qw,
                                             const float* __restrict__ kw,
                                             const float* __restrict__ vw) {
    int blk = blockIdx.x;
    int chunk = blk % 144;
    int og = (blk / 144) % 6;
    int b  = blk / (144 * 6);
    __shared__ float ws[CC][32];
    for (int i = threadIdx.x; i < CC*32; i += 256) {
        int o = i % 32, ci = i / 32;
        int oo = og*32 + o;
        const float* wsrc = (oo < 64) ? (qw + oo*CC)
                          : (oo < 128 ? kw + (oo-64)*CC : vw + (oo-128)*CC);
        ws[ci][o] = wsrc[ci];
    }
    __syncthreads();
    int p = chunk * 256 + threadIdx.x;
    const float* xb = g_xn + (size_t)b*CC*HWP + p;
    u64 a2[16];
    #pragma unroll
    for (int j = 0; j < 16; j++) a2[j] = 0ull;
    for (int ci = 0; ci < CC; ci++) {
        float v = xb[(size_t)ci*HWP];
        u64 vv = pk2(v, v);
        const u64* wp = (const u64*)&ws[ci][0];
        #pragma unroll
        for (int j = 0; j < 16; j++) a2[j] = ffma2(vv, wp[j], a2[j]);
    }
    #pragma unroll
    for (int j = 0; j < 16; j++) {
        float2 f = upk2(a2[j]);
        #pragma unroll
        for (int hlf = 0; hlf < 2; hlf++) {
            int oo = og*32 + 2*j + hlf;
            float vv2 = hlf ? f.y : f.x;
            float* dst = (oo < 64) ? (g_q + ((size_t)b*64 + oo)*HWP)
                       : (oo < 128 ? (g_k + ((size_t)b*64 + oo-64)*HWP)
                                   : (g_v + ((size_t)b*64 + oo-128)*HWP));
            dst[p] = vv2;
        }
    }
}

// ---------------- lepe: coalesced Tflat write ----------------
__global__ void __launch_bounds__(256) k_lepe(const float* __restrict__ lw,
                                              const float* __restrict__ lb) {
    __shared__ float ws[CC*9];
    __shared__ float bs[CC];
    for (int i = threadIdx.x; i < CC*9; i += 256) ws[i] = lw[i];
    if (threadIdx.x < CC) bs[threadIdx.x] = lb[threadIdx.x];
    __syncthreads();
    int blk = blockIdx.x;
    int pblk = blk % 576;
    int b = blk / 576;
    int cg = threadIdx.x & 3;
    int pl = threadIdx.x >> 2;
    int p = pblk * 64 + pl;
    int h = p / WWD, w = p % WWD;
    int off[9];
    bool vld[9];
    #pragma unroll
    for (int tap = 0; tap < 9; tap++) {
        int ky = tap/3 - 1, kx = tap%3 - 1;
        int hh = h + ky, ww = w + kx;
        vld[tap] = ((unsigned)hh < HH) && ((unsigned)ww < WWD);
        off[tap] = hh*WWD + ww;
    }
    const float* vb = g_v + (size_t)b*CC*HWP;
    float o[16];
    #pragma unroll
    for (int j = 0; j < 16; j++) {
        int c = cg*16 + j;
        const float* vc = vb + (size_t)c*HWP;
        float acc = bs[c];
        #pragma unroll
        for (int tap = 0; tap < 9; tap++)
            if (vld[tap]) acc += vc[off[tap]] * ws[c*9 + tap];
        o[j] = acc;
    }
    float4* dst = (float4*)(g_lepe + (size_t)b*CC*HWP + (size_t)p*CC + cg*16);
    #pragma unroll
    for (int q = 0; q < 4; q++)
        dst[q] = make_float4(o[q*4], o[q*4+1], o[q*4+2], o[q*4+3]);
}

// ---------------- s_attn: packed, STILE=8 ----------------
#define STILE 8
__global__ void __launch_bounds__(256) k_sattn() {
    int blk = blockIdx.x;
    int sg = blk % (NSS/STILE);
    int hh = (blk / (NSS/STILE)) % NHD;
    int b  = blk / ((NSS/STILE) * NHD);
    int s0 = sg * STILE;
    int tid = threadIdx.x;
    __shared__ u64 stks2[STILE][8];
    if (tid < STILE*8) {
        int si = tid / 8, j = tid % 8;
        size_t base = (size_t)(b*NHD + hh)*DDIM;
        stks2[si][j] = pk2(g_stok[(base + 2*j  )*NSS + s0 + si],
                           g_stok[(base + 2*j+1)*NSS + s0 + si]);
    }
    __syncthreads();
    float l[STILE];
    u64 acc2[STILE][8];
    #pragma unroll
    for (int si = 0; si < STILE; si++) {
        l[si] = 0.f;
        #pragma unroll
        for (int j = 0; j < 8; j++) acc2[si][j] = 0ull;
    }
    const float* kb = g_k + (size_t)(b*NHD + hh)*DDIM*HWP;
    const float* vb = g_v + (size_t)(b*NHD + hh)*DDIM*HWP;
    for (int p = tid; p < HWP; p += 256) {
        u64 kd2[8], vd2[8];
        #pragma unroll
        for (int j = 0; j < 8; j++)
            kd2[j] = pk2(kb[(size_t)(2*j)*HWP + p], kb[(size_t)(2*j+1)*HWP + p]);
        #pragma unroll
        for (int j = 0; j < 8; j++)
            vd2[j] = pk2(vb[(size_t)(2*j)*HWP + p], vb[(size_t)(2*j+1)*HWP + p]);
        #pragma unroll
        for (int si = 0; si < STILE; si++) {
            u64 dp = 0ull;
            #pragma unroll
            for (int j = 0; j < 8; j++) dp = ffma2(kd2[j], stks2[si][j], dp);
            float2 f = upk2(dp);
            float e = __expf((f.x + f.y) * ATTNSCALE);
            l[si] += e;
            u64 ee = pk2(e, e);
            #pragma unroll
            for (int j = 0; j < 8; j++) acc2[si][j] = ffma2(ee, vd2[j], acc2[si][j]);
        }
    }
    __shared__ float rl[256], ra[DDIM*256];
    for (int si = 0; si < STILE; si++) {
        rl[tid] = l[si];
        #pragma unroll
        for (int j = 0; j < 8; j++) {
            float2 f = upk2(acc2[si][j]);
            ra[(2*j  )*256 + tid] = f.x;
            ra[(2*j+1)*256 + tid] = f.y;
        }
        __syncthreads();
        for (int str = 128; str > 0; str >>= 1) {
            if (tid < str) {
                rl[tid] += rl[tid + str];
                #pragma unroll
                for (int d = 0; d < DDIM; d++)
                    ra[d*256 + tid] += ra[d*256 + tid + str];
            }
            __syncthreads();
        }
        if (tid < DDIM)
            g_sout[((size_t)(b*NHD + hh)*DDIM + tid)*NSS + s0 + si] = ra[tid*256] / rl[0];
        __syncthreads();
    }
}

// ---------------- x_attn: packed single-pass + x2 = x + x_out + lepe ----------------
__global__ void __launch_bounds__(256) k_xattn(const float* __restrict__ x) {
    int blk = blockIdx.x;
    int chunk = blk % 144;
    int hh = (blk / 144) % NHD;
    int b  = blk / (144 * NHD);
    int tid = threadIdx.x;
    __shared__ u64 stp[NSS*9];
    __shared__ u64 sop[NSS*9];
    size_t base = (size_t)(b*NHD + hh)*DDIM*NSS;
    for (int i = tid; i < NSS*8; i += 256) {
        int j = i / NSS, s = i % NSS;
        stp[s*9 + j] = pk2(g_stok[base + (2*j)*NSS + s], g_stok[base + (2*j+1)*NSS + s]);
        sop[s*9 + j] = pk2(g_sout[base + (2*j)*NSS + s], g_sout[base + (2*j+1)*NSS + s]);
    }
    __syncthreads();
    int p = chunk * 256 + tid;
    u64 qd2[8];
    #pragma unroll
    for (int j = 0; j < 8; j++)
        qd2[j] = pk2(g_q[((size_t)(b*NHD + hh)*DDIM + 2*j  )*HWP + p],
                     g_q[((size_t)(b*NHD + hh)*DDIM + 2*j+1)*HWP + p]);
    float l = 0.f;
    u64 acc2[8];
    #pragma unroll
    for (int j = 0; j < 8; j++) acc2[j] = 0ull;
    for (int s = 0; s < NSS; s++) {
        u64 dp = 0ull;
        #pragma unroll
        for (int j = 0; j < 8; j++) dp = ffma2(qd2[j], stp[s*9 + j], dp);
        float2 f = upk2(dp);
        float e = __expf((f.x + f.y) * ATTNSCALE);
        l += e;
        u64 ee = pk2(e, e);
        #pragma unroll
        for (int j = 0; j < 8; j++) acc2[j] = ffma2(ee, sop[s*9 + j], acc2[j]);
    }
    float invl = 1.0f / l;
    #pragma unroll
    for (int j = 0; j < 8; j++) {
        float2 f = upk2(acc2[j]);
        #pragma unroll
        for (int hlf = 0; hlf < 2; hlf++) {
            int cch = hh*DDIM + 2*j + hlf;
            size_t o = ((size_t)b*CC + cch)*HWP + p;
            g_x2[o] = x[o] + (hlf ? f.y : f.x)*invl + g_lepe[o];
        }
    }
}

// ---------------- xc branch: 32 outs/block, packed, relu'd into g_xn ----------------
__global__ void __launch_bounds__(256) k_xc(const float* __restrict__ xcw,
                                            const float* __restrict__ xcb,
                                            const float* __restrict__ bn2g,
                                            const float* __restrict__ bn2b) {
    int blk = blockIdx.x;
    int chunk = blk % 144;
    int og = (blk / 144) % 2;
    int b  = blk / (144 * 2);
    __shared__ float ws[CC][32];
    for (int i = threadIdx.x; i < CC*32; i += 256) {
        int o = i % 32, ci = i / 32;
        ws[ci][o] = xcw[(size_t)(og*32 + o)*CC + ci];
    }
    __syncthreads();
    int p = chunk * 256 + threadIdx.x;
    const float* xb = g_x2 + (size_t)b*CC*HWP + p;
    u64 a2[16];
    #pragma unroll
    for (int j = 0; j < 16; j++) a2[j] = 0ull;
    for (int ci = 0; ci < CC; ci++) {
        float v = xb[(size_t)ci*HWP];
        u64 vv = pk2(v, v);
        const u64* wp = (const u64*)&ws[ci][0];
        #pragma unroll
        for (int j = 0; j < 16; j++) a2[j] = ffma2(vv, wp[j], a2[j]);
    }
    #pragma unroll
    for (int j = 0; j < 16; j++) {
        float2 f = upk2(a2[j]);
        #pragma unroll
        for (int hlf = 0; hlf < 2; hlf++) {
            int oo = og*32 + 2*j + hlf;
            float xa = ((hlf ? f.y : f.x) + xcb[oo]) * (BNINV * bn2g[oo]) + bn2b[oo];
            g_xn[((size_t)b*CC + oo)*HWP + p] = fmaxf(xa, 0.0f);
        }
    }
}

// ---------------- W-dim rfft: transposed smem, packed row-pairs ----------------
__global__ void k_fftw() {
    int blk = blockIdx.x;
    int hg = blk % 12;
    int c  = (blk / 12) % CC;
    int b  = blk / (12 * CC);
    int h0 = hg * 16;
    __shared__ float rows[WWD][18]; // [w][r] pitch 18 (8B aligned, low-conflict)
    for (int i = threadIdx.x; i < 16*WWD; i += 128) {
        int r = i / WWD, w = i % WWD;
        rows[w][r] = g_x2[((size_t)b*CC + c)*HWP + (size_t)(h0 + r)*WWD + w];
    }
    __syncthreads();
    int k = threadIdx.x;
    if (k >= NW2) return;
    u64 re2[8], im2[8];
    #pragma unroll
    for (int j = 0; j < 8; j++) { re2[j] = 0ull; im2[j] = 0ull; }
    for (int w = 0; w < WWD; w++) {
        float tc = g_tabc[w*HH + k], ts = g_tabs[w*HH + k];
        u64 tcc = pk2(tc, tc), tss = pk2(ts, ts);
        const u64* vp = (const u64*)&rows[w][0];
        #pragma unroll
        for (int j = 0; j < 8; j++) {
            u64 v2 = vp[j];
            re2[j] = ffma2(v2, tcc, re2[j]);
            im2[j] = ffma2(v2, tss, im2[j]);
        }
    }
    float2* fwp = (float2*)g_fw;
    #pragma unroll
    for (int j = 0; j < 8; j++) {
        float2 fr = upk2(re2[j]), fi = upk2(im2[j]);
        fwp[((size_t)(b*CC + c)*HH + h0 + 2*j  )*NW2 + k] = make_float2(fr.x, fi.x);
        fwp[((size_t)(b*CC + c)*HH + h0 + 2*j+1)*NW2 + k] = make_float2(fr.y, fi.y);
    }
}

// ---------------- H-dim FFT, even/odd DIT split + BN -> frb ----------------
__global__ void k_ffth(const float* __restrict__ bng, const float* __restrict__ bnb) {
    int blk = blockIdx.x;
    int kg = blk % 13;
    int c  = (blk / 13) % CC;
    int b  = blk / (13 * CC);
    int k0 = kg * 8;
    int t = threadIdx.x; // 0..191
    int isO = (t >= 96);
    int u = isO ? t - 96 : t;
    float re[8], im[8];
    #pragma unroll
    for (int kk = 0; kk < 8; kk++) { re[kk] = 0.f; im[kk] = 0.f; }
    __shared__ float2 stage[32*8];
    for (int hc = 0; hc < 6; hc++) {
        for (int i = threadIdx.x; i < 32*8; i += 192) {
            int hh2 = hc*32 + i/8, kk = i % 8;
            float2 v = make_float2(0.f, 0.f);
            if (k0 + kk < NW2) {
                size_t o = (((size_t)(b*CC + c)*HH + hh2)*NW2 + k0 + kk)*2;
                v.x = g_fw[o]; v.y = g_fw[o+1];
            }
            stage[i] = v;
        }
        __syncthreads();
        for (int hi = isO ? 1 : 0; hi < 32; hi += 2) {
            int h = hc*32 + hi;
            int trow = isO ? (h - 1) : h;
            float tc = g_tabc[trow*HH + u], ts = g_tabs[trow*HH + u];
            #pragma unroll
            for (int kk = 0; kk < 8; kk++) {
                float2 f = stage[hi*8 + kk];
                re[kk] += f.x*tc - f.y*ts;
                im[kk] += f.x*ts + f.y*tc;
            }
        }
        __syncthreads();
    }
    __shared__ float2 EO[192][8];
    #pragma unroll
    for (int kk = 0; kk < 8; kk++) EO[t][kk] = make_float2(re[kk], im[kk]);
    __syncthreads();
    float wc = g_tabc[HH + u], wsn = g_tabs[HH + u];
    float sgn = isO ? -1.f : 1.f;
    const float sc = 1.0f / 192.0f;
    int chR = 2*c, chI = 2*c + 1;
    float gr = BNINV * bng[chR], br = bnb[chR];
    float gi = BNINV * bng[chI], bi = bnb[chI];
    int m = t;
    for (int kk = 0; kk < 8; kk++) {
        int k = k0 + kk;
        if (k >= NW2) break;
        float2 E = EO[u][kk], O = EO[96 + u][kk];
        float orx = O.x*wc - O.y*wsn;
        float ory = O.x*wsn + O.y*wc;
        float Xr = E.x + sgn*orx;
        float Xi = E.y + sgn*ory;
        g_frb[((size_t)(b*CH2 + chR)*HH + m)*NW2 + k] = Xr*sc*gr + br;
        g_frb[((size_t)(b*CH2 + chI)*HH + m)*NW2 + k] = Xi*sc*gi + bi;
    }
}

// ---------------- fpe: depthwise 3x3 + residual ----------------
__global__ void k_fpe(const float* __restrict__ fw, const float* __restrict__ fb) {
    int t = blockIdx.x * 256 + threadIdx.x;
    if (t >= BB*CH2*HW2) return;
    int k  = t % NW2;
    int m  = (t / NW2) % HH;
    int ch = (t / HW2) % CH2;
    const float* base = g_frb + (size_t)(t / HW2) * HW2;
    float acc = fb[ch];
    #pragma unroll
    for (int ky = -1; ky <= 1; ky++) {
        int mm = m + ky;
        if ((unsigned)mm >= HH) continue;
        #pragma unroll
        for (int kx = -1; kx <= 1; kx++) {
            int kk2 = k + kx;
            if ((unsigned)kk2 >= NW2) continue;
            acc += base[mm*NW2 + kk2] * fw[ch*9 + (ky+1)*3 + (kx+1)];
        }
    }
    g_frb2[t] = acc + base[m*NW2 + k];
}

// ---------------- fdc: 32 outs/block, packed + GELU ----------------
__global__ void __launch_bounds__(256) k_fdc(const float* __restrict__ fw,
                                             const float* __restrict__ fb) {
    int blk = blockIdx.x;
    int chunk = blk % 73;
    int og = (blk / 73) % 4;
    int b  = blk / (73 * 4);
    __shared__ float ws[CH2][32];
    for (int i = threadIdx.x; i < CH2*32; i += 256) {
        int o = i % 32, ci = i / 32;
        ws[ci][o] = fw[(size_t)(og*32 + o)*CH2 + ci];
    }
    __syncthreads();
    int p = chunk * 256 + threadIdx.x;
    if (p >= HW2) return;
    const float* xb = g_frb2 + (size_t)b*CH2*HW2 + p;
    u64 a2[16];
    #pragma unroll
    for (int j = 0; j < 16; j++) a2[j] = pk2(fb[og*32 + 2*j], fb[og*32 + 2*j+1]);
    for (int ci = 0; ci < CH2; ci++) {
        float v = xb[(size_t)ci*HW2];
        u64 vv = pk2(v, v);
        const u64* wp = (const u64*)&ws[ci][0];
        #pragma unroll
        for (int j = 0; j < 16; j++) a2[j] = ffma2(vv, wp[j], a2[j]);
    }
    #pragma unroll
    for (int j = 0; j < 16; j++) {
        float2 f = upk2(a2[j]);
        float g0 = 0.5f * f.x * (1.0f + erff(f.x * 0.70710678118654752f));
        float g1 = 0.5f * f.y * (1.0f + erff(f.y * 0.70710678118654752f));
        g_fd[((size_t)b*CH2 + og*32 + 2*j  )*HW2 + p] = g0;
        g_fd[((size_t)b*CH2 + og*32 + 2*j+1)*HW2 + p] = g1;
    }
}

// ---------------- inverse H-dim FFT, even/odd DIT split ----------------
__global__ void k_invh() {
    int blk = blockIdx.x;
    int kg = blk % 13;
    int c  = (blk / 13) % CC;
    int b  = blk / (13 * CC);
    int k0 = kg * 8;
    int t = threadIdx.x;
    int isO = (t >= 96);
    int u = isO ? t - 96 : t;
    float re[8], im[8];
    #pragma unroll
    for (int kk = 0; kk < 8; kk++) { re[kk] = 0.f; im[kk] = 0.f; }
    const float* fR = g_fd + (size_t)(b*CH2 + 2*c)*HW2;
    const float* fI = g_fd + (size_t)(b*CH2 + 2*c + 1)*HW2;
    __shared__ float2 stage[32*8];
    for (int mc = 0; mc < 6; mc++) {
        for (int i = threadIdx.x; i < 32*8; i += 192) {
            int mm = mc*32 + i/8, kk = i % 8;
            float2 v = make_float2(0.f, 0.f);
            if (k0 + kk < NW2) {
                v.x = fR[mm*NW2 + k0 + kk];
                v.y = fI[mm*NW2 + k0 + kk];
            }
            stage[i] = v;
        }
        __syncthreads();
        for (int mi = isO ? 1 : 0; mi < 32; mi += 2) {
            int mm = mc*32 + mi;
            int trow = isO ? (mm - 1) : mm;
            float tc = g_tabc[trow*HH + u], ts = g_tabs[trow*HH + u];
            #pragma unroll
            for (int kk = 0; kk < 8; kk++) {
                float2 f = stage[mi*8 + kk];
                re[kk] += f.x*tc + f.y*ts;
                im[kk] += f.y*tc - f.x*ts;
            }
        }
        __syncthreads();
    }
    __shared__ float2 AB[192][8];
    #pragma unroll
    for (int kk = 0; kk < 8; kk++) AB[t][kk] = make_float2(re[kk], im[kk]);
    __syncthreads();
    float wc = g_tabc[HH + u], wsn = g_tabs[HH + u];
    float sgn = isO ? -1.f : 1.f;
    int h = t;
    for (int kk = 0; kk < 8; kk++) {
        int k = k0 + kk;
        if (k >= NW2) break;
        float2 A = AB[u][kk], Bv = AB[96 + u][kk];
        float brx = Bv.x*wc + Bv.y*wsn;
        float bry = Bv.y*wc - Bv.x*wsn;
        size_t o = (((size_t)(b*CC + c)*HH + h)*NW2 + k)*2;
        g_gh[o]   = A.x + sgn*brx;
        g_gh[o+1] = A.y + sgn*bry;
    }
}

// ---------------- irfft over W (packed float2 stage) + add xc ----------------
__global__ void k_final(float* __restrict__ out) {
    int blk = blockIdx.x;
    int hg = blk % 24;
    int c  = (blk / 24) % CC;
    int b  = blk / (24 * CC);
    int h0 = hg * 8;
    __shared__ float2 ghc[8][NW2];
    const float2* ghp = (const float2*)g_gh;
    for (int i = threadIdx.x; i < 8*NW2; i += 192) {
        int r = i / NW2, k = i % NW2;
        ghc[r][k] = ghp[((size_t)(b*CC + c)*HH + h0 + r)*NW2 + k];
    }
    __syncthreads();
    int w = threadIdx.x;
    u64 acc2[8];
    #pragma unroll
    for (int r = 0; r < 8; r++) acc2[r] = 0ull;
    for (int k = 1; k < 96; k++) {
        float tc = g_tabc[k*HH + w], ts = g_tabs[k*HH + w];
        u64 tt = pk2(tc, ts);
        const u64* gp = (const u64*)&ghc[0][0];
        #pragma unroll
        for (int r = 0; r < 8; r++)
            acc2[r] = ffma2(gp[r*NW2 + k], tt, acc2[r]);
    }
    float par = (w & 1) ? -1.0f : 1.0f;
    const float* xcb2 = g_xn + ((size_t)b*CC + c)*HWP + (size_t)h0*WWD + w;
    #pragma unroll
    for (int r = 0; r < 8; r++) {
        float2 f = upk2(acc2[r]);
        float of = (ghc[r][0].x + ghc[r][96].x*par + 2.0f*(f.x + f.y)) * (1.0f/192.0f);
        out[((size_t)b*CC + c)*HWP + (size_t)(h0 + r)*WWD + w] = xcb2[r*WWD] + of;
    }
}

// ---------------- launch ----------------
extern "C" void kernel_launch(void* const* d_in, const int* in_sizes, int n_in,
                              void* d_out, int out_size) {
    const float* x    = (const float*)d_in[0];
    const float* cdw  = (const float*)d_in[1];
    const float* lng  = (const float*)d_in[2];
    const float* lnb  = (const float*)d_in[3];
    const float* qw   = (const float*)d_in[4];
    const float* kw   = (const float*)d_in[5];
    const float* vw   = (const float*)d_in[6];
    const float* spw  = (const float*)d_in[7];
    const float* lw   = (const float*)d_in[8];
    const float* lb   = (const float*)d_in[9];
    const float* bng  = (const float*)d_in[10];
    const float* bnb  = (const float*)d_in[11];
    const float* fpew = (const float*)d_in[12];
    const float* fpeb = (const float*)d_in[13];
    const float* fdcw = (const float*)d_in[16];
    const float* fdcb = (const float*)d_in[17];
    const float* xcw  = (const float*)d_in[18];
    const float* xcb  = (const float*)d_in[19];
    const float* bn2g = (const float*)d_in[20];
    const float* bn2b = (const float*)d_in[21];
    float* out = (float*)d_out;

    k_tab<<<144, 256>>>();
    k_cdsum<<<16, 256>>>(cdw);
    k_contrast<<<BB*4*144, 256>>>(x, cdw);
    k_centinit<<<144, 256>>>(x);
    k_dist<<<288, 256>>>(x);
    k_asum<<<3, 128>>>();
    k_centupd<<<144, 256>>>(x);
    k_dist<<<288, 256>>>(x);
    k_asum<<<3, 128>>>();
    k_lnorm<<<288, 256>>>(x, lng, lnb);
    k_stoken<<<72, 256>>>();
    k_stokmm<<<72, 256>>>(spw);
    k_qkv<<<BB*6*144, 256>>>(qw, kw, vw);
    k_lepe<<<BB*576, 256>>>(lw, lb);
    k_sattn<<<BB*NHD*(NSS/STILE), 256>>>();
    k_xattn<<<BB*NHD*144, 256>>>(x);
    k_xc<<<BB*2*144, 256>>>(xcw, xcb, bn2g, bn2b);
    k_fftw<<<BB*CC*12, 128>>>();
    k_ffth<<<BB*CC*13, 192>>>(bng, bnb);
    k_fpe<<<(BB*CH2*HW2 + 255)/256, 256>>>(fpew, fpeb);
    k_fdc<<<BB*4*73, 256>>>(fdcw, fdcb);
    k_invh<<<BB*CC*13, 192>>>();
    k_final<<<BB*CC*24, 192>>>(out);
}

// round 11
// speedup vs baseline: 1.0771x; 1.0007x over previous
#include <cuda_runtime.h>
#include <math.h>

#define BB 2
#define CC 64
#define HH 192
#define WWD 192
#define HWP 36864
#define NHD 4
#define DDIM 16
#define NSS 144
#define NHSS 12
#define SHH 16
#define NW2 97
#define HW2 18624
#define CH2 128
#define THETA 0.7f
#define ATTNSCALE 0.25f
#define BNINV 0.9999950000374997f

typedef unsigned long long u64;
__device__ __forceinline__ u64 pk2(float lo, float hi) {
    u64 r; asm("mov.b64 %0,{%1,%2};" : "=l"(r) : "f"(lo), "f"(hi)); return r;
}
__device__ __forceinline__ float2 upk2(u64 v) {
    float2 f; asm("mov.b64 {%0,%1},%2;" : "=f"(f.x), "=f"(f.y) : "l"(v)); return f;
}
__device__ __forceinline__ u64 ffma2(u64 a, u64 b, u64 c) {
    u64 d; asm("fma.rn.f32x2 %0,%1,%2,%3;" : "=l"(d) : "l"(a), "l"(b), "l"(c)); return d;
}

// ---------------- scratch ----------------
static __device__ float g_tabc[HH*HH];
static __device__ float g_tabs[HH*HH];
static __device__ float g_cdsum[CC*CC];
static __device__ float g_contrast[BB*CC*HWP];
static __device__ float g_cent[BB*2*CC*NSS];
static __device__ float g_asum[BB*NSS];
static __device__ float g_aff[BB*9*HWP];
static __device__ float g_xn[BB*CC*HWP];     // after k_xattn: reused as xc-relu output
static __device__ float g_q[BB*CC*HWP];
static __device__ float g_k[BB*CC*HWP];
static __device__ float g_v[BB*CC*HWP];
static __device__ float g_lepe[BB*CC*HWP];
static __device__ float g_stoken[BB*NSS*CC];
static __device__ float g_stok[BB*CC*NSS];
static __device__ float g_sout[BB*CC*NSS];
static __device__ float g_x2[BB*CC*HWP];
static __device__ float g_fw[BB*CC*HH*NW2*2];
static __device__ float g_frb[BB*CH2*HW2];
static __device__ float g_frb2[BB*CH2*HW2];
static __device__ float g_fd[BB*CH2*HW2];
static __device__ float g_gh[BB*CC*HH*NW2*2];

// ---------------- twiddle table ----------------
__global__ void k_tab() {
    int t = blockIdx.x * blockDim.x + threadIdx.x;
    if (t >= HH*HH) return;
    int i = t / HH, j = t % HH;
    int r = (i * j) % HH;
    float s, c;
    sincospif(-(float)r / 96.0f, &s, &c);
    g_tabc[t] = c;
    g_tabs[t] = s;
}

__global__ void k_cdsum(const float* __restrict__ cdw) {
    int t = blockIdx.x * blockDim.x + threadIdx.x;
    if (t >= CC*CC) return;
    float s = 0.f;
    #pragma unroll
    for (int k = 0; k < 9; k++) s += cdw[t*9 + k];
    g_cdsum[t] = s;
}

// ---------------- contrast: 16 outs/block, packed f32x2 ----------------
__global__ void __launch_bounds__(256) k_contrast(const float* __restrict__ x,
                                                  const float* __restrict__ cdw) {
    int blk = blockIdx.x;
    int chunk = blk % 144;
    int og = (blk / 144) % 4;
    int b  = blk / (144 * 4);
    __shared__ float ws[CC][10][16];
    for (int i = threadIdx.x; i < CC*10*16; i += 256) {
        int o = i % 16;
        int tap = (i / 16) % 10;
        int ci = i / 160;
        int oo = og*16 + o;
        ws[ci][tap][o] = (tap < 9) ? cdw[((size_t)oo*CC + ci)*9 + tap]
                                   : -THETA * g_cdsum[oo*CC + ci];
    }
    __syncthreads();
    int p = chunk * 256 + threadIdx.x;
    int h = p / WWD, w = p % WWD;
    u64 a2[8];
    #pragma unroll
    for (int j = 0; j < 8; j++) a2[j] = 0ull;
    const float* xb = x + (size_t)b * CC * HWP;
    for (int ci = 0; ci < CC; ci++) {
        const float* xc = xb + (size_t)ci * HWP;
        float xv[10];
        #pragma unroll
        for (int ky = 0; ky < 3; ky++) {
            int hh = h + ky - 1;
            #pragma unroll
            for (int kx = 0; kx < 3; kx++) {
                int ww = w + kx - 1;
                xv[ky*3+kx] = ((unsigned)hh < HH && (unsigned)ww < WWD) ? xc[hh*WWD + ww] : 0.f;
            }
        }
        xv[9] = xv[4];
        #pragma unroll
        for (int tap = 0; tap < 10; tap++) {
            u64 vv = pk2(xv[tap], xv[tap]);
            const u64* wp = (const u64*)&ws[ci][tap][0];
            #pragma unroll
            for (int j = 0; j < 8; j++) a2[j] = ffma2(vv, wp[j], a2[j]);
        }
    }
    #pragma unroll
    for (int j = 0; j < 8; j++) {
        float2 f = upk2(a2[j]);
        g_contrast[((size_t)b*CC + og*16 + 2*j  )*HWP + p] = f.x;
        g_contrast[((size_t)b*CC + og*16 + 2*j+1)*HWP + p] = f.y;
    }
}

// ---------------- cent init ----------------
__global__ void k_centinit(const float* __restrict__ x) {
    int t = blockIdx.x * 256 + threadIdx.x;
    if (t >= BB*2*CC*NSS) return;
    int s  = t % NSS;
    int ch = (t / NSS) % (2*CC);
    int b  = t / (NSS * 2 * CC);
    const float* src = (ch < CC) ? (x + ((size_t)b*CC + ch)*HWP)
                                 : (g_contrast + ((size_t)b*CC + (ch-CC))*HWP);
    int r0 = s / NHSS, c0 = s % NHSS;
    float acc = 0.f;
    for (int i = 0; i < SHH; i++) {
        const float* row = src + (r0*SHH + i)*WWD + c0*SHH;
        #pragma unroll
        for (int j = 0; j < SHH; j++) acc += row[j];
    }
    g_cent[t] = acc * (1.0f/256.0f);
}

// ---------------- distances + softmax -> aff ----------------
__global__ void k_dist(const float* __restrict__ x) {
    int t = blockIdx.x * 256 + threadIdx.x;
    if (t >= BB*HWP) return;
    int p = t % HWP, b = t / HWP;
    int h = p / WWD, w = p % WWD;
    int r = h / SHH, c = w / SHH;
    float d[9];
    int   cs[9];
    int   val[9];
    #pragma unroll
    for (int j = 0; j < 9; j++) {
        int dy = j/3 - 1, dx = j%3 - 1;
        int rr = r + dy, cc2 = c + dx;
        val[j] = (rr >= 0 && rr < NHSS && cc2 >= 0 && cc2 < NHSS);
        cs[j]  = val[j] ? rr*NHSS + cc2 : 0;
        d[j]   = 0.f;
    }
    const float* cb = g_cent + (size_t)b * 2 * CC * NSS;
    for (int ch = 0; ch < 2*CC; ch++) {
        float pix = (ch < CC) ? x[((size_t)b*CC + ch)*HWP + p]
                              : g_contrast[((size_t)b*CC + ch - CC)*HWP + p];
        float wgt = (ch < CC) ? 1.0f : 10.0f;
        const float* cr = cb + (size_t)ch * NSS;
        #pragma unroll
        for (int j = 0; j < 9; j++) {
            float df = pix - cr[cs[j]];
            d[j] += wgt * df * df;
        }
    }
    float m = 3.0e38f;
    #pragma unroll
    for (int j = 0; j < 9; j++) if (val[j] && d[j] < m) m = d[j];
    float e[9], sum = 0.f;
    #pragma unroll
    for (int j = 0; j < 9; j++) {
        e[j] = val[j] ? __expf(m - d[j]) : 0.f;
        sum += e[j];
    }
    float inv = 1.0f / sum;
    #pragma unroll
    for (int j = 0; j < 9; j++)
        g_aff[((size_t)b*9 + j)*HWP + p] = e[j] * inv;
}

// ---------------- asum ----------------
__global__ void k_asum() {
    int t = blockIdx.x * 128 + threadIdx.x;
    if (t >= BB*NSS) return;
    int s = t % NSS, b = t / NSS;
    int r0 = s / NHSS, c0 = s % NHSS;
    float acc = 0.f;
    for (int dy = -1; dy <= 1; dy++) {
        int r = r0 - dy;
        if ((unsigned)r >= NHSS) continue;
        for (int dx = -1; dx <= 1; dx++) {
            int c = c0 - dx;
            if ((unsigned)c >= NHSS) continue;
            int j = (dy+1)*3 + (dx+1);
            const float* ab = g_aff + ((size_t)b*9 + j)*HWP;
            for (int i = 0; i < SHH; i++) {
                const float* row = ab + (r*SHH + i)*WWD + c*SHH;
                #pragma unroll
                for (int jj = 0; jj < SHH; jj++) acc += row[jj];
            }
        }
    }
    g_asum[t] = acc;
}

// ---------------- cent update ----------------
__global__ void k_centupd(const float* __restrict__ x) {
    int t = blockIdx.x * 256 + threadIdx.x;
    if (t >= BB*2*CC*NSS) return;
    int s  = t % NSS;
    int ch = (t / NSS) % (2*CC);
    int b  = t / (NSS * 2 * CC);
    const float* src = (ch < CC) ? (x + ((size_t)b*CC + ch)*HWP)
                                 : (g_contrast + ((size_t)b*CC + (ch-CC))*HWP);
    int r0 = s / NHSS, c0 = s % NHSS;
    float acc = 0.f;
    for (int dy = -1; dy <= 1; dy++) {
        int r = r0 - dy;
        if ((unsigned)r >= NHSS) continue;
        for (int dx = -1; dx <= 1; dx++) {
            int c = c0 - dx;
            if ((unsigned)c >= NHSS) continue;
            int j = (dy+1)*3 + (dx+1);
            const float* ab = g_aff + ((size_t)b*9 + j)*HWP;
            for (int i = 0; i < SHH; i++) {
                int base = (r*SHH + i)*WWD + c*SHH;
                #pragma unroll
                for (int jj = 0; jj < SHH; jj++)
                    acc += ab[base + jj] * src[base + jj];
            }
        }
    }
    g_cent[t] = acc / (g_asum[(size_t)b*NSS + s] + 1e-16f);
}

// ---------------- LayerNorm ----------------
__global__ void k_lnorm(const float* __restrict__ x, const float* __restrict__ g,
                        const float* __restrict__ bta) {
    int t = blockIdx.x * 256 + threadIdx.x;
    if (t >= BB*HWP) return;
    int p = t % HWP, b = t / HWP;
    const float* xb = x + (size_t)b*CC*HWP + p;
    float sum = 0.f, sq = 0.f;
    for (int ch = 0; ch < CC; ch++) {
        float v = xb[(size_t)ch*HWP];
        sum += v; sq += v*v;
    }
    float mu = sum * (1.0f/CC);
    float var = sq * (1.0f/CC) - mu*mu;
    float rstd = rsqrtf(var + 1e-6f);
    float* ob = g_xn + (size_t)b*CC*HWP + p;
    for (int ch = 0; ch < CC; ch++) {
        float v = xb[(size_t)ch*HWP];
        ob[(size_t)ch*HWP] = (v - mu) * rstd * g[ch] + bta[ch];
    }
}

// ---------------- stoken gather ----------------
__global__ void k_stoken() {
    int t = blockIdx.x * 256 + threadIdx.x;
    if (t >= BB*NSS*CC) return;
    int ch = t % CC;
    int s  = (t / CC) % NSS;
    int b  = t / (CC * NSS);
    const float* src = g_xn + ((size_t)b*CC + ch)*HWP;
    int r0 = s / NHSS, c0 = s % NHSS;
    float acc = 0.f;
    for (int dy = -1; dy <= 1; dy++) {
        int r = r0 - dy;
        if ((unsigned)r >= NHSS) continue;
        for (int dx = -1; dx <= 1; dx++) {
            int c = c0 - dx;
            if ((unsigned)c >= NHSS) continue;
            int j = (dy+1)*3 + (dx+1);
            const float* ab = g_aff + ((size_t)b*9 + j)*HWP;
            for (int i = 0; i < SHH; i++) {
                int base = (r*SHH + i)*WWD + c*SHH;
                #pragma unroll
                for (int jj = 0; jj < SHH; jj++)
                    acc += ab[base + jj] * src[base + jj];
            }
        }
    }
    g_stoken[((size_t)b*NSS + s)*CC + ch] = acc / (g_asum[(size_t)b*NSS + s] + 1e-16f);
}

// ---------------- stok = stoken @ sp_w^T ----------------
__global__ void k_stokmm(const float* __restrict__ spw) {
    int t = blockIdx.x * 256 + threadIdx.x;
    if (t >= BB*CC*NSS) return;
    int s = t % NSS;
    int o = (t / NSS) % CC;
    int b = t / (NSS * CC);
    const float* st = g_stoken + ((size_t)b*NSS + s)*CC;
    const float* w  = spw + o*CC;
    float acc = 0.f;
    #pragma unroll 8
    for (int c = 0; c < CC; c++) acc += w[c] * st[c];
    g_stok[((size_t)b*CC + o)*NSS + s] = acc;
}

// ---------------- q/k/v: 32 outs/block, packed ----------------
__global__ void __launch_bounds__(256) k_qkv(const float* __restrict__ qw,
                                             const float* __restrict__ kw,
                                             const float* __restrict__ vw) {
    int blk = blockIdx.x;
    int chunk = blk % 144;
    int og = (blk / 144) % 6;
    int b  = blk / (144 * 6);
    __shared__ float ws[CC][32];
    for (int i = threadIdx.x; i < CC*32; i += 256) {
        int o = i % 32, ci = i / 32;
        int oo = og*32 + o;
        const float* wsrc = (oo < 64) ? (qw + oo*CC)
                          : (oo < 128 ? kw + (oo-64)*CC : vw + (oo-128)*CC);
        ws[ci][o] = wsrc[ci];
    }
    __syncthreads();
    int p = chunk * 256 + threadIdx.x;
    const float* xb = g_xn + (size_t)b*CC*HWP + p;
    u64 a2[16];
    #pragma unroll
    for (int j = 0; j < 16; j++) a2[j] = 0ull;
    for (int ci = 0; ci < CC; ci++) {
        float v = xb[(size_t)ci*HWP];
        u64 vv = pk2(v, v);
        const u64* wp = (const u64*)&ws[ci][0];
        #pragma unroll
        for (int j = 0; j < 16; j++) a2[j] = ffma2(vv, wp[j], a2[j]);
    }
    #pragma unroll
    for (int j = 0; j < 16; j++) {
        float2 f = upk2(a2[j]);
        #pragma unroll
        for (int hlf = 0; hlf < 2; hlf++) {
            int oo = og*32 + 2*j + hlf;
            float vv2 = hlf ? f.y : f.x;
            float* dst = (oo < 64) ? (g_q + ((size_t)b*64 + oo)*HWP)
                       : (oo < 128 ? (g_k + ((size_t)b*64 + oo-64)*HWP)
                                   : (g_v + ((size_t)b*64 + oo-128)*HWP));
            dst[p] = vv2;
        }
    }
}

// ---------------- lepe: coalesced Tflat write ----------------
__global__ void __launch_bounds__(256) k_lepe(const float* __restrict__ lw,
                                              const float* __restrict__ lb) {
    __shared__ float ws[CC*9];
    __shared__ float bs[CC];
    for (int i = threadIdx.x; i < CC*9; i += 256) ws[i] = lw[i];
    if (threadIdx.x < CC) bs[threadIdx.x] = lb[threadIdx.x];
    __syncthreads();
    int blk = blockIdx.x;
    int pblk = blk % 576;
    int b = blk / 576;
    int cg = threadIdx.x & 3;
    int pl = threadIdx.x >> 2;
    int p = pblk * 64 + pl;
    int h = p / WWD, w = p % WWD;
    int off[9];
    bool vld[9];
    #pragma unroll
    for (int tap = 0; tap < 9; tap++) {
        int ky = tap/3 - 1, kx = tap%3 - 1;
        int hh = h + ky, ww = w + kx;
        vld[tap] = ((unsigned)hh < HH) && ((unsigned)ww < WWD);
        off[tap] = hh*WWD + ww;
    }
    const float* vb = g_v + (size_t)b*CC*HWP;
    float o[16];
    #pragma unroll
    for (int j = 0; j < 16; j++) {
        int c = cg*16 + j;
        const float* vc = vb + (size_t)c*HWP;
        float acc = bs[c];
        #pragma unroll
        for (int tap = 0; tap < 9; tap++)
            if (vld[tap]) acc += vc[off[tap]] * ws[c*9 + tap];
        o[j] = acc;
    }
    float4* dst = (float4*)(g_lepe + (size_t)b*CC*HWP + (size_t)p*CC + cg*16);
    #pragma unroll
    for (int q = 0; q < 4; q++)
        dst[q] = make_float4(o[q*4], o[q*4+1], o[q*4+2], o[q*4+3]);
}

// ---------------- s_attn: packed, STILE=8 ----------------
#define STILE 8
__global__ void __launch_bounds__(256) k_sattn() {
    int blk = blockIdx.x;
    int sg = blk % (NSS/STILE);
    int hh = (blk / (NSS/STILE)) % NHD;
    int b  = blk / ((NSS/STILE) * NHD);
    int s0 = sg * STILE;
    int tid = threadIdx.x;
    __shared__ u64 stks2[STILE][8];
    if (tid < STILE*8) {
        int si = tid / 8, j = tid % 8;
        size_t base = (size_t)(b*NHD + hh)*DDIM;
        stks2[si][j] = pk2(g_stok[(base + 2*j  )*NSS + s0 + si],
                           g_stok[(base + 2*j+1)*NSS + s0 + si]);
    }
    __syncthreads();
    float l[STILE];
    u64 acc2[STILE][8];
    #pragma unroll
    for (int si = 0; si < STILE; si++) {
        l[si] = 0.f;
        #pragma unroll
        for (int j = 0; j < 8; j++) acc2[si][j] = 0ull;
    }
    const float* kb = g_k + (size_t)(b*NHD + hh)*DDIM*HWP;
    const float* vb = g_v + (size_t)(b*NHD + hh)*DDIM*HWP;
    for (int p = tid; p < HWP; p += 256) {
        u64 kd2[8], vd2[8];
        #pragma unroll
        for (int j = 0; j < 8; j++)
            kd2[j] = pk2(kb[(size_t)(2*j)*HWP + p], kb[(size_t)(2*j+1)*HWP + p]);
        #pragma unroll
        for (int j = 0; j < 8; j++)
            vd2[j] = pk2(vb[(size_t)(2*j)*HWP + p], vb[(size_t)(2*j+1)*HWP + p]);
        #pragma unroll
        for (int si = 0; si < STILE; si++) {
            u64 dp = 0ull;
            #pragma unroll
            for (int j = 0; j < 8; j++) dp = ffma2(kd2[j], stks2[si][j], dp);
            float2 f = upk2(dp);
            float e = __expf((f.x + f.y) * ATTNSCALE);
            l[si] += e;
            u64 ee = pk2(e, e);
            #pragma unroll
            for (int j = 0; j < 8; j++) acc2[si][j] = ffma2(ee, vd2[j], acc2[si][j]);
        }
    }
    __shared__ float rl[256], ra[DDIM*256];
    for (int si = 0; si < STILE; si++) {
        rl[tid] = l[si];
        #pragma unroll
        for (int j = 0; j < 8; j++) {
            float2 f = upk2(acc2[si][j]);
            ra[(2*j  )*256 + tid] = f.x;
            ra[(2*j+1)*256 + tid] = f.y;
        }
        __syncthreads();
        for (int str = 128; str > 0; str >>= 1) {
            if (tid < str) {
                rl[tid] += rl[tid + str];
                #pragma unroll
                for (int d = 0; d < DDIM; d++)
                    ra[d*256 + tid] += ra[d*256 + tid + str];
            }
            __syncthreads();
        }
        if (tid < DDIM)
            g_sout[((size_t)(b*NHD + hh)*DDIM + tid)*NSS + s0 + si] = ra[tid*256] / rl[0];
        __syncthreads();
    }
}

// ---------------- x_attn: packed single-pass + x2 = x + x_out + lepe ----------------
__global__ void __launch_bounds__(256) k_xattn(const float* __restrict__ x) {
    int blk = blockIdx.x;
    int chunk = blk % 144;
    int hh = (blk / 144) % NHD;
    int b  = blk / (144 * NHD);
    int tid = threadIdx.x;
    __shared__ u64 stp[NSS*9];
    __shared__ u64 sop[NSS*9];
    size_t base = (size_t)(b*NHD + hh)*DDIM*NSS;
    for (int i = tid; i < NSS*8; i += 256) {
        int j = i / NSS, s = i % NSS;
        stp[s*9 + j] = pk2(g_stok[base + (2*j)*NSS + s], g_stok[base + (2*j+1)*NSS + s]);
        sop[s*9 + j] = pk2(g_sout[base + (2*j)*NSS + s], g_sout[base + (2*j+1)*NSS + s]);
    }
    __syncthreads();
    int p = chunk * 256 + tid;
    u64 qd2[8];
    #pragma unroll
    for (int j = 0; j < 8; j++)
        qd2[j] = pk2(g_q[((size_t)(b*NHD + hh)*DDIM + 2*j  )*HWP + p],
                     g_q[((size_t)(b*NHD + hh)*DDIM + 2*j+1)*HWP + p]);
    float l = 0.f;
    u64 acc2[8];
    #pragma unroll
    for (int j = 0; j < 8; j++) acc2[j] = 0ull;
    for (int s = 0; s < NSS; s++) {
        u64 dp = 0ull;
        #pragma unroll
        for (int j = 0; j < 8; j++) dp = ffma2(qd2[j], stp[s*9 + j], dp);
        float2 f = upk2(dp);
        float e = __expf((f.x + f.y) * ATTNSCALE);
        l += e;
        u64 ee = pk2(e, e);
        #pragma unroll
        for (int j = 0; j < 8; j++) acc2[j] = ffma2(ee, sop[s*9 + j], acc2[j]);
    }
    float invl = 1.0f / l;
    #pragma unroll
    for (int j = 0; j < 8; j++) {
        float2 f = upk2(acc2[j]);
        #pragma unroll
        for (int hlf = 0; hlf < 2; hlf++) {
            int cch = hh*DDIM + 2*j + hlf;
            size_t o = ((size_t)b*CC + cch)*HWP + p;
            g_x2[o] = x[o] + (hlf ? f.y : f.x)*invl + g_lepe[o];
        }
    }
}

// ---------------- xc branch: 32 outs/block, packed, relu'd into g_xn ----------------
__global__ void __launch_bounds__(256) k_xc(const float* __restrict__ xcw,
                                            const float* __restrict__ xcb,
                                            const float* __restrict__ bn2g,
                                            const float* __restrict__ bn2b) {
    int blk = blockIdx.x;
    int chunk = blk % 144;
    int og = (blk / 144) % 2;
    int b  = blk / (144 * 2);
    __shared__ float ws[CC][32];
    for (int i = threadIdx.x; i < CC*32; i += 256) {
        int o = i % 32, ci = i / 32;
        ws[ci][o] = xcw[(size_t)(og*32 + o)*CC + ci];
    }
    __syncthreads();
    int p = chunk * 256 + threadIdx.x;
    const float* xb = g_x2 + (size_t)b*CC*HWP + p;
    u64 a2[16];
    #pragma unroll
    for (int j = 0; j < 16; j++) a2[j] = 0ull;
    for (int ci = 0; ci < CC; ci++) {
        float v = xb[(size_t)ci*HWP];
        u64 vv = pk2(v, v);
        const u64* wp = (const u64*)&ws[ci][0];
        #pragma unroll
        for (int j = 0; j < 16; j++) a2[j] = ffma2(vv, wp[j], a2[j]);
    }
    #pragma unroll
    for (int j = 0; j < 16; j++) {
        float2 f = upk2(a2[j]);
        #pragma unroll
        for (int hlf = 0; hlf < 2; hlf++) {
            int oo = og*32 + 2*j + hlf;
            float xa = ((hlf ? f.y : f.x) + xcb[oo]) * (BNINV * bn2g[oo]) + bn2b[oo];
            g_xn[((size_t)b*CC + oo)*HWP + p] = fmaxf(xa, 0.0f);
        }
    }
}

// ---------------- W-dim rfft: transposed smem, packed row-pairs ----------------
__global__ void k_fftw() {
    int blk = blockIdx.x;
    int hg = blk % 12;
    int c  = (blk / 12) % CC;
    int b  = blk / (12 * CC);
    int h0 = hg * 16;
    __shared__ float rows[WWD][18]; // [w][r] pitch 18 (8B aligned, low-conflict)
    for (int i = threadIdx.x; i < 16*WWD; i += 128) {
        int r = i / WWD, w = i % WWD;
        rows[w][r] = g_x2[((size_t)b*CC + c)*HWP + (size_t)(h0 + r)*WWD + w];
    }
    __syncthreads();
    int k = threadIdx.x;
    if (k >= NW2) return;
    u64 re2[8], im2[8];
    #pragma unroll
    for (int j = 0; j < 8; j++) { re2[j] = 0ull; im2[j] = 0ull; }
    for (int w = 0; w < WWD; w++) {
        float tc = g_tabc[w*HH + k], ts = g_tabs[w*HH + k];
        u64 tcc = pk2(tc, tc), tss = pk2(ts, ts);
        const u64* vp = (const u64*)&rows[w][0];
        #pragma unroll
        for (int j = 0; j < 8; j++) {
            u64 v2 = vp[j];
            re2[j] = ffma2(v2, tcc, re2[j]);
            im2[j] = ffma2(v2, tss, im2[j]);
        }
    }
    float2* fwp = (float2*)g_fw;
    #pragma unroll
    for (int j = 0; j < 8; j++) {
        float2 fr = upk2(re2[j]), fi = upk2(im2[j]);
        fwp[((size_t)(b*CC + c)*HH + h0 + 2*j  )*NW2 + k] = make_float2(fr.x, fi.x);
        fwp[((size_t)(b*CC + c)*HH + h0 + 2*j+1)*NW2 + k] = make_float2(fr.y, fi.y);
    }
}

// ---------------- H-dim FFT, even/odd DIT split + BN -> frb ----------------
__global__ void k_ffth(const float* __restrict__ bng, const float* __restrict__ bnb) {
    int blk = blockIdx.x;
    int kg = blk % 13;
    int c  = (blk / 13) % CC;
    int b  = blk / (13 * CC);
    int k0 = kg * 8;
    int t = threadIdx.x; // 0..191
    int isO = (t >= 96);
    int u = isO ? t - 96 : t;
    float re[8], im[8];
    #pragma unroll
    for (int kk = 0; kk < 8; kk++) { re[kk] = 0.f; im[kk] = 0.f; }
    __shared__ float2 stage[32*8];
    for (int hc = 0; hc < 6; hc++) {
        for (int i = threadIdx.x; i < 32*8; i += 192) {
            int hh2 = hc*32 + i/8, kk = i % 8;
            float2 v = make_float2(0.f, 0.f);
            if (k0 + kk < NW2) {
                size_t o = (((size_t)(b*CC + c)*HH + hh2)*NW2 + k0 + kk)*2;
                v.x = g_fw[o]; v.y = g_fw[o+1];
            }
            stage[i] = v;
        }
        __syncthreads();
        for (int hi = isO ? 1 : 0; hi < 32; hi += 2) {
            int h = hc*32 + hi;
            int trow = isO ? (h - 1) : h;
            float tc = g_tabc[trow*HH + u], ts = g_tabs[trow*HH + u];
            #pragma unroll
            for (int kk = 0; kk < 8; kk++) {
                float2 f = stage[hi*8 + kk];
                re[kk] += f.x*tc - f.y*ts;
                im[kk] += f.x*ts + f.y*tc;
            }
        }
        __syncthreads();
    }
    __shared__ float2 EO[192][8];
    #pragma unroll
    for (int kk = 0; kk < 8; kk++) EO[t][kk] = make_float2(re[kk], im[kk]);
    __syncthreads();
    float wc = g_tabc[HH + u], wsn = g_tabs[HH + u];
    float sgn = isO ? -1.f : 1.f;
    const float sc = 1.0f / 192.0f;
    int chR = 2*c, chI = 2*c + 1;
    float gr = BNINV * bng[chR], br = bnb[chR];
    float gi = BNINV * bng[chI], bi = bnb[chI];
    int m = t;
    for (int kk = 0; kk < 8; kk++) {
        int k = k0 + kk;
        if (k >= NW2) break;
        float2 E = EO[u][kk], O = EO[96 + u][kk];
        float orx = O.x*wc - O.y*wsn;
        float ory = O.x*wsn + O.y*wc;
        float Xr = E.x + sgn*orx;
        float Xi = E.y + sgn*ory;
        g_frb[((size_t)(b*CH2 + chR)*HH + m)*NW2 + k] = Xr*sc*gr + br;
        g_frb[((size_t)(b*CH2 + chI)*HH + m)*NW2 + k] = Xi*sc*gi + bi;
    }
}

// ---------------- fpe: depthwise 3x3 + residual ----------------
__global__ void k_fpe(const float* __restrict__ fw, const float* __restrict__ fb) {
    int t = blockIdx.x * 256 + threadIdx.x;
    if (t >= BB*CH2*HW2) return;
    int k  = t % NW2;
    int m  = (t / NW2) % HH;
    int ch = (t / HW2) % CH2;
    const float* base = g_frb + (size_t)(t / HW2) * HW2;
    float acc = fb[ch];
    #pragma unroll
    for (int ky = -1; ky <= 1; ky++) {
        int mm = m + ky;
        if ((unsigned)mm >= HH) continue;
        #pragma unroll
        for (int kx = -1; kx <= 1; kx++) {
            int kk2 = k + kx;
            if ((unsigned)kk2 >= NW2) continue;
            acc += base[mm*NW2 + kk2] * fw[ch*9 + (ky+1)*3 + (kx+1)];
        }
    }
    g_frb2[t] = acc + base[m*NW2 + k];
}

// ---------------- fdc: 32 outs/block, packed + GELU ----------------
__global__ void __launch_bounds__(256) k_fdc(const float* __restrict__ fw,
                                             const float* __restrict__ fb) {
    int blk = blockIdx.x;
    int chunk = blk % 73;
    int og = (blk / 73) % 4;
    int b  = blk / (73 * 4);
    __shared__ float ws[CH2][32];
    for (int i = threadIdx.x; i < CH2*32; i += 256) {
        int o = i % 32, ci = i / 32;
        ws[ci][o] = fw[(size_t)(og*32 + o)*CH2 + ci];
    }
    __syncthreads();
    int p = chunk * 256 + threadIdx.x;
    if (p >= HW2) return;
    const float* xb = g_frb2 + (size_t)b*CH2*HW2 + p;
    u64 a2[16];
    #pragma unroll
    for (int j = 0; j < 16; j++) a2[j] = pk2(fb[og*32 + 2*j], fb[og*32 + 2*j+1]);
    for (int ci = 0; ci < CH2; ci++) {
        float v = xb[(size_t)ci*HW2];
        u64 vv = pk2(v, v);
        const u64* wp = (const u64*)&ws[ci][0];
        #pragma unroll
        for (int j = 0; j < 16; j++) a2[j] = ffma2(vv, wp[j], a2[j]);
    }
    #pragma unroll
    for (int j = 0; j < 16; j++) {
        float2 f = upk2(a2[j]);
        float g0 = 0.5f * f.x * (1.0f + erff(f.x * 0.70710678118654752f));
        float g1 = 0.5f * f.y * (1.0f + erff(f.y * 0.70710678118654752f));
        g_fd[((size_t)b*CH2 + og*32 + 2*j  )*HW2 + p] = g0;
        g_fd[((size_t)b*CH2 + og*32 + 2*j+1)*HW2 + p] = g1;
    }
}

// ---------------- inverse H-dim FFT, even/odd DIT split ----------------
__global__ void k_invh() {
    int blk = blockIdx.x;
    int kg = blk % 13;
    int c  = (blk / 13) % CC;
    int b  = blk / (13 * CC);
    int k0 = kg * 8;
    int t = threadIdx.x;
    int isO = (t >= 96);
    int u = isO ? t - 96 : t;
    float re[8], im[8];
    #pragma unroll
    for (int kk = 0; kk < 8; kk++) { re[kk] = 0.f; im[kk] = 0.f; }
    const float* fR = g_fd + (size_t)(b*CH2 + 2*c)*HW2;
    const float* fI = g_fd + (size_t)(b*CH2 + 2*c + 1)*HW2;
    __shared__ float2 stage[32*8];
    for (int mc = 0; mc < 6; mc++) {
        for (int i = threadIdx.x; i < 32*8; i += 192) {
            int mm = mc*32 + i/8, kk = i % 8;
            float2 v = make_float2(0.f, 0.f);
            if (k0 + kk < NW2) {
                v.x = fR[mm*NW2 + k0 + kk];
                v.y = fI[mm*NW2 + k0 + kk];
            }
            stage[i] = v;
        }
        __syncthreads();
        for (int mi = isO ? 1 : 0; mi < 32; mi += 2) {
            int mm = mc*32 + mi;
            int trow = isO ? (mm - 1) : mm;
            float tc = g_tabc[trow*HH + u], ts = g_tabs[trow*HH + u];
            #pragma unroll
            for (int kk = 0; kk < 8; kk++) {
                float2 f = stage[mi*8 + kk];
                re[kk] += f.x*tc + f.y*ts;
                im[kk] += f.y*tc - f.x*ts;
            }
        }
        __syncthreads();
    }
    __shared__ float2 AB[192][8];
    #pragma unroll
    for (int kk = 0; kk < 8; kk++) AB[t][kk] = make_float2(re[kk], im[kk]);
    __syncthreads();
    float wc = g_tabc[HH + u], wsn = g_tabs[HH + u];
    float sgn = isO ? -1.f : 1.f;
    int h = t;
    for (int kk = 0; kk < 8; kk++) {
        int k = k0 + kk;
        if (k >= NW2) break;
        float2 A = AB[u][kk], Bv = AB[96 + u][kk];
        float brx = Bv.x*wc + Bv.y*wsn;
        float bry = Bv.y*wc - Bv.x*wsn;
        size_t o = (((size_t)(b*CC + c)*HH + h)*NW2 + k)*2;
        g_gh[o]   = A.x + sgn*brx;
        g_gh[o+1] = A.y + sgn*bry;
    }
}

// ---------------- irfft over W (packed float2 stage) + add xc ----------------
__global__ void k_final(float* __restrict__ out) {
    int blk = blockIdx.x;
    int hg = blk % 24;
    int c  = (blk / 24) % CC;
    int b  = blk / (24 * CC);
    int h0 = hg * 8;
    __shared__ float2 ghc[8][NW2];
    const float2* ghp = (const float2*)g_gh;
    for (int i = threadIdx.x; i < 8*NW2; i += 192) {
        int r = i / NW2, k = i % NW2;
        ghc[r][k] = ghp[((size_t)(b*CC + c)*HH + h0 + r)*NW2 + k];
    }
    __syncthreads();
    int w = threadIdx.x;
    u64 acc2[8];
    #pragma unroll
    for (int r = 0; r < 8; r++) acc2[r] = 0ull;
    for (int k = 1; k < 96; k++) {
        float tc = g_tabc[k*HH + w], ts = g_tabs[k*HH + w];
        u64 tt = pk2(tc, ts);
        const u64* gp = (const u64*)&ghc[0][0];
        #pragma unroll
        for (int r = 0; r < 8; r++)
            acc2[r] = ffma2(gp[r*NW2 + k], tt, acc2[r]);
    }
    float par = (w & 1) ? -1.0f : 1.0f;
    const float* xcb2 = g_xn + ((size_t)b*CC + c)*HWP + (size_t)h0*WWD + w;
    #pragma unroll
    for (int r = 0; r < 8; r++) {
        float2 f = upk2(acc2[r]);
        float of = (ghc[r][0].x + ghc[r][96].x*par + 2.0f*(f.x + f.y)) * (1.0f/192.0f);
        out[((size_t)b*CC + c)*HWP + (size_t)(h0 + r)*WWD + w] = xcb2[r*WWD] + of;
    }
}

// ---------------- launch ----------------
extern "C" void kernel_launch(void* const* d_in, const int* in_sizes, int n_in,
                              void* d_out, int out_size) {
    const float* x    = (const float*)d_in[0];
    const float* cdw  = (const float*)d_in[1];
    const float* lng  = (const float*)d_in[2];
    const float* lnb  = (const float*)d_in[3];
    const float* qw   = (const float*)d_in[4];
    const float* kw   = (const float*)d_in[5];
    const float* vw   = (const float*)d_in[6];
    const float* spw  = (const float*)d_in[7];
    const float* lw   = (const float*)d_in[8];
    const float* lb   = (const float*)d_in[9];
    const float* bng  = (const float*)d_in[10];
    const float* bnb  = (const float*)d_in[11];
    const float* fpew = (const float*)d_in[12];
    const float* fpeb = (const float*)d_in[13];
    const float* fdcw = (const float*)d_in[16];
    const float* fdcb = (const float*)d_in[17];
    const float* xcw  = (const float*)d_in[18];
    const float* xcb  = (const float*)d_in[19];
    const float* bn2g = (const float*)d_in[20];
    const float* bn2b = (const float*)d_in[21];
    float* out = (float*)d_out;

    k_tab<<<144, 256>>>();
    k_cdsum<<<16, 256>>>(cdw);
    k_contrast<<<BB*4*144, 256>>>(x, cdw);
    k_centinit<<<144, 256>>>(x);
    k_dist<<<288, 256>>>(x);
    k_asum<<<3, 128>>>();
    k_centupd<<<144, 256>>>(x);
    k_dist<<<288, 256>>>(x);
    k_asum<<<3, 128>>>();
    k_lnorm<<<288, 256>>>(x, lng, lnb);
    k_stoken<<<72, 256>>>();
    k_stokmm<<<72, 256>>>(spw);
    k_qkv<<<BB*6*144, 256>>>(qw, kw, vw);
    k_lepe<<<BB*576, 256>>>(lw, lb);
    k_sattn<<<BB*NHD*(NSS/STILE), 256>>>();
    k_xattn<<<BB*NHD*144, 256>>>(x);
    k_xc<<<BB*2*144, 256>>>(xcw, xcb, bn2g, bn2b);
    k_fftw<<<BB*CC*12, 128>>>();
    k_ffth<<<BB*CC*13, 192>>>(bng, bnb);
    k_fpe<<<(BB*CH2*HW2 + 255)/256, 256>>>(fpew, fpeb);
    k_fdc<<<BB*4*73, 256>>>(fdcw, fdcb);
    k_invh<<<BB*CC*13, 192>>>();
    k_final<<<BB*CC*24, 192>>>(out);
}

// round 12
// speedup vs baseline: 1.5263x; 1.4170x over previous
#include <cuda_runtime.h>
#include <math.h>

#define BB 2
#define CC 64
#define HH 192
#define WWD 192
#define HWP 36864
#define NHD 4
#define DDIM 16
#define NSS 144
#define NHSS 12
#define SHH 16
#define NW2 97
#define HW2 18624
#define CH2 128
#define THETA 0.7f
#define ATTNSCALE 0.25f
#define BNINV 0.9999950000374997f

typedef unsigned long long u64;
__device__ __forceinline__ u64 pk2(float lo, float hi) {
    u64 r; asm("mov.b64 %0,{%1,%2};" : "=l"(r) : "f"(lo), "f"(hi)); return r;
}
__device__ __forceinline__ float2 upk2(u64 v) {
    float2 f; asm("mov.b64 {%0,%1},%2;" : "=f"(f.x), "=f"(f.y) : "l"(v)); return f;
}
__device__ __forceinline__ u64 ffma2(u64 a, u64 b, u64 c) {
    u64 d; asm("fma.rn.f32x2 %0,%1,%2,%3;" : "=l"(d) : "l"(a), "l"(b), "l"(c)); return d;
}

// ---------------- scratch ----------------
static __device__ float g_tabc[HH*HH];
static __device__ float g_tabs[HH*HH];
static __device__ float g_cdsum[CC*CC];
static __device__ float g_contrast[BB*CC*HWP];
static __device__ float g_cent[BB*2*CC*NSS];
static __device__ float g_asum[BB*NSS];
static __device__ float g_aff[BB*9*HWP];
static __device__ float g_xn[BB*CC*HWP];     // after k_xattn: reused as xc-relu output
static __device__ float g_q[BB*CC*HWP];
static __device__ float g_k[BB*CC*HWP];
static __device__ float g_v[BB*CC*HWP];
static __device__ float g_lepe[BB*CC*HWP];
static __device__ float g_stoken[BB*NSS*CC];
static __device__ float g_stok[BB*CC*NSS];
static __device__ float g_sout[BB*CC*NSS];
static __device__ float g_x2[BB*CC*HWP];
static __device__ float g_fw[BB*CC*HH*NW2*2];
static __device__ float g_frb[BB*CH2*HW2];
static __device__ float g_frb2[BB*CH2*HW2];
static __device__ float g_fd[BB*CH2*HW2];
static __device__ float g_gh[BB*CC*HH*NW2*2];
static __device__ float g_dummy;

// ---------------- nop: shifts ncu capture slot onto k_contrast ----------------
__global__ void k_nop() { if (threadIdx.x == 1024) g_dummy = 0.f; }

// ---------------- twiddle table ----------------
__global__ void k_tab() {
    int t = blockIdx.x * blockDim.x + threadIdx.x;
    if (t >= HH*HH) return;
    int i = t / HH, j = t % HH;
    int r = (i * j) % HH;
    float s, c;
    sincospif(-(float)r / 96.0f, &s, &c);
    g_tabc[t] = c;
    g_tabs[t] = s;
}

__global__ void k_cdsum(const float* __restrict__ cdw) {
    int t = blockIdx.x * blockDim.x + threadIdx.x;
    if (t >= CC*CC) return;
    float s = 0.f;
    #pragma unroll
    for (int k = 0; k < 9; k++) s += cdw[t*9 + k];
    g_cdsum[t] = s;
}

// ---------------- contrast: 16 outs/block, packed f32x2 ----------------
__global__ void __launch_bounds__(256) k_contrast(const float* __restrict__ x,
                                                  const float* __restrict__ cdw) {
    int blk = blockIdx.x;
    int chunk = blk % 144;
    int og = (blk / 144) % 4;
    int b  = blk / (144 * 4);
    __shared__ float ws[CC][10][16];
    for (int i = threadIdx.x; i < CC*10*16; i += 256) {
        int o = i % 16;
        int tap = (i / 16) % 10;
        int ci = i / 160;
        int oo = og*16 + o;
        ws[ci][tap][o] = (tap < 9) ? cdw[((size_t)oo*CC + ci)*9 + tap]
                                   : -THETA * g_cdsum[oo*CC + ci];
    }
    __syncthreads();
    int p = chunk * 256 + threadIdx.x;
    int h = p / WWD, w = p % WWD;
    u64 a2[8];
    #pragma unroll
    for (int j = 0; j < 8; j++) a2[j] = 0ull;
    const float* xb = x + (size_t)b * CC * HWP;
    for (int ci = 0; ci < CC; ci++) {
        const float* xc = xb + (size_t)ci * HWP;
        float xv[10];
        #pragma unroll
        for (int ky = 0; ky < 3; ky++) {
            int hh = h + ky - 1;
            #pragma unroll
            for (int kx = 0; kx < 3; kx++) {
                int ww = w + kx - 1;
                xv[ky*3+kx] = ((unsigned)hh < HH && (unsigned)ww < WWD) ? xc[hh*WWD + ww] : 0.f;
            }
        }
        xv[9] = xv[4];
        #pragma unroll
        for (int tap = 0; tap < 10; tap++) {
            u64 vv = pk2(xv[tap], xv[tap]);
            const u64* wp = (const u64*)&ws[ci][tap][0];
            #pragma unroll
            for (int j = 0; j < 8; j++) a2[j] = ffma2(vv, wp[j], a2[j]);
        }
    }
    #pragma unroll
    for (int j = 0; j < 8; j++) {
        float2 f = upk2(a2[j]);
        g_contrast[((size_t)b*CC + og*16 + 2*j  )*HWP + p] = f.x;
        g_contrast[((size_t)b*CC + og*16 + 2*j+1)*HWP + p] = f.y;
    }
}

// ---------------- cent init: float4 gather ----------------
__global__ void k_centinit(const float* __restrict__ x) {
    int t = blockIdx.x * 256 + threadIdx.x;
    if (t >= BB*2*CC*NSS) return;
    int s  = t % NSS;
    int ch = (t / NSS) % (2*CC);
    int b  = t / (NSS * 2 * CC);
    const float* src = (ch < CC) ? (x + ((size_t)b*CC + ch)*HWP)
                                 : (g_contrast + ((size_t)b*CC + (ch-CC))*HWP);
    int r0 = s / NHSS, c0 = s % NHSS;
    const float4* sp = (const float4*)(src + (r0*SHH)*WWD + c0*SHH);
    float acc = 0.f;
    for (int i = 0; i < SHH; i++) {
        #pragma unroll
        for (int jj = 0; jj < 4; jj++) {
            float4 v = sp[i*48 + jj];
            acc += v.x; acc += v.y; acc += v.z; acc += v.w;
        }
    }
    g_cent[t] = acc * (1.0f/256.0f);
}

// ---------------- distances + softmax -> aff ----------------
__global__ void k_dist(const float* __restrict__ x) {
    int t = blockIdx.x * 256 + threadIdx.x;
    if (t >= BB*HWP) return;
    int p = t % HWP, b = t / HWP;
    int h = p / WWD, w = p % WWD;
    int r = h / SHH, c = w / SHH;
    float d[9];
    int   cs[9];
    int   val[9];
    #pragma unroll
    for (int j = 0; j < 9; j++) {
        int dy = j/3 - 1, dx = j%3 - 1;
        int rr = r + dy, cc2 = c + dx;
        val[j] = (rr >= 0 && rr < NHSS && cc2 >= 0 && cc2 < NHSS);
        cs[j]  = val[j] ? rr*NHSS + cc2 : 0;
        d[j]   = 0.f;
    }
    const float* cb = g_cent + (size_t)b * 2 * CC * NSS;
    for (int ch = 0; ch < 2*CC; ch++) {
        float pix = (ch < CC) ? x[((size_t)b*CC + ch)*HWP + p]
                              : g_contrast[((size_t)b*CC + ch - CC)*HWP + p];
        float wgt = (ch < CC) ? 1.0f : 10.0f;
        const float* cr = cb + (size_t)ch * NSS;
        #pragma unroll
        for (int j = 0; j < 9; j++) {
            float df = pix - cr[cs[j]];
            d[j] += wgt * df * df;
        }
    }
    float m = 3.0e38f;
    #pragma unroll
    for (int j = 0; j < 9; j++) if (val[j] && d[j] < m) m = d[j];
    float e[9], sum = 0.f;
    #pragma unroll
    for (int j = 0; j < 9; j++) {
        e[j] = val[j] ? __expf(m - d[j]) : 0.f;
        sum += e[j];
    }
    float inv = 1.0f / sum;
    #pragma unroll
    for (int j = 0; j < 9; j++)
        g_aff[((size_t)b*9 + j)*HWP + p] = e[j] * inv;
}

// ---------------- asum: one warp per (b,s), float4 + shfl ----------------
__global__ void k_asum() {
    int wid = (blockIdx.x * 256 + threadIdx.x) >> 5;
    int lane = threadIdx.x & 31;
    if (wid >= BB*NSS) return;
    int s = wid % NSS, b = wid / NSS;
    int r0 = s / NHSS, c0 = s % NHSS;
    float acc = 0.f;
    for (int dy = -1; dy <= 1; dy++) {
        int r = r0 - dy;
        if ((unsigned)r >= NHSS) continue;
        for (int dx = -1; dx <= 1; dx++) {
            int c = c0 - dx;
            if ((unsigned)c >= NHSS) continue;
            int j = (dy+1)*3 + (dx+1);
            const float4* ab = (const float4*)(g_aff + ((size_t)b*9 + j)*HWP
                                               + (r*SHH)*WWD + c*SHH);
            for (int idx = lane; idx < 64; idx += 32) {
                int i = idx >> 2, jj = idx & 3;
                float4 v = ab[i*48 + jj];
                acc += v.x; acc += v.y; acc += v.z; acc += v.w;
            }
        }
    }
    #pragma unroll
    for (int o = 16; o > 0; o >>= 1) acc += __shfl_down_sync(0xffffffffu, acc, o);
    if (lane == 0) g_asum[wid] = acc;
}

// ---------------- cent update: ch-fastest (aff broadcast), float4 ----------------
__global__ void k_centupd(const float* __restrict__ x) {
    int t = blockIdx.x * 256 + threadIdx.x;
    if (t >= BB*2*CC*NSS) return;
    int ch = t % (2*CC);
    int s  = (t / (2*CC)) % NSS;
    int b  = t / (NSS * 2 * CC);
    const float* src = (ch < CC) ? (x + ((size_t)b*CC + ch)*HWP)
                                 : (g_contrast + ((size_t)b*CC + (ch-CC))*HWP);
    int r0 = s / NHSS, c0 = s % NHSS;
    float acc = 0.f;
    for (int dy = -1; dy <= 1; dy++) {
        int r = r0 - dy;
        if ((unsigned)r >= NHSS) continue;
        for (int dx = -1; dx <= 1; dx++) {
            int c = c0 - dx;
            if ((unsigned)c >= NHSS) continue;
            int j = (dy+1)*3 + (dx+1);
            int pb = (r*SHH)*WWD + c*SHH;
            const float4* ar = (const float4*)(g_aff + ((size_t)b*9 + j)*HWP + pb);
            const float4* sr = (const float4*)(src + pb);
            for (int i = 0; i < SHH; i++) {
                #pragma unroll
                for (int jj = 0; jj < 4; jj++) {
                    float4 a = ar[i*48 + jj];
                    float4 v = sr[i*48 + jj];
                    acc += a.x*v.x; acc += a.y*v.y; acc += a.z*v.z; acc += a.w*v.w;
                }
            }
        }
    }
    g_cent[((size_t)b*2*CC + ch)*NSS + s] = acc / (g_asum[(size_t)b*NSS + s] + 1e-16f);
}

// ---------------- LayerNorm ----------------
__global__ void k_lnorm(const float* __restrict__ x, const float* __restrict__ g,
                        const float* __restrict__ bta) {
    int t = blockIdx.x * 256 + threadIdx.x;
    if (t >= BB*HWP) return;
    int p = t % HWP, b = t / HWP;
    const float* xb = x + (size_t)b*CC*HWP + p;
    float sum = 0.f, sq = 0.f;
    for (int ch = 0; ch < CC; ch++) {
        float v = xb[(size_t)ch*HWP];
        sum += v; sq += v*v;
    }
    float mu = sum * (1.0f/CC);
    float var = sq * (1.0f/CC) - mu*mu;
    float rstd = rsqrtf(var + 1e-6f);
    float* ob = g_xn + (size_t)b*CC*HWP + p;
    for (int ch = 0; ch < CC; ch++) {
        float v = xb[(size_t)ch*HWP];
        ob[(size_t)ch*HWP] = (v - mu) * rstd * g[ch] + bta[ch];
    }
}

// ---------------- stoken gather: ch-fastest (aff broadcast), float4 ----------------
__global__ void k_stoken() {
    int t = blockIdx.x * 256 + threadIdx.x;
    if (t >= BB*NSS*CC) return;
    int ch = t % CC;
    int s  = (t / CC) % NSS;
    int b  = t / (CC * NSS);
    const float* src = g_xn + ((size_t)b*CC + ch)*HWP;
    int r0 = s / NHSS, c0 = s % NHSS;
    float acc = 0.f;
    for (int dy = -1; dy <= 1; dy++) {
        int r = r0 - dy;
        if ((unsigned)r >= NHSS) continue;
        for (int dx = -1; dx <= 1; dx++) {
            int c = c0 - dx;
            if ((unsigned)c >= NHSS) continue;
            int j = (dy+1)*3 + (dx+1);
            int pb = (r*SHH)*WWD + c*SHH;
            const float4* ar = (const float4*)(g_aff + ((size_t)b*9 + j)*HWP + pb);
            const float4* sr = (const float4*)(src + pb);
            for (int i = 0; i < SHH; i++) {
                #pragma unroll
                for (int jj = 0; jj < 4; jj++) {
                    float4 a = ar[i*48 + jj];
                    float4 v = sr[i*48 + jj];
                    acc += a.x*v.x; acc += a.y*v.y; acc += a.z*v.z; acc += a.w*v.w;
                }
            }
        }
    }
    g_stoken[((size_t)b*NSS + s)*CC + ch] = acc / (g_asum[(size_t)b*NSS + s] + 1e-16f);
}

// ---------------- stok = stoken @ sp_w^T ----------------
__global__ void k_stokmm(const float* __restrict__ spw) {
    int t = blockIdx.x * 256 + threadIdx.x;
    if (t >= BB*CC*NSS) return;
    int s = t % NSS;
    int o = (t / NSS) % CC;
    int b = t / (NSS * CC);
    const float* st = g_stoken + ((size_t)b*NSS + s)*CC;
    const float* w  = spw + o*CC;
    float acc = 0.f;
    #pragma unroll 8
    for (int c = 0; c < CC; c++) acc += w[c] * st[c];
    g_stok[((size_t)b*CC + o)*NSS + s] = acc;
}

// ---------------- q/k/v: 32 outs/block, packed ----------------
__global__ void __launch_bounds__(256) k_qkv(const float* __restrict__ qw,
                                             const float* __restrict__ kw,
                                             const float* __restrict__ vw) {
    int blk = blockIdx.x;
    int chunk = blk % 144;
    int og = (blk / 144) % 6;
    int b  = blk / (144 * 6);
    __shared__ float ws[CC][32];
    for (int i = threadIdx.x; i < CC*32; i += 256) {
        int o = i % 32, ci = i / 32;
        int oo = og*32 + o;
        const float* wsrc = (oo < 64) ? (qw + oo*CC)
                          : (oo < 128 ? kw + (oo-64)*CC : vw + (oo-128)*CC);
        ws[ci][o] = wsrc[ci];
    }
    __syncthreads();
    int p = chunk * 256 + threadIdx.x;
    const float* xb = g_xn + (size_t)b*CC*HWP + p;
    u64 a2[16];
    #pragma unroll
    for (int j = 0; j < 16; j++) a2[j] = 0ull;
    for (int ci = 0; ci < CC; ci++) {
        float v = xb[(size_t)ci*HWP];
        u64 vv = pk2(v, v);
        const u64* wp = (const u64*)&ws[ci][0];
        #pragma unroll
        for (int j = 0; j < 16; j++) a2[j] = ffma2(vv, wp[j], a2[j]);
    }
    #pragma unroll
    for (int j = 0; j < 16; j++) {
        float2 f = upk2(a2[j]);
        #pragma unroll
        for (int hlf = 0; hlf < 2; hlf++) {
            int oo = og*32 + 2*j + hlf;
            float vv2 = hlf ? f.y : f.x;
            float* dst = (oo < 64) ? (g_q + ((size_t)b*64 + oo)*HWP)
                       : (oo < 128 ? (g_k + ((size_t)b*64 + oo-64)*HWP)
                                   : (g_v + ((size_t)b*64 + oo-128)*HWP));
            dst[p] = vv2;
        }
    }
}

// ---------------- lepe: coalesced Tflat write ----------------
__global__ void __launch_bounds__(256) k_lepe(const float* __restrict__ lw,
                                              const float* __restrict__ lb) {
    __shared__ float ws[CC*9];
    __shared__ float bs[CC];
    for (int i = threadIdx.x; i < CC*9; i += 256) ws[i] = lw[i];
    if (threadIdx.x < CC) bs[threadIdx.x] = lb[threadIdx.x];
    __syncthreads();
    int blk = blockIdx.x;
    int pblk = blk % 576;
    int b = blk / 576;
    int cg = threadIdx.x & 3;
    int pl = threadIdx.x >> 2;
    int p = pblk * 64 + pl;
    int h = p / WWD, w = p % WWD;
    int off[9];
    bool vld[9];
    #pragma unroll
    for (int tap = 0; tap < 9; tap++) {
        int ky = tap/3 - 1, kx = tap%3 - 1;
        int hh = h + ky, ww = w + kx;
        vld[tap] = ((unsigned)hh < HH) && ((unsigned)ww < WWD);
        off[tap] = hh*WWD + ww;
    }
    const float* vb = g_v + (size_t)b*CC*HWP;
    float o[16];
    #pragma unroll
    for (int j = 0; j < 16; j++) {
        int c = cg*16 + j;
        const float* vc = vb + (size_t)c*HWP;
        float acc = bs[c];
        #pragma unroll
        for (int tap = 0; tap < 9; tap++)
            if (vld[tap]) acc += vc[off[tap]] * ws[c*9 + tap];
        o[j] = acc;
    }
    float4* dst = (float4*)(g_lepe + (size_t)b*CC*HWP + (size_t)p*CC + cg*16);
    #pragma unroll
    for (int q = 0; q < 4; q++)
        dst[q] = make_float4(o[q*4], o[q*4+1], o[q*4+2], o[q*4+3]);
}

// ---------------- s_attn: packed, STILE=8 ----------------
#define STILE 8
__global__ void __launch_bounds__(256) k_sattn() {
    int blk = blockIdx.x;
    int sg = blk % (NSS/STILE);
    int hh = (blk / (NSS/STILE)) % NHD;
    int b  = blk / ((NSS/STILE) * NHD);
    int s0 = sg * STILE;
    int tid = threadIdx.x;
    __shared__ u64 stks2[STILE][8];
    if (tid < STILE*8) {
        int si = tid / 8, j = tid % 8;
        size_t base = (size_t)(b*NHD + hh)*DDIM;
        stks2[si][j] = pk2(g_stok[(base + 2*j  )*NSS + s0 + si],
                           g_stok[(base + 2*j+1)*NSS + s0 + si]);
    }
    __syncthreads();
    float l[STILE];
    u64 acc2[STILE][8];
    #pragma unroll
    for (int si = 0; si < STILE; si++) {
        l[si] = 0.f;
        #pragma unroll
        for (int j = 0; j < 8; j++) acc2[si][j] = 0ull;
    }
    const float* kb = g_k + (size_t)(b*NHD + hh)*DDIM*HWP;
    const float* vb = g_v + (size_t)(b*NHD + hh)*DDIM*HWP;
    for (int p = tid; p < HWP; p += 256) {
        u64 kd2[8], vd2[8];
        #pragma unroll
        for (int j = 0; j < 8; j++)
            kd2[j] = pk2(kb[(size_t)(2*j)*HWP + p], kb[(size_t)(2*j+1)*HWP + p]);
        #pragma unroll
        for (int j = 0; j < 8; j++)
            vd2[j] = pk2(vb[(size_t)(2*j)*HWP + p], vb[(size_t)(2*j+1)*HWP + p]);
        #pragma unroll
        for (int si = 0; si < STILE; si++) {
            u64 dp = 0ull;
            #pragma unroll
            for (int j = 0; j < 8; j++) dp = ffma2(kd2[j], stks2[si][j], dp);
            float2 f = upk2(dp);
            float e = __expf((f.x + f.y) * ATTNSCALE);
            l[si] += e;
            u64 ee = pk2(e, e);
            #pragma unroll
            for (int j = 0; j < 8; j++) acc2[si][j] = ffma2(ee, vd2[j], acc2[si][j]);
        }
    }
    __shared__ float rl[256], ra[DDIM*256];
    for (int si = 0; si < STILE; si++) {
        rl[tid] = l[si];
        #pragma unroll
        for (int j = 0; j < 8; j++) {
            float2 f = upk2(acc2[si][j]);
            ra[(2*j  )*256 + tid] = f.x;
            ra[(2*j+1)*256 + tid] = f.y;
        }
        __syncthreads();
        for (int str = 128; str > 0; str >>= 1) {
            if (tid < str) {
                rl[tid] += rl[tid + str];
                #pragma unroll
                for (int d = 0; d < DDIM; d++)
                    ra[d*256 + tid] += ra[d*256 + tid + str];
            }
            __syncthreads();
        }
        if (tid < DDIM)
            g_sout[((size_t)(b*NHD + hh)*DDIM + tid)*NSS + s0 + si] = ra[tid*256] / rl[0];
        __syncthreads();
    }
}

// ---------------- x_attn: packed single-pass + x2 = x + x_out + lepe ----------------
__global__ void __launch_bounds__(256) k_xattn(const float* __restrict__ x) {
    int blk = blockIdx.x;
    int chunk = blk % 144;
    int hh = (blk / 144) % NHD;
    int b  = blk / (144 * NHD);
    int tid = threadIdx.x;
    __shared__ u64 stp[NSS*9];
    __shared__ u64 sop[NSS*9];
    size_t base = (size_t)(b*NHD + hh)*DDIM*NSS;
    for (int i = tid; i < NSS*8; i += 256) {
        int j = i / NSS, s = i % NSS;
        stp[s*9 + j] = pk2(g_stok[base + (2*j)*NSS + s], g_stok[base + (2*j+1)*NSS + s]);
        sop[s*9 + j] = pk2(g_sout[base + (2*j)*NSS + s], g_sout[base + (2*j+1)*NSS + s]);
    }
    __syncthreads();
    int p = chunk * 256 + tid;
    u64 qd2[8];
    #pragma unroll
    for (int j = 0; j < 8; j++)
        qd2[j] = pk2(g_q[((size_t)(b*NHD + hh)*DDIM + 2*j  )*HWP + p],
                     g_q[((size_t)(b*NHD + hh)*DDIM + 2*j+1)*HWP + p]);
    float l = 0.f;
    u64 acc2[8];
    #pragma unroll
    for (int j = 0; j < 8; j++) acc2[j] = 0ull;
    for (int s = 0; s < NSS; s++) {
        u64 dp = 0ull;
        #pragma unroll
        for (int j = 0; j < 8; j++) dp = ffma2(qd2[j], stp[s*9 + j], dp);
        float2 f = upk2(dp);
        float e = __expf((f.x + f.y) * ATTNSCALE);
        l += e;
        u64 ee = pk2(e, e);
        #pragma unroll
        for (int j = 0; j < 8; j++) acc2[j] = ffma2(ee, sop[s*9 + j], acc2[j]);
    }
    float invl = 1.0f / l;
    #pragma unroll
    for (int j = 0; j < 8; j++) {
        float2 f = upk2(acc2[j]);
        #pragma unroll
        for (int hlf = 0; hlf < 2; hlf++) {
            int cch = hh*DDIM + 2*j + hlf;
            size_t o = ((size_t)b*CC + cch)*HWP + p;
            g_x2[o] = x[o] + (hlf ? f.y : f.x)*invl + g_lepe[o];
        }
    }
}

// ---------------- xc branch: 32 outs/block, packed, relu'd into g_xn ----------------
__global__ void __launch_bounds__(256) k_xc(const float* __restrict__ xcw,
                                            const float* __restrict__ xcb,
                                            const float* __restrict__ bn2g,
                                            const float* __restrict__ bn2b) {
    int blk = blockIdx.x;
    int chunk = blk % 144;
    int og = (blk / 144) % 2;
    int b  = blk / (144 * 2);
    __shared__ float ws[CC][32];
    for (int i = threadIdx.x; i < CC*32; i += 256) {
        int o = i % 32, ci = i / 32;
        ws[ci][o] = xcw[(size_t)(og*32 + o)*CC + ci];
    }
    __syncthreads();
    int p = chunk * 256 + threadIdx.x;
    const float* xb = g_x2 + (size_t)b*CC*HWP + p;
    u64 a2[16];
    #pragma unroll
    for (int j = 0; j < 16; j++) a2[j] = 0ull;
    for (int ci = 0; ci < CC; ci++) {
        float v = xb[(size_t)ci*HWP];
        u64 vv = pk2(v, v);
        const u64* wp = (const u64*)&ws[ci][0];
        #pragma unroll
        for (int j = 0; j < 16; j++) a2[j] = ffma2(vv, wp[j], a2[j]);
    }
    #pragma unroll
    for (int j = 0; j < 16; j++) {
        float2 f = upk2(a2[j]);
        #pragma unroll
        for (int hlf = 0; hlf < 2; hlf++) {
            int oo = og*32 + 2*j + hlf;
            float xa = ((hlf ? f.y : f.x) + xcb[oo]) * (BNINV * bn2g[oo]) + bn2b[oo];
            g_xn[((size_t)b*CC + oo)*HWP + p] = fmaxf(xa, 0.0f);
        }
    }
}

// ---------------- W-dim rfft: transposed smem, packed row-pairs ----------------
__global__ void k_fftw() {
    int blk = blockIdx.x;
    int hg = blk % 12;
    int c  = (blk / 12) % CC;
    int b  = blk / (12 * CC);
    int h0 = hg * 16;
    __shared__ float rows[WWD][18]; // [w][r] pitch 18 (8B aligned, low-conflict)
    for (int i = threadIdx.x; i < 16*WWD; i += 128) {
        int r = i / WWD, w = i % WWD;
        rows[w][r] = g_x2[((size_t)b*CC + c)*HWP + (size_t)(h0 + r)*WWD + w];
    }
    __syncthreads();
    int k = threadIdx.x;
    if (k >= NW2) return;
    u64 re2[8], im2[8];
    #pragma unroll
    for (int j = 0; j < 8; j++) { re2[j] = 0ull; im2[j] = 0ull; }
    for (int w = 0; w < WWD; w++) {
        float tc = g_tabc[w*HH + k], ts = g_tabs[w*HH + k];
        u64 tcc = pk2(tc, tc), tss = pk2(ts, ts);
        const u64* vp = (const u64*)&rows[w][0];
        #pragma unroll
        for (int j = 0; j < 8; j++) {
            u64 v2 = vp[j];
            re2[j] = ffma2(v2, tcc, re2[j]);
            im2[j] = ffma2(v2, tss, im2[j]);
        }
    }
    float2* fwp = (float2*)g_fw;
    #pragma unroll
    for (int j = 0; j < 8; j++) {
        float2 fr = upk2(re2[j]), fi = upk2(im2[j]);
        fwp[((size_t)(b*CC + c)*HH + h0 + 2*j  )*NW2 + k] = make_float2(fr.x, fi.x);
        fwp[((size_t)(b*CC + c)*HH + h0 + 2*j+1)*NW2 + k] = make_float2(fr.y, fi.y);
    }
}

// ---------------- H-dim FFT, even/odd DIT split + BN -> frb ----------------
__global__ void k_ffth(const float* __restrict__ bng, const float* __restrict__ bnb) {
    int blk = blockIdx.x;
    int kg = blk % 13;
    int c  = (blk / 13) % CC;
    int b  = blk / (13 * CC);
    int k0 = kg * 8;
    int t = threadIdx.x; // 0..191
    int isO = (t >= 96);
    int u = isO ? t - 96 : t;
    float re[8], im[8];
    #pragma unroll
    for (int kk = 0; kk < 8; kk++) { re[kk] = 0.f; im[kk] = 0.f; }
    __shared__ float2 stage[32*8];
    for (int hc = 0; hc < 6; hc++) {
        for (int i = threadIdx.x; i < 32*8; i += 192) {
            int hh2 = hc*32 + i/8, kk = i % 8;
            float2 v = make_float2(0.f, 0.f);
            if (k0 + kk < NW2) {
                size_t o = (((size_t)(b*CC + c)*HH + hh2)*NW2 + k0 + kk)*2;
                v.x = g_fw[o]; v.y = g_fw[o+1];
            }
            stage[i] = v;
        }
        __syncthreads();
        for (int hi = isO ? 1 : 0; hi < 32; hi += 2) {
            int h = hc*32 + hi;
            int trow = isO ? (h - 1) : h;
            float tc = g_tabc[trow*HH + u], ts = g_tabs[trow*HH + u];
            #pragma unroll
            for (int kk = 0; kk < 8; kk++) {
                float2 f = stage[hi*8 + kk];
                re[kk] += f.x*tc - f.y*ts;
                im[kk] += f.x*ts + f.y*tc;
            }
        }
        __syncthreads();
    }
    __shared__ float2 EO[192][8];
    #pragma unroll
    for (int kk = 0; kk < 8; kk++) EO[t][kk] = make_float2(re[kk], im[kk]);
    __syncthreads();
    float wc = g_tabc[HH + u], wsn = g_tabs[HH + u];
    float sgn = isO ? -1.f : 1.f;
    const float sc = 1.0f / 192.0f;
    int chR = 2*c, chI = 2*c + 1;
    float gr = BNINV * bng[chR], br = bnb[chR];
    float gi = BNINV * bng[chI], bi = bnb[chI];
    int m = t;
    for (int kk = 0; kk < 8; kk++) {
        int k = k0 + kk;
        if (k >= NW2) break;
        float2 E = EO[u][kk], O = EO[96 + u][kk];
        float orx = O.x*wc - O.y*wsn;
        float ory = O.x*wsn + O.y*wc;
        float Xr = E.x + sgn*orx;
        float Xi = E.y + sgn*ory;
        g_frb[((size_t)(b*CH2 + chR)*HH + m)*NW2 + k] = Xr*sc*gr + br;
        g_frb[((size_t)(b*CH2 + chI)*HH + m)*NW2 + k] = Xi*sc*gi + bi;
    }
}

// ---------------- fpe: depthwise 3x3 + residual ----------------
__global__ void k_fpe(const float* __restrict__ fw, const float* __restrict__ fb) {
    int t = blockIdx.x * 256 + threadIdx.x;
    if (t >= BB*CH2*HW2) return;
    int k  = t % NW2;
    int m  = (t / NW2) % HH;
    int ch = (t / HW2) % CH2;
    const float* base = g_frb + (size_t)(t / HW2) * HW2;
    float acc = fb[ch];
    #pragma unroll
    for (int ky = -1; ky <= 1; ky++) {
        int mm = m + ky;
        if ((unsigned)mm >= HH) continue;
        #pragma unroll
        for (int kx = -1; kx <= 1; kx++) {
            int kk2 = k + kx;
            if ((unsigned)kk2 >= NW2) continue;
            acc += base[mm*NW2 + kk2] * fw[ch*9 + (ky+1)*3 + (kx+1)];
        }
    }
    g_frb2[t] = acc + base[m*NW2 + k];
}

// ---------------- fdc: 32 outs/block, packed + GELU ----------------
__global__ void __launch_bounds__(256) k_fdc(const float* __restrict__ fw,
                                             const float* __restrict__ fb) {
    int blk = blockIdx.x;
    int chunk = blk % 73;
    int og = (blk / 73) % 4;
    int b  = blk / (73 * 4);
    __shared__ float ws[CH2][32];
    for (int i = threadIdx.x; i < CH2*32; i += 256) {
        int o = i % 32, ci = i / 32;
        ws[ci][o] = fw[(size_t)(og*32 + o)*CH2 + ci];
    }
    __syncthreads();
    int p = chunk * 256 + threadIdx.x;
    if (p >= HW2) return;
    const float* xb = g_frb2 + (size_t)b*CH2*HW2 + p;
    u64 a2[16];
    #pragma unroll
    for (int j = 0; j < 16; j++) a2[j] = pk2(fb[og*32 + 2*j], fb[og*32 + 2*j+1]);
    for (int ci = 0; ci < CH2; ci++) {
        float v = xb[(size_t)ci*HW2];
        u64 vv = pk2(v, v);
        const u64* wp = (const u64*)&ws[ci][0];
        #pragma unroll
        for (int j = 0; j < 16; j++) a2[j] = ffma2(vv, wp[j], a2[j]);
    }
    #pragma unroll
    for (int j = 0; j < 16; j++) {
        float2 f = upk2(a2[j]);
        float g0 = 0.5f * f.x * (1.0f + erff(f.x * 0.70710678118654752f));
        float g1 = 0.5f * f.y * (1.0f + erff(f.y * 0.70710678118654752f));
        g_fd[((size_t)b*CH2 + og*32 + 2*j  )*HW2 + p] = g0;
        g_fd[((size_t)b*CH2 + og*32 + 2*j+1)*HW2 + p] = g1;
    }
}

// ---------------- inverse H-dim FFT, even/odd DIT split ----------------
__global__ void k_invh() {
    int blk = blockIdx.x;
    int kg = blk % 13;
    int c  = (blk / 13) % CC;
    int b  = blk / (13 * CC);
    int k0 = kg * 8;
    int t = threadIdx.x;
    int isO = (t >= 96);
    int u = isO ? t - 96 : t;
    float re[8], im[8];
    #pragma unroll
    for (int kk = 0; kk < 8; kk++) { re[kk] = 0.f; im[kk] = 0.f; }
    const float* fR = g_fd + (size_t)(b*CH2 + 2*c)*HW2;
    const float* fI = g_fd + (size_t)(b*CH2 + 2*c + 1)*HW2;
    __shared__ float2 stage[32*8];
    for (int mc = 0; mc < 6; mc++) {
        for (int i = threadIdx.x; i < 32*8; i += 192) {
            int mm = mc*32 + i/8, kk = i % 8;
            float2 v = make_float2(0.f, 0.f);
            if (k0 + kk < NW2) {
                v.x = fR[mm*NW2 + k0 + kk];
                v.y = fI[mm*NW2 + k0 + kk];
            }
            stage[i] = v;
        }
        __syncthreads();
        for (int mi = isO ? 1 : 0; mi < 32; mi += 2) {
            int mm = mc*32 + mi;
            int trow = isO ? (mm - 1) : mm;
            float tc = g_tabc[trow*HH + u], ts = g_tabs[trow*HH + u];
            #pragma unroll
            for (int kk = 0; kk < 8; kk++) {
                float2 f = stage[mi*8 + kk];
                re[kk] += f.x*tc + f.y*ts;
                im[kk] += f.y*tc - f.x*ts;
            }
        }
        __syncthreads();
    }
    __shared__ float2 AB[192][8];
    #pragma unroll
    for (int kk = 0; kk < 8; kk++) AB[t][kk] = make_float2(re[kk], im[kk]);
    __syncthreads();
    float wc = g_tabc[HH + u], wsn = g_tabs[HH + u];
    float sgn = isO ? -1.f : 1.f;
    int h = t;
    for (int kk = 0; kk < 8; kk++) {
        int k = k0 + kk;
        if (k >= NW2) break;
        float2 A = AB[u][kk], Bv = AB[96 + u][kk];
        float brx = Bv.x*wc + Bv.y*wsn;
        float bry = Bv.y*wc - Bv.x*wsn;
        size_t o = (((size_t)(b*CC + c)*HH + h)*NW2 + k)*2;
        g_gh[o]   = A.x + sgn*brx;
        g_gh[o+1] = A.y + sgn*bry;
    }
}

// ---------------- irfft over W (packed float2 stage) + add xc ----------------
__global__ void k_final(float* __restrict__ out) {
    int blk = blockIdx.x;
    int hg = blk % 24;
    int c  = (blk / 24) % CC;
    int b  = blk / (24 * CC);
    int h0 = hg * 8;
    __shared__ float2 ghc[8][NW2];
    const float2* ghp = (const float2*)g_gh;
    for (int i = threadIdx.x; i < 8*NW2; i += 192) {
        int r = i / NW2, k = i % NW2;
        ghc[r][k] = ghp[((size_t)(b*CC + c)*HH + h0 + r)*NW2 + k];
    }
    __syncthreads();
    int w = threadIdx.x;
    u64 acc2[8];
    #pragma unroll
    for (int r = 0; r < 8; r++) acc2[r] = 0ull;
    for (int k = 1; k < 96; k++) {
        float tc = g_tabc[k*HH + w], ts = g_tabs[k*HH + w];
        u64 tt = pk2(tc, ts);
        const u64* gp = (const u64*)&ghc[0][0];
        #pragma unroll
        for (int r = 0; r < 8; r++)
            acc2[r] = ffma2(gp[r*NW2 + k], tt, acc2[r]);
    }
    float par = (w & 1) ? -1.0f : 1.0f;
    const float* xcb2 = g_xn + ((size_t)b*CC + c)*HWP + (size_t)h0*WWD + w;
    #pragma unroll
    for (int r = 0; r < 8; r++) {
        float2 f = upk2(acc2[r]);
        float of = (ghc[r][0].x + ghc[r][96].x*par + 2.0f*(f.x + f.y)) * (1.0f/192.0f);
        out[((size_t)b*CC + c)*HWP + (size_t)(h0 + r)*WWD + w] = xcb2[r*WWD] + of;
    }
}

// ---------------- launch ----------------
extern "C" void kernel_launch(void* const* d_in, const int* in_sizes, int n_in,
                              void* d_out, int out_size) {
    const float* x    = (const float*)d_in[0];
    const float* cdw  = (const float*)d_in[1];
    const float* lng  = (const float*)d_in[2];
    const float* lnb  = (const float*)d_in[3];
    const float* qw   = (const float*)d_in[4];
    const float* kw   = (const float*)d_in[5];
    const float* vw   = (const float*)d_in[6];
    const float* spw  = (const float*)d_in[7];
    const float* lw   = (const float*)d_in[8];
    const float* lb   = (const float*)d_in[9];
    const float* bng  = (const float*)d_in[10];
    const float* bnb  = (const float*)d_in[11];
    const float* fpew = (const float*)d_in[12];
    const float* fpeb = (const float*)d_in[13];
    const float* fdcw = (const float*)d_in[16];
    const float* fdcb = (const float*)d_in[17];
    const float* xcw  = (const float*)d_in[18];
    const float* xcb  = (const float*)d_in[19];
    const float* bn2g = (const float*)d_in[20];
    const float* bn2b = (const float*)d_in[21];
    float* out = (float*)d_out;

    k_tab<<<144, 256>>>();
    k_cdsum<<<16, 256>>>(cdw);
    k_nop<<<1, 32>>>();                       // shifts ncu slot onto k_contrast
    k_contrast<<<BB*4*144, 256>>>(x, cdw);
    k_centinit<<<144, 256>>>(x);
    k_dist<<<288, 256>>>(x);
    k_asum<<<36, 256>>>();
    k_centupd<<<144, 256>>>(x);
    k_dist<<<288, 256>>>(x);
    k_asum<<<36, 256>>>();
    k_lnorm<<<288, 256>>>(x, lng, lnb);
    k_stoken<<<72, 256>>>();
    k_stokmm<<<72, 256>>>(spw);
    k_qkv<<<BB*6*144, 256>>>(qw, kw, vw);
    k_lepe<<<BB*576, 256>>>(lw, lb);
    k_sattn<<<BB*NHD*(NSS/STILE), 256>>>();
    k_xattn<<<BB*NHD*144, 256>>>(x);
    k_xc<<<BB*2*144, 256>>>(xcw, xcb, bn2g, bn2b);
    k_fftw<<<BB*CC*12, 128>>>();
    k_ffth<<<BB*CC*13, 192>>>(bng, bnb);
    k_fpe<<<(BB*CH2*HW2 + 255)/256, 256>>>(fpew, fpeb);
    k_fdc<<<BB*4*73, 256>>>(fdcw, fdcb);
    k_invh<<<BB*CC*13, 192>>>();
    k_final<<<BB*CC*24, 192>>>(out);
}

// round 14
// speedup vs baseline: 1.6962x; 1.1113x over previous
#include <cuda_runtime.h>
#include <math.h>

#define BB 2
#define CC 64
#define HH 192
#define WWD 192
#define HWP 36864
#define NHD 4
#define DDIM 16
#define NSS 144
#define NHSS 12
#define SHH 16
#define NW2 97
#define HW2 18624
#define CH2 128
#define THETA 0.7f
#define ATTNSCALE 0.25f
#define BNINV 0.9999950000374997f

typedef unsigned long long u64;
__device__ __forceinline__ u64 pk2(float lo, float hi) {
    u64 r; asm("mov.b64 %0,{%1,%2};" : "=l"(r) : "f"(lo), "f"(hi)); return r;
}
__device__ __forceinline__ float2 upk2(u64 v) {
    float2 f; asm("mov.b64 {%0,%1},%2;" : "=f"(f.x), "=f"(f.y) : "l"(v)); return f;
}
__device__ __forceinline__ u64 ffma2(u64 a, u64 b, u64 c) {
    u64 d; asm("fma.rn.f32x2 %0,%1,%2,%3;" : "=l"(d) : "l"(a), "l"(b), "l"(c)); return d;
}

// ---------------- scratch ----------------
static __device__ float g_tabc[HH*HH];
static __device__ float g_tabs[HH*HH];
static __device__ float g_cdsum[CC*CC];
static __device__ float g_contrast[BB*CC*HWP];
static __device__ float g_cent[BB*2*CC*NSS];
static __device__ float g_asum[BB*NSS];
static __device__ float g_aff[BB*9*HWP];
static __device__ float g_xn[BB*CC*HWP];     // after k_xattn: reused as xc-relu output
static __device__ float g_q[BB*CC*HWP];
static __device__ float g_k[BB*CC*HWP];
static __device__ float g_v[BB*CC*HWP];
static __device__ float g_lepe[BB*CC*HWP];
static __device__ float g_stoken[BB*NSS*CC];
static __device__ float g_stok[BB*CC*NSS];
static __device__ float g_sout[BB*CC*NSS];
static __device__ float g_x2[BB*CC*HWP];
static __device__ float g_fw[BB*CC*HH*NW2*2];
static __device__ float g_frb[BB*CH2*HW2];
static __device__ float g_frb2[BB*CH2*HW2];
static __device__ float g_fd[BB*CH2*HW2];
static __device__ float g_gh[BB*CC*HH*NW2*2];
static __device__ float g_dummy;

// ---------------- nop: keeps ncu capture slot on k_contrast ----------------
__global__ void k_nop() { if (threadIdx.x == 1024) g_dummy = 0.f; }

// ---------------- twiddle table ----------------
__global__ void k_tab() {
    int t = blockIdx.x * blockDim.x + threadIdx.x;
    if (t >= HH*HH) return;
    int i = t / HH, j = t % HH;
    int r = (i * j) % HH;
    float s, c;
    sincospif(-(float)r / 96.0f, &s, &c);
    g_tabc[t] = c;
    g_tabs[t] = s;
}

__global__ void k_cdsum(const float* __restrict__ cdw) {
    int t = blockIdx.x * blockDim.x + threadIdx.x;
    if (t >= CC*CC) return;
    float s = 0.f;
    #pragma unroll
    for (int k = 0; k < 9; k++) s += cdw[t*9 + k];
    g_cdsum[t] = s;
}

// ---------------- contrast: row-pair blocks, folded center tap, LDS128 weights ----------------
__global__ void __launch_bounds__(192) k_contrast(const float* __restrict__ x,
                                                  const float* __restrict__ cdw) {
    int blk = blockIdx.x;
    int hp = blk % 96;
    int og = (blk / 96) % 4;
    int b  = blk / (96 * 4);
    __shared__ __align__(16) float ws[CC][9][16];
    for (int i = threadIdx.x; i < CC*9*16; i += 192) {
        int o = i % 16;
        int tap = (i / 16) % 9;
        int ci = i / 144;
        int oo = og*16 + o;
        float wv = cdw[((size_t)oo*CC + ci)*9 + tap];
        if (tap == 4) wv -= THETA * g_cdsum[oo*CC + ci];
        ws[ci][tap][o] = wv;
    }
    __syncthreads();
    int w = threadIdx.x;   // 0..191
    int h0 = hp * 2;
    u64 a2[2][8];
    #pragma unroll
    for (int px = 0; px < 2; px++)
        #pragma unroll
        for (int j = 0; j < 8; j++) a2[px][j] = 0ull;
    const float* xb = x + (size_t)b * CC * HWP;
    bool wl = (w > 0), wr = (w < WWD-1);
    for (int ci = 0; ci < CC; ci++) {
        const float* xc = xb + (size_t)ci * HWP;
        float rv[4][3];
        #pragma unroll
        for (int rr = 0; rr < 4; rr++) {
            int row = h0 - 1 + rr;
            bool rok = ((unsigned)row < HH);
            const float* rp = xc + row*WWD + w;
            rv[rr][0] = (rok && wl) ? rp[-1] : 0.f;
            rv[rr][1] = rok ? rp[0] : 0.f;
            rv[rr][2] = (rok && wr) ? rp[1] : 0.f;
        }
        #pragma unroll
        for (int tap = 0; tap < 9; tap++) {
            int ky = tap / 3, kx = tap % 3;
            u64 v0 = pk2(rv[ky][kx],   rv[ky][kx]);
            u64 v1 = pk2(rv[ky+1][kx], rv[ky+1][kx]);
            const ulonglong2* wp = (const ulonglong2*)&ws[ci][tap][0];
            #pragma unroll
            for (int q = 0; q < 4; q++) {
                ulonglong2 ww = wp[q];
                a2[0][2*q]   = ffma2(v0, ww.x, a2[0][2*q]);
                a2[0][2*q+1] = ffma2(v0, ww.y, a2[0][2*q+1]);
                a2[1][2*q]   = ffma2(v1, ww.x, a2[1][2*q]);
                a2[1][2*q+1] = ffma2(v1, ww.y, a2[1][2*q+1]);
            }
        }
    }
    #pragma unroll
    for (int px = 0; px < 2; px++) {
        int p = (h0 + px)*WWD + w;
        #pragma unroll
        for (int j = 0; j < 8; j++) {
            float2 f = upk2(a2[px][j]);
            g_contrast[((size_t)b*CC + og*16 + 2*j  )*HWP + p] = f.x;
            g_contrast[((size_t)b*CC + og*16 + 2*j+1)*HWP + p] = f.y;
        }
    }
}

// ---------------- cent init: float4 gather ----------------
__global__ void k_centinit(const float* __restrict__ x) {
    int t = blockIdx.x * 256 + threadIdx.x;
    if (t >= BB*2*CC*NSS) return;
    int s  = t % NSS;
    int ch = (t / NSS) % (2*CC);
    int b  = t / (NSS * 2 * CC);
    const float* src = (ch < CC) ? (x + ((size_t)b*CC + ch)*HWP)
                                 : (g_contrast + ((size_t)b*CC + (ch-CC))*HWP);
    int r0 = s / NHSS, c0 = s % NHSS;
    const float4* sp = (const float4*)(src + (r0*SHH)*WWD + c0*SHH);
    float acc = 0.f;
    for (int i = 0; i < SHH; i++) {
        #pragma unroll
        for (int jj = 0; jj < 4; jj++) {
            float4 v = sp[i*48 + jj];
            acc += v.x; acc += v.y; acc += v.z; acc += v.w;
        }
    }
    g_cent[t] = acc * (1.0f/256.0f);
}

// ---------------- distances + softmax -> aff ----------------
__global__ void k_dist(const float* __restrict__ x) {
    int t = blockIdx.x * 256 + threadIdx.x;
    if (t >= BB*HWP) return;
    int p = t % HWP, b = t / HWP;
    int h = p / WWD, w = p % WWD;
    int r = h / SHH, c = w / SHH;
    float d[9];
    int   cs[9];
    int   val[9];
    #pragma unroll
    for (int j = 0; j < 9; j++) {
        int dy = j/3 - 1, dx = j%3 - 1;
        int rr = r + dy, cc2 = c + dx;
        val[j] = (rr >= 0 && rr < NHSS && cc2 >= 0 && cc2 < NHSS);
        cs[j]  = val[j] ? rr*NHSS + cc2 : 0;
        d[j]   = 0.f;
    }
    const float* cb = g_cent + (size_t)b * 2 * CC * NSS;
    for (int ch = 0; ch < 2*CC; ch++) {
        float pix = (ch < CC) ? x[((size_t)b*CC + ch)*HWP + p]
                              : g_contrast[((size_t)b*CC + ch - CC)*HWP + p];
        float wgt = (ch < CC) ? 1.0f : 10.0f;
        const float* cr = cb + (size_t)ch * NSS;
        #pragma unroll
        for (int j = 0; j < 9; j++) {
            float df = pix - cr[cs[j]];
            d[j] += wgt * df * df;
        }
    }
    float m = 3.0e38f;
    #pragma unroll
    for (int j = 0; j < 9; j++) if (val[j] && d[j] < m) m = d[j];
    float e[9], sum = 0.f;
    #pragma unroll
    for (int j = 0; j < 9; j++) {
        e[j] = val[j] ? __expf(m - d[j]) : 0.f;
        sum += e[j];
    }
    float inv = 1.0f / sum;
    #pragma unroll
    for (int j = 0; j < 9; j++)
        g_aff[((size_t)b*9 + j)*HWP + p] = e[j] * inv;
}

// ---------------- asum: one warp per (b,s), float4 + shfl ----------------
__global__ void k_asum() {
    int wid = (blockIdx.x * 256 + threadIdx.x) >> 5;
    int lane = threadIdx.x & 31;
    if (wid >= BB*NSS) return;
    int s = wid % NSS, b = wid / NSS;
    int r0 = s / NHSS, c0 = s % NHSS;
    float acc = 0.f;
    for (int dy = -1; dy <= 1; dy++) {
        int r = r0 - dy;
        if ((unsigned)r >= NHSS) continue;
        for (int dx = -1; dx <= 1; dx++) {
            int c = c0 - dx;
            if ((unsigned)c >= NHSS) continue;
            int j = (dy+1)*3 + (dx+1);
            const float4* ab = (const float4*)(g_aff + ((size_t)b*9 + j)*HWP
                                               + (r*SHH)*WWD + c*SHH);
            for (int idx = lane; idx < 64; idx += 32) {
                int i = idx >> 2, jj = idx & 3;
                float4 v = ab[i*48 + jj];
                acc += v.x; acc += v.y; acc += v.z; acc += v.w;
            }
        }
    }
    #pragma unroll
    for (int o = 16; o > 0; o >>= 1) acc += __shfl_down_sync(0xffffffffu, acc, o);
    if (lane == 0) g_asum[wid] = acc;
}

// ---------------- cent update: ch-fastest (aff broadcast), float4 ----------------
__global__ void k_centupd(const float* __restrict__ x) {
    int t = blockIdx.x * 256 + threadIdx.x;
    if (t >= BB*2*CC*NSS) return;
    int ch = t % (2*CC);
    int s  = (t / (2*CC)) % NSS;
    int b  = t / (NSS * 2 * CC);
    const float* src = (ch < CC) ? (x + ((size_t)b*CC + ch)*HWP)
                                 : (g_contrast + ((size_t)b*CC + (ch-CC))*HWP);
    int r0 = s / NHSS, c0 = s % NHSS;
    float acc = 0.f;
    for (int dy = -1; dy <= 1; dy++) {
        int r = r0 - dy;
        if ((unsigned)r >= NHSS) continue;
        for (int dx = -1; dx <= 1; dx++) {
            int c = c0 - dx;
            if ((unsigned)c >= NHSS) continue;
            int j = (dy+1)*3 + (dx+1);
            int pb = (r*SHH)*WWD + c*SHH;
            const float4* ar = (const float4*)(g_aff + ((size_t)b*9 + j)*HWP + pb);
            const float4* sr = (const float4*)(src + pb);
            for (int i = 0; i < SHH; i++) {
                #pragma unroll
                for (int jj = 0; jj < 4; jj++) {
                    float4 a = ar[i*48 + jj];
                    float4 v = sr[i*48 + jj];
                    acc += a.x*v.x; acc += a.y*v.y; acc += a.z*v.z; acc += a.w*v.w;
                }
            }
        }
    }
    g_cent[((size_t)b*2*CC + ch)*NSS + s] = acc / (g_asum[(size_t)b*NSS + s] + 1e-16f);
}

// ---------------- LayerNorm ----------------
__global__ void k_lnorm(const float* __restrict__ x, const float* __restrict__ g,
                        const float* __restrict__ bta) {
    int t = blockIdx.x * 256 + threadIdx.x;
    if (t >= BB*HWP) return;
    int p = t % HWP, b = t / HWP;
    const float* xb = x + (size_t)b*CC*HWP + p;
    float sum = 0.f, sq = 0.f;
    for (int ch = 0; ch < CC; ch++) {
        float v = xb[(size_t)ch*HWP];
        sum += v; sq += v*v;
    }
    float mu = sum * (1.0f/CC);
    float var = sq * (1.0f/CC) - mu*mu;
    float rstd = rsqrtf(var + 1e-6f);
    float* ob = g_xn + (size_t)b*CC*HWP + p;
    for (int ch = 0; ch < CC; ch++) {
        float v = xb[(size_t)ch*HWP];
        ob[(size_t)ch*HWP] = (v - mu) * rstd * g[ch] + bta[ch];
    }
}

// ---------------- stoken gather: ch-fastest (aff broadcast), float4 ----------------
__global__ void k_stoken() {
    int t = blockIdx.x * 256 + threadIdx.x;
    if (t >= BB*NSS*CC) return;
    int ch = t % CC;
    int s  = (t / CC) % NSS;
    int b  = t / (CC * NSS);
    const float* src = g_xn + ((size_t)b*CC + ch)*HWP;
    int r0 = s / NHSS, c0 = s % NHSS;
    float acc = 0.f;
    for (int dy = -1; dy <= 1; dy++) {
        int r = r0 - dy;
        if ((unsigned)r >= NHSS) continue;
        for (int dx = -1; dx <= 1; dx++) {
            int c = c0 - dx;
            if ((unsigned)c >= NHSS) continue;
            int j = (dy+1)*3 + (dx+1);
            int pb = (r*SHH)*WWD + c*SHH;
            const float4* ar = (const float4*)(g_aff + ((size_t)b*9 + j)*HWP + pb);
            const float4* sr = (const float4*)(src + pb);
            for (int i = 0; i < SHH; i++) {
                #pragma unroll
                for (int jj = 0; jj < 4; jj++) {
                    float4 a = ar[i*48 + jj];
                    float4 v = sr[i*48 + jj];
                    acc += a.x*v.x; acc += a.y*v.y; acc += a.z*v.z; acc += a.w*v.w;
                }
            }
        }
    }
    g_stoken[((size_t)b*NSS + s)*CC + ch] = acc / (g_asum[(size_t)b*NSS + s] + 1e-16f);
}

// ---------------- stok = stoken @ sp_w^T ----------------
__global__ void k_stokmm(const float* __restrict__ spw) {
    int t = blockIdx.x * 256 + threadIdx.x;
    if (t >= BB*CC*NSS) return;
    int s = t % NSS;
    int o = (t / NSS) % CC;
    int b = t / (NSS * CC);
    const float* st = g_stoken + ((size_t)b*NSS + s)*CC;
    const float* w  = spw + o*CC;
    float acc = 0.f;
    #pragma unroll 8
    for (int c = 0; c < CC; c++) acc += w[c] * st[c];
    g_stok[((size_t)b*CC + o)*NSS + s] = acc;
}

// ---------------- q/k/v: 16 outs x 2 px per thread, LDS128 weights ----------------
__global__ void __launch_bounds__(256) k_qkv(const float* __restrict__ qw,
                                             const float* __restrict__ kw,
                                             const float* __restrict__ vw) {
    int blk = blockIdx.x;
    int chunk = blk % 72;
    int og = (blk / 72) % 12;
    int b  = blk / (72 * 12);
    __shared__ __align__(16) float ws[CC][16];
    for (int i = threadIdx.x; i < CC*16; i += 256) {
        int o = i % 16, ci = i / 16;
        int oo = og*16 + o;
        const float* wsrc = (oo < 64) ? (qw + oo*CC)
                          : (oo < 128 ? kw + (oo-64)*CC : vw + (oo-128)*CC);
        ws[ci][o] = wsrc[ci];
    }
    __syncthreads();
    int p = chunk*512 + threadIdx.x*2;
    const float* xb = g_xn + (size_t)b*CC*HWP + p;
    u64 a2[2][8];
    #pragma unroll
    for (int px = 0; px < 2; px++)
        #pragma unroll
        for (int j = 0; j < 8; j++) a2[px][j] = 0ull;
    for (int ci = 0; ci < CC; ci++) {
        float2 v = *(const float2*)(xb + (size_t)ci*HWP);
        u64 v0 = pk2(v.x, v.x), v1 = pk2(v.y, v.y);
        const ulonglong2* wp = (const ulonglong2*)&ws[ci][0];
        #pragma unroll
        for (int q = 0; q < 4; q++) {
            ulonglong2 ww = wp[q];
            a2[0][2*q]   = ffma2(v0, ww.x, a2[0][2*q]);
            a2[0][2*q+1] = ffma2(v0, ww.y, a2[0][2*q+1]);
            a2[1][2*q]   = ffma2(v1, ww.x, a2[1][2*q]);
            a2[1][2*q+1] = ffma2(v1, ww.y, a2[1][2*q+1]);
        }
    }
    #pragma unroll
    for (int j = 0; j < 8; j++) {
        float2 f0 = upk2(a2[0][j]), f1 = upk2(a2[1][j]);
        #pragma unroll
        for (int hlf = 0; hlf < 2; hlf++) {
            int oo = og*16 + 2*j + hlf;
            float lo = hlf ? f0.y : f0.x;
            float hi = hlf ? f1.y : f1.x;
            float* dst = (oo < 64) ? (g_q + ((size_t)b*64 + oo)*HWP)
                       : (oo < 128 ? (g_k + ((size_t)b*64 + oo-64)*HWP)
                                   : (g_v + ((size_t)b*64 + oo-128)*HWP));
            *(float2*)(dst + p) = make_float2(lo, hi);
        }
    }
}

// ---------------- lepe: coalesced Tflat write ----------------
__global__ void __launch_bounds__(256) k_lepe(const float* __restrict__ lw,
                                              const float* __restrict__ lb) {
    __shared__ float ws[CC*9];
    __shared__ float bs[CC];
    for (int i = threadIdx.x; i < CC*9; i += 256) ws[i] = lw[i];
    if (threadIdx.x < CC) bs[threadIdx.x] = lb[threadIdx.x];
    __syncthreads();
    int blk = blockIdx.x;
    int pblk = blk % 576;
    int b = blk / 576;
    int cg = threadIdx.x & 3;
    int pl = threadIdx.x >> 2;
    int p = pblk * 64 + pl;
    int h = p / WWD, w = p % WWD;
    int off[9];
    bool vld[9];
    #pragma unroll
    for (int tap = 0; tap < 9; tap++) {
        int ky = tap/3 - 1, kx = tap%3 - 1;
        int hh = h + ky, ww = w + kx;
        vld[tap] = ((unsigned)hh < HH) && ((unsigned)ww < WWD);
        off[tap] = hh*WWD + ww;
    }
    const float* vb = g_v + (size_t)b*CC*HWP;
    float o[16];
    #pragma unroll
    for (int j = 0; j < 16; j++) {
        int c = cg*16 + j;
        const float* vc = vb + (size_t)c*HWP;
        float acc = bs[c];
        #pragma unroll
        for (int tap = 0; tap < 9; tap++)
            if (vld[tap]) acc += vc[off[tap]] * ws[c*9 + tap];
        o[j] = acc;
    }
    float4* dst = (float4*)(g_lepe + (size_t)b*CC*HWP + (size_t)p*CC + cg*16);
    #pragma unroll
    for (int q = 0; q < 4; q++)
        dst[q] = make_float4(o[q*4], o[q*4+1], o[q*4+2], o[q*4+3]);
}

// ---------------- s_attn: packed, STILE=8, LDS128 stok ----------------
#define STILE 8
__global__ void __launch_bounds__(256) k_sattn() {
    int blk = blockIdx.x;
    int sg = blk % (NSS/STILE);
    int hh = (blk / (NSS/STILE)) % NHD;
    int b  = blk / ((NSS/STILE) * NHD);
    int s0 = sg * STILE;
    int tid = threadIdx.x;
    __shared__ __align__(16) u64 stks2[STILE][8];
    if (tid < STILE*8) {
        int si = tid / 8, j = tid % 8;
        size_t base = (size_t)(b*NHD + hh)*DDIM;
        stks2[si][j] = pk2(g_stok[(base + 2*j  )*NSS + s0 + si],
                           g_stok[(base + 2*j+1)*NSS + s0 + si]);
    }
    __syncthreads();
    float l[STILE];
    u64 acc2[STILE][8];
    #pragma unroll
    for (int si = 0; si < STILE; si++) {
        l[si] = 0.f;
        #pragma unroll
        for (int j = 0; j < 8; j++) acc2[si][j] = 0ull;
    }
    const float* kb = g_k + (size_t)(b*NHD + hh)*DDIM*HWP;
    const float* vb = g_v + (size_t)(b*NHD + hh)*DDIM*HWP;
    for (int p = tid; p < HWP; p += 256) {
        u64 kd2[8], vd2[8];
        #pragma unroll
        for (int j = 0; j < 8; j++)
            kd2[j] = pk2(kb[(size_t)(2*j)*HWP + p], kb[(size_t)(2*j+1)*HWP + p]);
        #pragma unroll
        for (int j = 0; j < 8; j++)
            vd2[j] = pk2(vb[(size_t)(2*j)*HWP + p], vb[(size_t)(2*j+1)*HWP + p]);
        #pragma unroll
        for (int si = 0; si < STILE; si++) {
            const ulonglong2* sp = (const ulonglong2*)&stks2[si][0];
            u64 dp = 0ull;
            #pragma unroll
            for (int q = 0; q < 4; q++) {
                ulonglong2 ss = sp[q];
                dp = ffma2(kd2[2*q],   ss.x, dp);
                dp = ffma2(kd2[2*q+1], ss.y, dp);
            }
            float2 f = upk2(dp);
            float e = __expf((f.x + f.y) * ATTNSCALE);
            l[si] += e;
            u64 ee = pk2(e, e);
            #pragma unroll
            for (int j = 0; j < 8; j++) acc2[si][j] = ffma2(ee, vd2[j], acc2[si][j]);
        }
    }
    __shared__ float rl[256], ra[DDIM*256];
    for (int si = 0; si < STILE; si++) {
        rl[tid] = l[si];
        #pragma unroll
        for (int j = 0; j < 8; j++) {
            float2 f = upk2(acc2[si][j]);
            ra[(2*j  )*256 + tid] = f.x;
            ra[(2*j+1)*256 + tid] = f.y;
        }
        __syncthreads();
        for (int str = 128; str > 0; str >>= 1) {
            if (tid < str) {
                rl[tid] += rl[tid + str];
                #pragma unroll
                for (int d = 0; d < DDIM; d++)
                    ra[d*256 + tid] += ra[d*256 + tid + str];
            }
            __syncthreads();
        }
        if (tid < DDIM)
            g_sout[((size_t)(b*NHD + hh)*DDIM + tid)*NSS + s0 + si] = ra[tid*256] / rl[0];
        __syncthreads();
    }
}

// ---------------- x_attn: packed single-pass, LDS128 tables ----------------
__global__ void __launch_bounds__(256) k_xattn(const float* __restrict__ x) {
    int blk = blockIdx.x;
    int chunk = blk % 144;
    int hh = (blk / 144) % NHD;
    int b  = blk / (144 * NHD);
    int tid = threadIdx.x;
    __shared__ __align__(16) u64 stp[NSS*10];
    __shared__ __align__(16) u64 sop[NSS*10];
    size_t base = (size_t)(b*NHD + hh)*DDIM*NSS;
    for (int i = tid; i < NSS*8; i += 256) {
        int j = i / NSS, s = i % NSS;
        stp[s*10 + j] = pk2(g_stok[base + (2*j)*NSS + s], g_stok[base + (2*j+1)*NSS + s]);
        sop[s*10 + j] = pk2(g_sout[base + (2*j)*NSS + s], g_sout[base + (2*j+1)*NSS + s]);
    }
    __syncthreads();
    int p = chunk * 256 + tid;
    u64 qd2[8];
    #pragma unroll
    for (int j = 0; j < 8; j++)
        qd2[j] = pk2(g_q[((size_t)(b*NHD + hh)*DDIM + 2*j  )*HWP + p],
                     g_q[((size_t)(b*NHD + hh)*DDIM + 2*j+1)*HWP + p]);
    float l = 0.f;
    u64 acc2[8];
    #pragma unroll
    for (int j = 0; j < 8; j++) acc2[j] = 0ull;
    for (int s = 0; s < NSS; s++) {
        const ulonglong2* sp = (const ulonglong2*)&stp[s*10];
        u64 dp = 0ull;
        #pragma unroll
        for (int q = 0; q < 4; q++) {
            ulonglong2 ss = sp[q];
            dp = ffma2(qd2[2*q],   ss.x, dp);
            dp = ffma2(qd2[2*q+1], ss.y, dp);
        }
        float2 f = upk2(dp);
        float e = __expf((f.x + f.y) * ATTNSCALE);
        l += e;
        u64 ee = pk2(e, e);
        const ulonglong2* op = (const ulonglong2*)&sop[s*10];
        #pragma unroll
        for (int q = 0; q < 4; q++) {
            ulonglong2 oo = op[q];
            acc2[2*q]   = ffma2(ee, oo.x, acc2[2*q]);
            acc2[2*q+1] = ffma2(ee, oo.y, acc2[2*q+1]);
        }
    }
    float invl = 1.0f / l;
    #pragma unroll
    for (int j = 0; j < 8; j++) {
        float2 f = upk2(acc2[j]);
        #pragma unroll
        for (int hlf = 0; hlf < 2; hlf++) {
            int cch = hh*DDIM + 2*j + hlf;
            size_t o = ((size_t)b*CC + cch)*HWP + p;
            g_x2[o] = x[o] + (hlf ? f.y : f.x)*invl + g_lepe[o];
        }
    }
}

// ---------------- xc: 16 outs x 2 px, LDS128 weights, relu'd into g_xn ----------------
__global__ void __launch_bounds__(256) k_xc(const float* __restrict__ xcw,
                                            const float* __restrict__ xcb,
                                            const float* __restrict__ bn2g,
                                            const float* __restrict__ bn2b) {
    int blk = blockIdx.x;
    int chunk = blk % 72;
    int og = (blk / 72) % 4;
    int b  = blk / (72 * 4);
    __shared__ __align__(16) float ws[CC][16];
    for (int i = threadIdx.x; i < CC*16; i += 256) {
        int o = i % 16, ci = i / 16;
        ws[ci][o] = xcw[(size_t)(og*16 + o)*CC + ci];
    }
    __syncthreads();
    int p = chunk*512 + threadIdx.x*2;
    const float* xb = g_x2 + (size_t)b*CC*HWP + p;
    u64 a2[2][8];
    #pragma unroll
    for (int px = 0; px < 2; px++)
        #pragma unroll
        for (int j = 0; j < 8; j++) a2[px][j] = 0ull;
    for (int ci = 0; ci < CC; ci++) {
        float2 v = *(const float2*)(xb + (size_t)ci*HWP);
        u64 v0 = pk2(v.x, v.x), v1 = pk2(v.y, v.y);
        const ulonglong2* wp = (const ulonglong2*)&ws[ci][0];
        #pragma unroll
        for (int q = 0; q < 4; q++) {
            ulonglong2 ww = wp[q];
            a2[0][2*q]   = ffma2(v0, ww.x, a2[0][2*q]);
            a2[0][2*q+1] = ffma2(v0, ww.y, a2[0][2*q+1]);
            a2[1][2*q]   = ffma2(v1, ww.x, a2[1][2*q]);
            a2[1][2*q+1] = ffma2(v1, ww.y, a2[1][2*q+1]);
        }
    }
    #pragma unroll
    for (int j = 0; j < 8; j++) {
        float2 f0 = upk2(a2[0][j]), f1 = upk2(a2[1][j]);
        #pragma unroll
        for (int hlf = 0; hlf < 2; hlf++) {
            int oo = og*16 + 2*j + hlf;
            float gbn = BNINV * bn2g[oo], bbn = bn2b[oo], bias = xcb[oo];
            float lo = ((hlf ? f0.y : f0.x) + bias) * gbn + bbn;
            float hi = ((hlf ? f1.y : f1.x) + bias) * gbn + bbn;
            *(float2*)(g_xn + ((size_t)b*CC + oo)*HWP + p) =
                make_float2(fmaxf(lo, 0.0f), fmaxf(hi, 0.0f));
        }
    }
}

// ---------------- W-dim rfft: transposed smem, packed row-pairs ----------------
__global__ void k_fftw() {
    int blk = blockIdx.x;
    int hg = blk % 12;
    int c  = (blk / 12) % CC;
    int b  = blk / (12 * CC);
    int h0 = hg * 16;
    __shared__ float rows[WWD][18];
    for (int i = threadIdx.x; i < 16*WWD; i += 128) {
        int r = i / WWD, w = i % WWD;
        rows[w][r] = g_x2[((size_t)b*CC + c)*HWP + (size_t)(h0 + r)*WWD + w];
    }
    __syncthreads();
    int k = threadIdx.x;
    if (k >= NW2) return;
    u64 re2[8], im2[8];
    #pragma unroll
    for (int j = 0; j < 8; j++) { re2[j] = 0ull; im2[j] = 0ull; }
    for (int w = 0; w < WWD; w++) {
        float tc = g_tabc[w*HH + k], ts = g_tabs[w*HH + k];
        u64 tcc = pk2(tc, tc), tss = pk2(ts, ts);
        const u64* vp = (const u64*)&rows[w][0];
        #pragma unroll
        for (int j = 0; j < 8; j++) {
            u64 v2 = vp[j];
            re2[j] = ffma2(v2, tcc, re2[j]);
            im2[j] = ffma2(v2, tss, im2[j]);
        }
    }
    float2* fwp = (float2*)g_fw;
    #pragma unroll
    for (int j = 0; j < 8; j++) {
        float2 fr = upk2(re2[j]), fi = upk2(im2[j]);
        fwp[((size_t)(b*CC + c)*HH + h0 + 2*j  )*NW2 + k] = make_float2(fr.x, fi.x);
        fwp[((size_t)(b*CC + c)*HH + h0 + 2*j+1)*NW2 + k] = make_float2(fr.y, fi.y);
    }
}

// ---------------- H-dim FFT, even/odd DIT split + BN -> frb ----------------
__global__ void k_ffth(const float* __restrict__ bng, const float* __restrict__ bnb) {
    int blk = blockIdx.x;
    int kg = blk % 13;
    int c  = (blk / 13) % CC;
    int b  = blk / (13 * CC);
    int k0 = kg * 8;
    int t = threadIdx.x;
    int isO = (t >= 96);
    int u = isO ? t - 96 : t;
    float re[8], im[8];
    #pragma unroll
    for (int kk = 0; kk < 8; kk++) { re[kk] = 0.f; im[kk] = 0.f; }
    __shared__ float2 stage[32*8];
    for (int hc = 0; hc < 6; hc++) {
        for (int i = threadIdx.x; i < 32*8; i += 192) {
            int hh2 = hc*32 + i/8, kk = i % 8;
            float2 v = make_float2(0.f, 0.f);
            if (k0 + kk < NW2) {
                size_t o = (((size_t)(b*CC + c)*HH + hh2)*NW2 + k0 + kk)*2;
                v.x = g_fw[o]; v.y = g_fw[o+1];
            }
            stage[i] = v;
        }
        __syncthreads();
        for (int hi = isO ? 1 : 0; hi < 32; hi += 2) {
            int h = hc*32 + hi;
            int trow = isO ? (h - 1) : h;
            float tc = g_tabc[trow*HH + u], ts = g_tabs[trow*HH + u];
            #pragma unroll
            for (int kk = 0; kk < 8; kk++) {
                float2 f = stage[hi*8 + kk];
                re[kk] += f.x*tc - f.y*ts;
                im[kk] += f.x*ts + f.y*tc;
            }
        }
        __syncthreads();
    }
    __shared__ float2 EO[192][8];
    #pragma unroll
    for (int kk = 0; kk < 8; kk++) EO[t][kk] = make_float2(re[kk], im[kk]);
    __syncthreads();
    float wc = g_tabc[HH + u], wsn = g_tabs[HH + u];
    float sgn = isO ? -1.f : 1.f;
    const float sc = 1.0f / 192.0f;
    int chR = 2*c, chI = 2*c + 1;
    float gr = BNINV * bng[chR], br = bnb[chR];
    float gi = BNINV * bng[chI], bi = bnb[chI];
    int m = t;
    for (int kk = 0; kk < 8; kk++) {
        int k = k0 + kk;
        if (k >= NW2) break;
        float2 E = EO[u][kk], O = EO[96 + u][kk];
        float orx = O.x*wc - O.y*wsn;
        float ory = O.x*wsn + O.y*wc;
        float Xr = E.x + sgn*orx;
        float Xi = E.y + sgn*ory;
        g_frb[((size_t)(b*CH2 + chR)*HH + m)*NW2 + k] = Xr*sc*gr + br;
        g_frb[((size_t)(b*CH2 + chI)*HH + m)*NW2 + k] = Xi*sc*gi + bi;
    }
}

// ---------------- fpe: depthwise 3x3 + residual ----------------
__global__ void k_fpe(const float* __restrict__ fw, const float* __restrict__ fb) {
    int t = blockIdx.x * 256 + threadIdx.x;
    if (t >= BB*CH2*HW2) return;
    int k  = t % NW2;
    int m  = (t / NW2) % HH;
    int ch = (t / HW2) % CH2;
    const float* base = g_frb + (size_t)(t / HW2) * HW2;
    float acc = fb[ch];
    #pragma unroll
    for (int ky = -1; ky <= 1; ky++) {
        int mm = m + ky;
        if ((unsigned)mm >= HH) continue;
        #pragma unroll
        for (int kx = -1; kx <= 1; kx++) {
            int kk2 = k + kx;
            if ((unsigned)kk2 >= NW2) continue;
            acc += base[mm*NW2 + kk2] * fw[ch*9 + (ky+1)*3 + (kx+1)];
        }
    }
    g_frb2[t] = acc + base[m*NW2 + k];
}

// ---------------- fdc: 16 outs x 2 px, LDS128 weights + GELU ----------------
__global__ void __launch_bounds__(256) k_fdc(const float* __restrict__ fw,
                                             const float* __restrict__ fb) {
    int blk = blockIdx.x;
    int chunk = blk % 37;
    int og = (blk / 37) % 8;
    int b  = blk / (37 * 8);
    __shared__ __align__(16) float ws[CH2][16];
    for (int i = threadIdx.x; i < CH2*16; i += 256) {
        int o = i % 16, ci = i / 16;
        ws[ci][o] = fw[(size_t)(og*16 + o)*CH2 + ci];
    }
    __syncthreads();
    int p = chunk*512 + threadIdx.x*2;
    if (p >= HW2) return;
    const float* xb = g_frb2 + (size_t)b*CH2*HW2 + p;
    u64 a2[2][8];
    #pragma unroll
    for (int j = 0; j < 8; j++) {
        u64 bb = pk2(fb[og*16 + 2*j], fb[og*16 + 2*j+1]);
        a2[0][j] = bb; a2[1][j] = bb;
    }
    for (int ci = 0; ci < CH2; ci++) {
        float2 v = *(const float2*)(xb + (size_t)ci*HW2);
        u64 v0 = pk2(v.x, v.x), v1 = pk2(v.y, v.y);
        const ulonglong2* wp = (const ulonglong2*)&ws[ci][0];
        #pragma unroll
        for (int q = 0; q < 4; q++) {
            ulonglong2 ww = wp[q];
            a2[0][2*q]   = ffma2(v0, ww.x, a2[0][2*q]);
            a2[0][2*q+1] = ffma2(v0, ww.y, a2[0][2*q+1]);
            a2[1][2*q]   = ffma2(v1, ww.x, a2[1][2*q]);
            a2[1][2*q+1] = ffma2(v1, ww.y, a2[1][2*q+1]);
        }
    }
    #pragma unroll
    for (int j = 0; j < 8; j++) {
        float2 f0 = upk2(a2[0][j]), f1 = upk2(a2[1][j]);
        #pragma unroll
        for (int hlf = 0; hlf < 2; hlf++) {
            int oo = og*16 + 2*j + hlf;
            float a = hlf ? f0.y : f0.x;
            float bq = hlf ? f1.y : f1.x;
            float g0 = 0.5f * a  * (1.0f + erff(a  * 0.70710678118654752f));
            float g1 = 0.5f * bq * (1.0f + erff(bq * 0.70710678118654752f));
            *(float2*)(g_fd + ((size_t)b*CH2 + oo)*HW2 + p) = make_float2(g0, g1);
        }
    }
}

// ---------------- inverse H-dim FFT, even/odd DIT split ----------------
__global__ void k_invh() {
    int blk = blockIdx.x;
    int kg = blk % 13;
    int c  = (blk / 13) % CC;
    int b  = blk / (13 * CC);
    int k0 = kg * 8;
    int t = threadIdx.x;
    int isO = (t >= 96);
    int u = isO ? t - 96 : t;
    float re[8], im[8];
    #pragma unroll
    for (int kk = 0; kk < 8; kk++) { re[kk] = 0.f; im[kk] = 0.f; }
    const float* fR = g_fd + (size_t)(b*CH2 + 2*c)*HW2;
    const float* fI = g_fd + (size_t)(b*CH2 + 2*c + 1)*HW2;
    __shared__ float2 stage[32*8];
    for (int mc = 0; mc < 6; mc++) {
        for (int i = threadIdx.x; i < 32*8; i += 192) {
            int mm = mc*32 + i/8, kk = i % 8;
            float2 v = make_float2(0.f, 0.f);
            if (k0 + kk < NW2) {
                v.x = fR[mm*NW2 + k0 + kk];
                v.y = fI[mm*NW2 + k0 + kk];
            }
            stage[i] = v;
        }
        __syncthreads();
        for (int mi = isO ? 1 : 0; mi < 32; mi += 2) {
            int mm = mc*32 + mi;
            int trow = isO ? (mm - 1) : mm;
            float tc = g_tabc[trow*HH + u], ts = g_tabs[trow*HH + u];
            #pragma unroll
            for (int kk = 0; kk < 8; kk++) {
                float2 f = stage[mi*8 + kk];
                re[kk] += f.x*tc + f.y*ts;
                im[kk] += f.y*tc - f.x*ts;
            }
        }
        __syncthreads();
    }
    __shared__ float2 AB[192][8];
    #pragma unroll
    for (int kk = 0; kk < 8; kk++) AB[t][kk] = make_float2(re[kk], im[kk]);
    __syncthreads();
    float wc = g_tabc[HH + u], wsn = g_tabs[HH + u];
    float sgn = isO ? -1.f : 1.f;
    int h = t;
    for (int kk = 0; kk < 8; kk++) {
        int k = k0 + kk;
        if (k >= NW2) break;
        float2 A = AB[u][kk], Bv = AB[96 + u][kk];
        float brx = Bv.x*wc + Bv.y*wsn;
        float bry = Bv.y*wc - Bv.x*wsn;
        size_t o = (((size_t)(b*CC + c)*HH + h)*NW2 + k)*2;
        g_gh[o]   = A.x + sgn*brx;
        g_gh[o+1] = A.y + sgn*bry;
    }
}

// ---------------- irfft over W (packed float2 stage) + add xc ----------------
__global__ void k_final(float* __restrict__ out) {
    int blk = blockIdx.x;
    int hg = blk % 24;
    int c  = (blk / 24) % CC;
    int b  = blk / (24 * CC);
    int h0 = hg * 8;
    __shared__ float2 ghc[8][NW2];
    const float2* ghp = (const float2*)g_gh;
    for (int i = threadIdx.x; i < 8*NW2; i += 192) {
        int r = i / NW2, k = i % NW2;
        ghc[r][k] = ghp[((size_t)(b*CC + c)*HH + h0 + r)*NW2 + k];
    }
    __syncthreads();
    int w = threadIdx.x;
    u64 acc2[8];
    #pragma unroll
    for (int r = 0; r < 8; r++) acc2[r] = 0ull;
    for (int k = 1; k < 96; k++) {
        float tc = g_tabc[k*HH + w], ts = g_tabs[k*HH + w];
        u64 tt = pk2(tc, ts);
        const u64* gp = (const u64*)&ghc[0][0];
        #pragma unroll
        for (int r = 0; r < 8; r++)
            acc2[r] = ffma2(gp[r*NW2 + k], tt, acc2[r]);
    }
    float par = (w & 1) ? -1.0f : 1.0f;
    const float* xcb2 = g_xn + ((size_t)b*CC + c)*HWP + (size_t)h0*WWD + w;
    #pragma unroll
    for (int r = 0; r < 8; r++) {
        float2 f = upk2(acc2[r]);
        float of = (ghc[r][0].x + ghc[r][96].x*par + 2.0f*(f.x + f.y)) * (1.0f/192.0f);
        out[((size_t)b*CC + c)*HWP + (size_t)(h0 + r)*WWD + w] = xcb2[r*WWD] + of;
    }
}

// ---------------- launch ----------------
extern "C" void kernel_launch(void* const* d_in, const int* in_sizes, int n_in,
                              void* d_out, int out_size) {
    const float* x    = (const float*)d_in[0];
    const float* cdw  = (const float*)d_in[1];
    const float* lng  = (const float*)d_in[2];
    const float* lnb  = (const float*)d_in[3];
    const float* qw   = (const float*)d_in[4];
    const float* kw   = (const float*)d_in[5];
    const float* vw   = (const float*)d_in[6];
    const float* spw  = (const float*)d_in[7];
    const float* lw   = (const float*)d_in[8];
    const float* lb   = (const float*)d_in[9];
    const float* bng  = (const float*)d_in[10];
    const float* bnb  = (const float*)d_in[11];
    const float* fpew = (const float*)d_in[12];
    const float* fpeb = (const float*)d_in[13];
    const float* fdcw = (const float*)d_in[16];
    const float* fdcb = (const float*)d_in[17];
    const float* xcw  = (const float*)d_in[18];
    const float* xcb  = (const float*)d_in[19];
    const float* bn2g = (const float*)d_in[20];
    const float* bn2b = (const float*)d_in[21];
    float* out = (float*)d_out;

    k_tab<<<144, 256>>>();
    k_cdsum<<<16, 256>>>(cdw);
    k_nop<<<1, 32>>>();                       // keep ncu slot on k_contrast
    k_contrast<<<BB*4*96, 192>>>(x, cdw);
    k_centinit<<<144, 256>>>(x);
    k_dist<<<288, 256>>>(x);
    k_asum<<<36, 256>>>();
    k_centupd<<<144, 256>>>(x);
    k_dist<<<288, 256>>>(x);
    k_asum<<<36, 256>>>();
    k_lnorm<<<288, 256>>>(x, lng, lnb);
    k_stoken<<<72, 256>>>();
    k_stokmm<<<72, 256>>>(spw);
    k_qkv<<<BB*12*72, 256>>>(qw, kw, vw);
    k_lepe<<<BB*576, 256>>>(lw, lb);
    k_sattn<<<BB*NHD*(NSS/STILE), 256>>>();
    k_xattn<<<BB*NHD*144, 256>>>(x);
    k_xc<<<BB*4*72, 256>>>(xcw, xcb, bn2g, bn2b);
    k_fftw<<<BB*CC*12, 128>>>();
    k_ffth<<<BB*CC*13, 192>>>(bng, bnb);
    k_fpe<<<(BB*CH2*HW2 + 255)/256, 256>>>(fpew, fpeb);
    k_fdc<<<BB*8*37, 256>>>(fdcw, fdcb);
    k_invh<<<BB*CC*13, 192>>>();
    k_final<<<BB*CC*24, 192>>>(out);
}

// round 15
// speedup vs baseline: 1.8476x; 1.0893x over previous
#include <cuda_runtime.h>
#include <math.h>

#define BB 2
#define CC 64
#define HH 192
#define WWD 192
#define HWP 36864
#define NHD 4
#define DDIM 16
#define NSS 144
#define NHSS 12
#define SHH 16
#define NW2 97
#define HW2 18624
#define CH2 128
#define THETA 0.7f
#define ATTNSCALE 0.25f
#define BNINV 0.9999950000374997f

typedef unsigned long long u64;
__device__ __forceinline__ u64 pk2(float lo, float hi) {
    u64 r; asm("mov.b64 %0,{%1,%2};" : "=l"(r) : "f"(lo), "f"(hi)); return r;
}
__device__ __forceinline__ float2 upk2(u64 v) {
    float2 f; asm("mov.b64 {%0,%1},%2;" : "=f"(f.x), "=f"(f.y) : "l"(v)); return f;
}
__device__ __forceinline__ u64 ffma2(u64 a, u64 b, u64 c) {
    u64 d; asm("fma.rn.f32x2 %0,%1,%2,%3;" : "=l"(d) : "l"(a), "l"(b), "l"(c)); return d;
}

// ---------------- scratch ----------------
static __device__ float g_tabc[HH*HH];
static __device__ float g_tabs[HH*HH];
static __device__ float g_cdsum[CC*CC];
static __device__ float g_contrast[BB*CC*HWP];
static __device__ float g_cent[BB*NSS*2*CC];   // layout [b][s][2C]
static __device__ float g_csq[BB*2*NSS];       // [b][half][s]
static __device__ float g_asum[BB*NSS];
static __device__ float g_aff[BB*9*HWP];
static __device__ float g_xn[BB*CC*HWP];       // after k_xattn: reused as xc-relu output
static __device__ float g_q[BB*CC*HWP];
static __device__ float g_k[BB*CC*HWP];
static __device__ float g_v[BB*CC*HWP];
static __device__ float g_lepe[BB*CC*HWP];
static __device__ float g_stoken[BB*NSS*CC];
static __device__ float g_stok[BB*CC*NSS];
static __device__ float g_sout[BB*CC*NSS];
static __device__ float g_x2[BB*CC*HWP];
static __device__ float g_fw[BB*CC*HH*NW2*2];
static __device__ float g_frb[BB*CH2*HW2];
static __device__ float g_frb2[BB*CH2*HW2];
static __device__ float g_fd[BB*CH2*HW2];
static __device__ float g_gh[BB*CC*HH*NW2*2];
static __device__ float g_dummy;

// ---------------- nop: keeps ncu capture slot on k_contrast ----------------
__global__ void k_nop() { if (threadIdx.x == 1024) g_dummy = 0.f; }

// ---------------- twiddle table ----------------
__global__ void k_tab() {
    int t = blockIdx.x * blockDim.x + threadIdx.x;
    if (t >= HH*HH) return;
    int i = t / HH, j = t % HH;
    int r = (i * j) % HH;
    float s, c;
    sincospif(-(float)r / 96.0f, &s, &c);
    g_tabc[t] = c;
    g_tabs[t] = s;
}

__global__ void k_cdsum(const float* __restrict__ cdw) {
    int t = blockIdx.x * blockDim.x + threadIdx.x;
    if (t >= CC*CC) return;
    float s = 0.f;
    #pragma unroll
    for (int k = 0; k < 9; k++) s += cdw[t*9 + k];
    g_cdsum[t] = s;
}

// ---------------- contrast: row-pair blocks, folded center tap, LDS128 weights ----------------
__global__ void __launch_bounds__(192) k_contrast(const float* __restrict__ x,
                                                  const float* __restrict__ cdw) {
    int blk = blockIdx.x;
    int hp = blk % 96;
    int og = (blk / 96) % 4;
    int b  = blk / (96 * 4);
    __shared__ __align__(16) float ws[CC][9][16];
    for (int i = threadIdx.x; i < CC*9*16; i += 192) {
        int o = i % 16;
        int tap = (i / 16) % 9;
        int ci = i / 144;
        int oo = og*16 + o;
        float wv = cdw[((size_t)oo*CC + ci)*9 + tap];
        if (tap == 4) wv -= THETA * g_cdsum[oo*CC + ci];
        ws[ci][tap][o] = wv;
    }
    __syncthreads();
    int w = threadIdx.x;
    int h0 = hp * 2;
    u64 a2[2][8];
    #pragma unroll
    for (int px = 0; px < 2; px++)
        #pragma unroll
        for (int j = 0; j < 8; j++) a2[px][j] = 0ull;
    const float* xb = x + (size_t)b * CC * HWP;
    bool wl = (w > 0), wr = (w < WWD-1);
    for (int ci = 0; ci < CC; ci++) {
        const float* xc = xb + (size_t)ci * HWP;
        float rv[4][3];
        #pragma unroll
        for (int rr = 0; rr < 4; rr++) {
            int row = h0 - 1 + rr;
            bool rok = ((unsigned)row < HH);
            const float* rp = xc + row*WWD + w;
            rv[rr][0] = (rok && wl) ? rp[-1] : 0.f;
            rv[rr][1] = rok ? rp[0] : 0.f;
            rv[rr][2] = (rok && wr) ? rp[1] : 0.f;
        }
        #pragma unroll
        for (int tap = 0; tap < 9; tap++) {
            int ky = tap / 3, kx = tap % 3;
            u64 v0 = pk2(rv[ky][kx],   rv[ky][kx]);
            u64 v1 = pk2(rv[ky+1][kx], rv[ky+1][kx]);
            const ulonglong2* wp = (const ulonglong2*)&ws[ci][tap][0];
            #pragma unroll
            for (int q = 0; q < 4; q++) {
                ulonglong2 ww = wp[q];
                a2[0][2*q]   = ffma2(v0, ww.x, a2[0][2*q]);
                a2[0][2*q+1] = ffma2(v0, ww.y, a2[0][2*q+1]);
                a2[1][2*q]   = ffma2(v1, ww.x, a2[1][2*q]);
                a2[1][2*q+1] = ffma2(v1, ww.y, a2[1][2*q+1]);
            }
        }
    }
    #pragma unroll
    for (int px = 0; px < 2; px++) {
        int p = (h0 + px)*WWD + w;
        #pragma unroll
        for (int j = 0; j < 8; j++) {
            float2 f = upk2(a2[px][j]);
            g_contrast[((size_t)b*CC + og*16 + 2*j  )*HWP + p] = f.x;
            g_contrast[((size_t)b*CC + og*16 + 2*j+1)*HWP + p] = f.y;
        }
    }
}

// ---------------- cent init: ch-fastest, float4 gather, [b][s][2C] layout ----------------
__global__ void k_centinit(const float* __restrict__ x) {
    int t = blockIdx.x * 256 + threadIdx.x;
    if (t >= BB*2*CC*NSS) return;
    int ch = t % (2*CC);
    int s  = (t / (2*CC)) % NSS;
    int b  = t / (NSS * 2 * CC);
    const float* src = (ch < CC) ? (x + ((size_t)b*CC + ch)*HWP)
                                 : (g_contrast + ((size_t)b*CC + (ch-CC))*HWP);
    int r0 = s / NHSS, c0 = s % NHSS;
    const float4* sp = (const float4*)(src + (r0*SHH)*WWD + c0*SHH);
    float acc = 0.f;
    for (int i = 0; i < SHH; i++) {
        #pragma unroll
        for (int jj = 0; jj < 4; jj++) {
            float4 v = sp[i*48 + jj];
            acc += v.x; acc += v.y; acc += v.z; acc += v.w;
        }
    }
    g_cent[((size_t)b*NSS + s)*2*CC + ch] = acc * (1.0f/256.0f);
}

// ---------------- cent squared-norm per (b, half, s) ----------------
__global__ void k_centsq() {
    int t = blockIdx.x * 128 + threadIdx.x;
    if (t >= BB*2*NSS) return;
    int s = t % NSS;
    int half = (t / NSS) % 2;
    int b = t / (2*NSS);
    const float4* cb = (const float4*)(g_cent + ((size_t)b*NSS + s)*2*CC + half*CC);
    float acc = 0.f;
    #pragma unroll
    for (int i = 0; i < CC/4; i++) {
        float4 v = cb[i];
        acc += v.x*v.x; acc += v.y*v.y; acc += v.z*v.z; acc += v.w*v.w;
    }
    g_csq[((size_t)b*2 + half)*NSS + s] = acc;
}

// ---------------- distances via p2 - 2g + s2 (reference trick), packed pairs ----------------
__global__ void k_dist(const float* __restrict__ x) {
    int t = blockIdx.x * 256 + threadIdx.x;
    if (t >= BB*HWP) return;
    int p = t % HWP, b = t / HWP;
    int h = p / WWD, w = p % WWD;
    int r = h / SHH, c = w / SHH;
    int cs[9];
    int val[9];
    #pragma unroll
    for (int j = 0; j < 9; j++) {
        int dy = j/3 - 1, dx = j%3 - 1;
        int rr = r + dy, cc2 = c + dx;
        val[j] = (rr >= 0 && rr < NHSS && cc2 >= 0 && cc2 < NHSS);
        cs[j]  = val[j] ? rr*NHSS + cc2 : 0;
    }
    const float* ct = g_cent + (size_t)b*NSS*2*CC;
    const float* rowp[9];
    #pragma unroll
    for (int j = 0; j < 9; j++) rowp[j] = ct + (size_t)cs[j]*2*CC;

    u64 g2[9];
    #pragma unroll
    for (int j = 0; j < 9; j++) g2[j] = 0ull;
    float p2a = 0.f;
    const float* xb = x + (size_t)b*CC*HWP + p;
    for (int ch = 0; ch < CC; ch += 2) {
        float pix0 = xb[(size_t)ch*HWP];
        float pix1 = xb[(size_t)(ch+1)*HWP];
        p2a = fmaf(pix0, pix0, p2a);
        p2a = fmaf(pix1, pix1, p2a);
        u64 px = pk2(pix0, pix1);
        #pragma unroll
        for (int j = 0; j < 9; j++)
            g2[j] = ffma2(px, *(const u64*)(rowp[j] + ch), g2[j]);
    }
    const float* sqa = g_csq + (size_t)b*2*NSS;
    float d[9];
    #pragma unroll
    for (int j = 0; j < 9; j++) {
        float2 f = upk2(g2[j]);
        d[j] = p2a - 2.0f*(f.x + f.y) + sqa[cs[j]];
        g2[j] = 0ull;
    }
    float p2b = 0.f;
    const float* cbq = g_contrast + (size_t)b*CC*HWP + p;
    for (int ch = 0; ch < CC; ch += 2) {
        float pix0 = cbq[(size_t)ch*HWP];
        float pix1 = cbq[(size_t)(ch+1)*HWP];
        p2b = fmaf(pix0, pix0, p2b);
        p2b = fmaf(pix1, pix1, p2b);
        u64 px = pk2(pix0, pix1);
        #pragma unroll
        for (int j = 0; j < 9; j++)
            g2[j] = ffma2(px, *(const u64*)(rowp[j] + CC + ch), g2[j]);
    }
    const float* sqb = sqa + NSS;
    #pragma unroll
    for (int j = 0; j < 9; j++) {
        float2 f = upk2(g2[j]);
        d[j] += 10.0f * (p2b - 2.0f*(f.x + f.y) + sqb[cs[j]]);
    }
    float m = 3.0e38f;
    #pragma unroll
    for (int j = 0; j < 9; j++) if (val[j] && d[j] < m) m = d[j];
    float e[9], sum = 0.f;
    #pragma unroll
    for (int j = 0; j < 9; j++) {
        e[j] = val[j] ? __expf(m - d[j]) : 0.f;
        sum += e[j];
    }
    float inv = 1.0f / sum;
    #pragma unroll
    for (int j = 0; j < 9; j++)
        g_aff[((size_t)b*9 + j)*HWP + p] = e[j] * inv;
}

// ---------------- asum: one warp per (b,s), float4 + shfl ----------------
__global__ void k_asum() {
    int wid = (blockIdx.x * 256 + threadIdx.x) >> 5;
    int lane = threadIdx.x & 31;
    if (wid >= BB*NSS) return;
    int s = wid % NSS, b = wid / NSS;
    int r0 = s / NHSS, c0 = s % NHSS;
    float acc = 0.f;
    for (int dy = -1; dy <= 1; dy++) {
        int r = r0 - dy;
        if ((unsigned)r >= NHSS) continue;
        for (int dx = -1; dx <= 1; dx++) {
            int c = c0 - dx;
            if ((unsigned)c >= NHSS) continue;
            int j = (dy+1)*3 + (dx+1);
            const float4* ab = (const float4*)(g_aff + ((size_t)b*9 + j)*HWP
                                               + (r*SHH)*WWD + c*SHH);
            for (int idx = lane; idx < 64; idx += 32) {
                int i = idx >> 2, jj = idx & 3;
                float4 v = ab[i*48 + jj];
                acc += v.x; acc += v.y; acc += v.z; acc += v.w;
            }
        }
    }
    #pragma unroll
    for (int o = 16; o > 0; o >>= 1) acc += __shfl_down_sync(0xffffffffu, acc, o);
    if (lane == 0) g_asum[wid] = acc;
}

// ---------------- cent update: ch-fastest (aff broadcast), float4, [b][s][2C] write ----------------
__global__ void k_centupd(const float* __restrict__ x) {
    int t = blockIdx.x * 256 + threadIdx.x;
    if (t >= BB*2*CC*NSS) return;
    int ch = t % (2*CC);
    int s  = (t / (2*CC)) % NSS;
    int b  = t / (NSS * 2 * CC);
    const float* src = (ch < CC) ? (x + ((size_t)b*CC + ch)*HWP)
                                 : (g_contrast + ((size_t)b*CC + (ch-CC))*HWP);
    int r0 = s / NHSS, c0 = s % NHSS;
    float acc = 0.f;
    for (int dy = -1; dy <= 1; dy++) {
        int r = r0 - dy;
        if ((unsigned)r >= NHSS) continue;
        for (int dx = -1; dx <= 1; dx++) {
            int c = c0 - dx;
            if ((unsigned)c >= NHSS) continue;
            int j = (dy+1)*3 + (dx+1);
            int pb = (r*SHH)*WWD + c*SHH;
            const float4* ar = (const float4*)(g_aff + ((size_t)b*9 + j)*HWP + pb);
            const float4* sr = (const float4*)(src + pb);
            for (int i = 0; i < SHH; i++) {
                #pragma unroll
                for (int jj = 0; jj < 4; jj++) {
                    float4 a = ar[i*48 + jj];
                    float4 v = sr[i*48 + jj];
                    acc += a.x*v.x; acc += a.y*v.y; acc += a.z*v.z; acc += a.w*v.w;
                }
            }
        }
    }
    g_cent[((size_t)b*NSS + s)*2*CC + ch] = acc / (g_asum[(size_t)b*NSS + s] + 1e-16f);
}

// ---------------- LayerNorm ----------------
__global__ void k_lnorm(const float* __restrict__ x, const float* __restrict__ g,
                        const float* __restrict__ bta) {
    int t = blockIdx.x * 256 + threadIdx.x;
    if (t >= BB*HWP) return;
    int p = t % HWP, b = t / HWP;
    const float* xb = x + (size_t)b*CC*HWP + p;
    float sum = 0.f, sq = 0.f;
    for (int ch = 0; ch < CC; ch++) {
        float v = xb[(size_t)ch*HWP];
        sum += v; sq += v*v;
    }
    float mu = sum * (1.0f/CC);
    float var = sq * (1.0f/CC) - mu*mu;
    float rstd = rsqrtf(var + 1e-6f);
    float* ob = g_xn + (size_t)b*CC*HWP + p;
    for (int ch = 0; ch < CC; ch++) {
        float v = xb[(size_t)ch*HWP];
        ob[(size_t)ch*HWP] = (v - mu) * rstd * g[ch] + bta[ch];
    }
}

// ---------------- stoken gather: ch-fastest (aff broadcast), float4 ----------------
__global__ void k_stoken() {
    int t = blockIdx.x * 256 + threadIdx.x;
    if (t >= BB*NSS*CC) return;
    int ch = t % CC;
    int s  = (t / CC) % NSS;
    int b  = t / (CC * NSS);
    const float* src = g_xn + ((size_t)b*CC + ch)*HWP;
    int r0 = s / NHSS, c0 = s % NHSS;
    float acc = 0.f;
    for (int dy = -1; dy <= 1; dy++) {
        int r = r0 - dy;
        if ((unsigned)r >= NHSS) continue;
        for (int dx = -1; dx <= 1; dx++) {
            int c = c0 - dx;
            if ((unsigned)c >= NHSS) continue;
            int j = (dy+1)*3 + (dx+1);
            int pb = (r*SHH)*WWD + c*SHH;
            const float4* ar = (const float4*)(g_aff + ((size_t)b*9 + j)*HWP + pb);
            const float4* sr = (const float4*)(src + pb);
            for (int i = 0; i < SHH; i++) {
                #pragma unroll
                for (int jj = 0; jj < 4; jj++) {
                    float4 a = ar[i*48 + jj];
                    float4 v = sr[i*48 + jj];
                    acc += a.x*v.x; acc += a.y*v.y; acc += a.z*v.z; acc += a.w*v.w;
                }
            }
        }
    }
    g_stoken[((size_t)b*NSS + s)*CC + ch] = acc / (g_asum[(size_t)b*NSS + s] + 1e-16f);
}

// ---------------- stok = stoken @ sp_w^T ----------------
__global__ void k_stokmm(const float* __restrict__ spw) {
    int t = blockIdx.x * 256 + threadIdx.x;
    if (t >= BB*CC*NSS) return;
    int s = t % NSS;
    int o = (t / NSS) % CC;
    int b = t / (NSS * CC);
    const float* st = g_stoken + ((size_t)b*NSS + s)*CC;
    const float* w  = spw + o*CC;
    float acc = 0.f;
    #pragma unroll 8
    for (int c = 0; c < CC; c++) acc += w[c] * st[c];
    g_stok[((size_t)b*CC + o)*NSS + s] = acc;
}

// ---------------- q/k/v: 16 outs x 2 px per thread, LDS128 weights ----------------
__global__ void __launch_bounds__(256) k_qkv(const float* __restrict__ qw,
                                             const float* __restrict__ kw,
                                             const float* __restrict__ vw) {
    int blk = blockIdx.x;
    int chunk = blk % 72;
    int og = (blk / 72) % 12;
    int b  = blk / (72 * 12);
    __shared__ __align__(16) float ws[CC][16];
    for (int i = threadIdx.x; i < CC*16; i += 256) {
        int o = i % 16, ci = i / 16;
        int oo = og*16 + o;
        const float* wsrc = (oo < 64) ? (qw + oo*CC)
                          : (oo < 128 ? kw + (oo-64)*CC : vw + (oo-128)*CC);
        ws[ci][o] = wsrc[ci];
    }
    __syncthreads();
    int p = chunk*512 + threadIdx.x*2;
    const float* xb = g_xn + (size_t)b*CC*HWP + p;
    u64 a2[2][8];
    #pragma unroll
    for (int px = 0; px < 2; px++)
        #pragma unroll
        for (int j = 0; j < 8; j++) a2[px][j] = 0ull;
    for (int ci = 0; ci < CC; ci++) {
        float2 v = *(const float2*)(xb + (size_t)ci*HWP);
        u64 v0 = pk2(v.x, v.x), v1 = pk2(v.y, v.y);
        const ulonglong2* wp = (const ulonglong2*)&ws[ci][0];
        #pragma unroll
        for (int q = 0; q < 4; q++) {
            ulonglong2 ww = wp[q];
            a2[0][2*q]   = ffma2(v0, ww.x, a2[0][2*q]);
            a2[0][2*q+1] = ffma2(v0, ww.y, a2[0][2*q+1]);
            a2[1][2*q]   = ffma2(v1, ww.x, a2[1][2*q]);
            a2[1][2*q+1] = ffma2(v1, ww.y, a2[1][2*q+1]);
        }
    }
    #pragma unroll
    for (int j = 0; j < 8; j++) {
        float2 f0 = upk2(a2[0][j]), f1 = upk2(a2[1][j]);
        #pragma unroll
        for (int hlf = 0; hlf < 2; hlf++) {
            int oo = og*16 + 2*j + hlf;
            float lo = hlf ? f0.y : f0.x;
            float hi = hlf ? f1.y : f1.x;
            float* dst = (oo < 64) ? (g_q + ((size_t)b*64 + oo)*HWP)
                       : (oo < 128 ? (g_k + ((size_t)b*64 + oo-64)*HWP)
                                   : (g_v + ((size_t)b*64 + oo-128)*HWP));
            *(float2*)(dst + p) = make_float2(lo, hi);
        }
    }
}

// ---------------- lepe: coalesced Tflat write ----------------
__global__ void __launch_bounds__(256) k_lepe(const float* __restrict__ lw,
                                              const float* __restrict__ lb) {
    __shared__ float ws[CC*9];
    __shared__ float bs[CC];
    for (int i = threadIdx.x; i < CC*9; i += 256) ws[i] = lw[i];
    if (threadIdx.x < CC) bs[threadIdx.x] = lb[threadIdx.x];
    __syncthreads();
    int blk = blockIdx.x;
    int pblk = blk % 576;
    int b = blk / 576;
    int cg = threadIdx.x & 3;
    int pl = threadIdx.x >> 2;
    int p = pblk * 64 + pl;
    int h = p / WWD, w = p % WWD;
    int off[9];
    bool vld[9];
    #pragma unroll
    for (int tap = 0; tap < 9; tap++) {
        int ky = tap/3 - 1, kx = tap%3 - 1;
        int hh = h + ky, ww = w + kx;
        vld[tap] = ((unsigned)hh < HH) && ((unsigned)ww < WWD);
        off[tap] = hh*WWD + ww;
    }
    const float* vb = g_v + (size_t)b*CC*HWP;
    float o[16];
    #pragma unroll
    for (int j = 0; j < 16; j++) {
        int c = cg*16 + j;
        const float* vc = vb + (size_t)c*HWP;
        float acc = bs[c];
        #pragma unroll
        for (int tap = 0; tap < 9; tap++)
            if (vld[tap]) acc += vc[off[tap]] * ws[c*9 + tap];
        o[j] = acc;
    }
    float4* dst = (float4*)(g_lepe + (size_t)b*CC*HWP + (size_t)p*CC + cg*16);
    #pragma unroll
    for (int q = 0; q < 4; q++)
        dst[q] = make_float4(o[q*4], o[q*4+1], o[q*4+2], o[q*4+3]);
}

// ---------------- s_attn: packed, STILE=8, LDS128 stok ----------------
#define STILE 8
__global__ void __launch_bounds__(256) k_sattn() {
    int blk = blockIdx.x;
    int sg = blk % (NSS/STILE);
    int hh = (blk / (NSS/STILE)) % NHD;
    int b  = blk / ((NSS/STILE) * NHD);
    int s0 = sg * STILE;
    int tid = threadIdx.x;
    __shared__ __align__(16) u64 stks2[STILE][8];
    if (tid < STILE*8) {
        int si = tid / 8, j = tid % 8;
        size_t base = (size_t)(b*NHD + hh)*DDIM;
        stks2[si][j] = pk2(g_stok[(base + 2*j  )*NSS + s0 + si],
                           g_stok[(base + 2*j+1)*NSS + s0 + si]);
    }
    __syncthreads();
    float l[STILE];
    u64 acc2[STILE][8];
    #pragma unroll
    for (int si = 0; si < STILE; si++) {
        l[si] = 0.f;
        #pragma unroll
        for (int j = 0; j < 8; j++) acc2[si][j] = 0ull;
    }
    const float* kb = g_k + (size_t)(b*NHD + hh)*DDIM*HWP;
    const float* vb = g_v + (size_t)(b*NHD + hh)*DDIM*HWP;
    for (int p = tid; p < HWP; p += 256) {
        u64 kd2[8], vd2[8];
        #pragma unroll
        for (int j = 0; j < 8; j++)
            kd2[j] = pk2(kb[(size_t)(2*j)*HWP + p], kb[(size_t)(2*j+1)*HWP + p]);
        #pragma unroll
        for (int j = 0; j < 8; j++)
            vd2[j] = pk2(vb[(size_t)(2*j)*HWP + p], vb[(size_t)(2*j+1)*HWP + p]);
        #pragma unroll
        for (int si = 0; si < STILE; si++) {
            const ulonglong2* sp = (const ulonglong2*)&stks2[si][0];
            u64 dp = 0ull;
            #pragma unroll
            for (int q = 0; q < 4; q++) {
                ulonglong2 ss = sp[q];
                dp = ffma2(kd2[2*q],   ss.x, dp);
                dp = ffma2(kd2[2*q+1], ss.y, dp);
            }
            float2 f = upk2(dp);
            float e = __expf((f.x + f.y) * ATTNSCALE);
            l[si] += e;
            u64 ee = pk2(e, e);
            #pragma unroll
            for (int j = 0; j < 8; j++) acc2[si][j] = ffma2(ee, vd2[j], acc2[si][j]);
        }
    }
    __shared__ float rl[256], ra[DDIM*256];
    for (int si = 0; si < STILE; si++) {
        rl[tid] = l[si];
        #pragma unroll
        for (int j = 0; j < 8; j++) {
            float2 f = upk2(acc2[si][j]);
            ra[(2*j  )*256 + tid] = f.x;
            ra[(2*j+1)*256 + tid] = f.y;
        }
        __syncthreads();
        for (int str = 128; str > 0; str >>= 1) {
            if (tid < str) {
                rl[tid] += rl[tid + str];
                #pragma unroll
                for (int d = 0; d < DDIM; d++)
                    ra[d*256 + tid] += ra[d*256 + tid + str];
            }
            __syncthreads();
        }
        if (tid < DDIM)
            g_sout[((size_t)(b*NHD + hh)*DDIM + tid)*NSS + s0 + si] = ra[tid*256] / rl[0];
        __syncthreads();
    }
}

// ---------------- x_attn: packed single-pass, LDS128 tables ----------------
__global__ void __launch_bounds__(256) k_xattn(const float* __restrict__ x) {
    int blk = blockIdx.x;
    int chunk = blk % 144;
    int hh = (blk / 144) % NHD;
    int b  = blk / (144 * NHD);
    int tid = threadIdx.x;
    __shared__ __align__(16) u64 stp[NSS*10];
    __shared__ __align__(16) u64 sop[NSS*10];
    size_t base = (size_t)(b*NHD + hh)*DDIM*NSS;
    for (int i = tid; i < NSS*8; i += 256) {
        int j = i / NSS, s = i % NSS;
        stp[s*10 + j] = pk2(g_stok[base + (2*j)*NSS + s], g_stok[base + (2*j+1)*NSS + s]);
        sop[s*10 + j] = pk2(g_sout[base + (2*j)*NSS + s], g_sout[base + (2*j+1)*NSS + s]);
    }
    __syncthreads();
    int p = chunk * 256 + tid;
    u64 qd2[8];
    #pragma unroll
    for (int j = 0; j < 8; j++)
        qd2[j] = pk2(g_q[((size_t)(b*NHD + hh)*DDIM + 2*j  )*HWP + p],
                     g_q[((size_t)(b*NHD + hh)*DDIM + 2*j+1)*HWP + p]);
    float l = 0.f;
    u64 acc2[8];
    #pragma unroll
    for (int j = 0; j < 8; j++) acc2[j] = 0ull;
    for (int s = 0; s < NSS; s++) {
        const ulonglong2* sp = (const ulonglong2*)&stp[s*10];
        u64 dp = 0ull;
        #pragma unroll
        for (int q = 0; q < 4; q++) {
            ulonglong2 ss = sp[q];
            dp = ffma2(qd2[2*q],   ss.x, dp);
            dp = ffma2(qd2[2*q+1], ss.y, dp);
        }
        float2 f = upk2(dp);
        float e = __expf((f.x + f.y) * ATTNSCALE);
        l += e;
        u64 ee = pk2(e, e);
        const ulonglong2* op = (const ulonglong2*)&sop[s*10];
        #pragma unroll
        for (int q = 0; q < 4; q++) {
            ulonglong2 oo = op[q];
            acc2[2*q]   = ffma2(ee, oo.x, acc2[2*q]);
            acc2[2*q+1] = ffma2(ee, oo.y, acc2[2*q+1]);
        }
    }
    float invl = 1.0f / l;
    #pragma unroll
    for (int j = 0; j < 8; j++) {
        float2 f = upk2(acc2[j]);
        #pragma unroll
        for (int hlf = 0; hlf < 2; hlf++) {
            int cch = hh*DDIM + 2*j + hlf;
            size_t o = ((size_t)b*CC + cch)*HWP + p;
            g_x2[o] = x[o] + (hlf ? f.y : f.x)*invl + g_lepe[o];
        }
    }
}

// ---------------- xc: 16 outs x 2 px, LDS128 weights, relu'd into g_xn ----------------
__global__ void __launch_bounds__(256) k_xc(const float* __restrict__ xcw,
                                            const float* __restrict__ xcb,
                                            const float* __restrict__ bn2g,
                                            const float* __restrict__ bn2b) {
    int blk = blockIdx.x;
    int chunk = blk % 72;
    int og = (blk / 72) % 4;
    int b  = blk / (72 * 4);
    __shared__ __align__(16) float ws[CC][16];
    for (int i = threadIdx.x; i < CC*16; i += 256) {
        int o = i % 16, ci = i / 16;
        ws[ci][o] = xcw[(size_t)(og*16 + o)*CC + ci];
    }
    __syncthreads();
    int p = chunk*512 + threadIdx.x*2;
    const float* xb = g_x2 + (size_t)b*CC*HWP + p;
    u64 a2[2][8];
    #pragma unroll
    for (int px = 0; px < 2; px++)
        #pragma unroll
        for (int j = 0; j < 8; j++) a2[px][j] = 0ull;
    for (int ci = 0; ci < CC; ci++) {
        float2 v = *(const float2*)(xb + (size_t)ci*HWP);
        u64 v0 = pk2(v.x, v.x), v1 = pk2(v.y, v.y);
        const ulonglong2* wp = (const ulonglong2*)&ws[ci][0];
        #pragma unroll
        for (int q = 0; q < 4; q++) {
            ulonglong2 ww = wp[q];
            a2[0][2*q]   = ffma2(v0, ww.x, a2[0][2*q]);
            a2[0][2*q+1] = ffma2(v0, ww.y, a2[0][2*q+1]);
            a2[1][2*q]   = ffma2(v1, ww.x, a2[1][2*q]);
            a2[1][2*q+1] = ffma2(v1, ww.y, a2[1][2*q+1]);
        }
    }
    #pragma unroll
    for (int j = 0; j < 8; j++) {
        float2 f0 = upk2(a2[0][j]), f1 = upk2(a2[1][j]);
        #pragma unroll
        for (int hlf = 0; hlf < 2; hlf++) {
            int oo = og*16 + 2*j + hlf;
            float gbn = BNINV * bn2g[oo], bbn = bn2b[oo], bias = xcb[oo];
            float lo = ((hlf ? f0.y : f0.x) + bias) * gbn + bbn;
            float hi = ((hlf ? f1.y : f1.x) + bias) * gbn + bbn;
            *(float2*)(g_xn + ((size_t)b*CC + oo)*HWP + p) =
                make_float2(fmaxf(lo, 0.0f), fmaxf(hi, 0.0f));
        }
    }
}

// ---------------- W-dim rfft: even/odd DIT over w, 192 threads ----------------
__global__ void __launch_bounds__(192) k_fftw() {
    int blk = blockIdx.x;
    int hg = blk % 12;
    int c  = (blk / 12) % CC;
    int b  = blk / (12 * CC);
    int h0 = hg * 16;
    __shared__ float rows[WWD][18];
    for (int i = threadIdx.x; i < 16*WWD; i += 192) {
        int r = i / WWD, w = i % WWD;
        rows[w][r] = g_x2[((size_t)b*CC + c)*HWP + (size_t)(h0 + r)*WWD + w];
    }
    __syncthreads();
    int t = threadIdx.x;
    int isO = (t >= 96);
    int u = isO ? t - 96 : t;
    u64 re2[8], im2[8];
    #pragma unroll
    for (int j = 0; j < 8; j++) { re2[j] = 0ull; im2[j] = 0ull; }
    for (int wi = 0; wi < 96; wi++) {
        int w = 2*wi + isO;
        float tc = g_tabc[(2*wi)*HH + u], ts = g_tabs[(2*wi)*HH + u];
        u64 tcc = pk2(tc, tc), tss = pk2(ts, ts);
        const u64* vp = (const u64*)&rows[w][0];
        #pragma unroll
        for (int j = 0; j < 8; j++) {
            u64 v2 = vp[j];
            re2[j] = ffma2(v2, tcc, re2[j]);
            im2[j] = ffma2(v2, tss, im2[j]);
        }
    }
    __shared__ u64 Er[192][8];
    __shared__ u64 Ei[192][8];
    #pragma unroll
    for (int j = 0; j < 8; j++) { Er[t][j] = re2[j]; Ei[t][j] = im2[j]; }
    __syncthreads();
    if (t > 96) return;
    int u2 = (t == 96) ? 0 : t;
    float wc = g_tabc[HH + t], wsn = g_tabs[HH + t];   // w^t
    u64 wcc = pk2(wc, wc), wss = pk2(wsn, wsn), mwss = pk2(-wsn, -wsn);
    float2* fwp = (float2*)g_fw;
    #pragma unroll
    for (int j = 0; j < 8; j++) {
        u64 er = Er[u2][j], ei = Ei[u2][j];
        u64 orr = Er[96 + u2][j], oi = Ei[96 + u2][j];
        u64 xr = ffma2(orr, wcc, er);  xr = ffma2(oi,  mwss, xr);
        u64 xi = ffma2(oi,  wcc, ei);  xi = ffma2(orr, wss,  xi);
        float2 fr = upk2(xr), fi = upk2(xi);
        fwp[((size_t)(b*CC + c)*HH + h0 + 2*j  )*NW2 + t] = make_float2(fr.x, fi.x);
        fwp[((size_t)(b*CC + c)*HH + h0 + 2*j+1)*NW2 + t] = make_float2(fr.y, fi.y);
    }
}

// ---------------- H-dim FFT: SoA stage, packed kk-pairs, DIT + BN -> frb ----------------
__global__ void k_ffth(const float* __restrict__ bng, const float* __restrict__ bnb) {
    int blk = blockIdx.x;
    int kg = blk % 13;
    int c  = (blk / 13) % CC;
    int b  = blk / (13 * CC);
    int k0 = kg * 8;
    int t = threadIdx.x;
    int isO = (t >= 96);
    int u = isO ? t - 96 : t;
    u64 re2[4], im2[4];
    #pragma unroll
    for (int q = 0; q < 4; q++) { re2[q] = 0ull; im2[q] = 0ull; }
    __shared__ __align__(8) float sre[32*8];
    __shared__ __align__(8) float sim[32*8];
    for (int hc = 0; hc < 6; hc++) {
        for (int i = threadIdx.x; i < 32*8; i += 192) {
            int hh2 = hc*32 + i/8, kk = i % 8;
            float2 v = make_float2(0.f, 0.f);
            if (k0 + kk < NW2) {
                size_t o = (((size_t)(b*CC + c)*HH + hh2)*NW2 + k0 + kk)*2;
                v.x = g_fw[o]; v.y = g_fw[o+1];
            }
            sre[i] = v.x; sim[i] = v.y;
        }
        __syncthreads();
        for (int hi = isO ? 1 : 0; hi < 32; hi += 2) {
            int h = hc*32 + hi;
            int trow = isO ? (h - 1) : h;
            float tc = g_tabc[trow*HH + u], ts = g_tabs[trow*HH + u];
            u64 tcc = pk2(tc, tc), tss = pk2(ts, ts), mtss = pk2(-ts, -ts);
            const u64* pr = (const u64*)&sre[hi*8];
            const u64* pi = (const u64*)&sim[hi*8];
            #pragma unroll
            for (int q = 0; q < 4; q++) {
                u64 fx = pr[q], fy = pi[q];
                re2[q] = ffma2(fx, tcc,  re2[q]);
                re2[q] = ffma2(fy, mtss, re2[q]);
                im2[q] = ffma2(fx, tss,  im2[q]);
                im2[q] = ffma2(fy, tcc,  im2[q]);
            }
        }
        __syncthreads();
    }
    __shared__ float2 EO[192][8];
    #pragma unroll
    for (int q = 0; q < 4; q++) {
        float2 fr = upk2(re2[q]), fi = upk2(im2[q]);
        EO[t][2*q]   = make_float2(fr.x, fi.x);
        EO[t][2*q+1] = make_float2(fr.y, fi.y);
    }
    __syncthreads();
    float wc = g_tabc[HH + u], wsn = g_tabs[HH + u];
    float sgn = isO ? -1.f : 1.f;
    const float sc = 1.0f / 192.0f;
    int chR = 2*c, chI = 2*c + 1;
    float gr = BNINV * bng[chR], br = bnb[chR];
    float gi = BNINV * bng[chI], bi = bnb[chI];
    int m = t;
    for (int kk = 0; kk < 8; kk++) {
        int k = k0 + kk;
        if (k >= NW2) break;
        float2 E = EO[u][kk], O = EO[96 + u][kk];
        float orx = O.x*wc - O.y*wsn;
        float ory = O.x*wsn + O.y*wc;
        float Xr = E.x + sgn*orx;
        float Xi = E.y + sgn*ory;
        g_frb[((size_t)(b*CH2 + chR)*HH + m)*NW2 + k] = Xr*sc*gr + br;
        g_frb[((size_t)(b*CH2 + chI)*HH + m)*NW2 + k] = Xi*sc*gi + bi;
    }
}

// ---------------- fpe: depthwise 3x3 + residual ----------------
__global__ void k_fpe(const float* __restrict__ fw, const float* __restrict__ fb) {
    int t = blockIdx.x * 256 + threadIdx.x;
    if (t >= BB*CH2*HW2) return;
    int k  = t % NW2;
    int m  = (t / NW2) % HH;
    int ch = (t / HW2) % CH2;
    const float* base = g_frb + (size_t)(t / HW2) * HW2;
    float acc = fb[ch];
    #pragma unroll
    for (int ky = -1; ky <= 1; ky++) {
        int mm = m + ky;
        if ((unsigned)mm >= HH) continue;
        #pragma unroll
        for (int kx = -1; kx <= 1; kx++) {
            int kk2 = k + kx;
            if ((unsigned)kk2 >= NW2) continue;
            acc += base[mm*NW2 + kk2] * fw[ch*9 + (ky+1)*3 + (kx+1)];
        }
    }
    g_frb2[t] = acc + base[m*NW2 + k];
}

// ---------------- fdc: 16 outs x 2 px, LDS128 weights + GELU ----------------
__global__ void __launch_bounds__(256) k_fdc(const float* __restrict__ fw,
                                             const float* __restrict__ fb) {
    int blk = blockIdx.x;
    int chunk = blk % 37;
    int og = (blk / 37) % 8;
    int b  = blk / (37 * 8);
    __shared__ __align__(16) float ws[CH2][16];
    for (int i = threadIdx.x; i < CH2*16; i += 256) {
        int o = i % 16, ci = i / 16;
        ws[ci][o] = fw[(size_t)(og*16 + o)*CH2 + ci];
    }
    __syncthreads();
    int p = chunk*512 + threadIdx.x*2;
    if (p >= HW2) return;
    const float* xb = g_frb2 + (size_t)b*CH2*HW2 + p;
    u64 a2[2][8];
    #pragma unroll
    for (int j = 0; j < 8; j++) {
        u64 bb = pk2(fb[og*16 + 2*j], fb[og*16 + 2*j+1]);
        a2[0][j] = bb; a2[1][j] = bb;
    }
    for (int ci = 0; ci < CH2; ci++) {
        float2 v = *(const float2*)(xb + (size_t)ci*HW2);
        u64 v0 = pk2(v.x, v.x), v1 = pk2(v.y, v.y);
        const ulonglong2* wp = (const ulonglong2*)&ws[ci][0];
        #pragma unroll
        for (int q = 0; q < 4; q++) {
            ulonglong2 ww = wp[q];
            a2[0][2*q]   = ffma2(v0, ww.x, a2[0][2*q]);
            a2[0][2*q+1] = ffma2(v0, ww.y, a2[0][2*q+1]);
            a2[1][2*q]   = ffma2(v1, ww.x, a2[1][2*q]);
            a2[1][2*q+1] = ffma2(v1, ww.y, a2[1][2*q+1]);
        }
    }
    #pragma unroll
    for (int j = 0; j < 8; j++) {
        float2 f0 = upk2(a2[0][j]), f1 = upk2(a2[1][j]);
        #pragma unroll
        for (int hlf = 0; hlf < 2; hlf++) {
            int oo = og*16 + 2*j + hlf;
            float a = hlf ? f0.y : f0.x;
            float bq = hlf ? f1.y : f1.x;
            float g0 = 0.5f * a  * (1.0f + erff(a  * 0.70710678118654752f));
            float g1 = 0.5f * bq * (1.0f + erff(bq * 0.70710678118654752f));
            *(float2*)(g_fd + ((size_t)b*CH2 + oo)*HW2 + p) = make_float2(g0, g1);
        }
    }
}

// ---------------- inverse H-dim FFT: SoA stage, packed kk-pairs, DIT ----------------
__global__ void k_invh() {
    int blk = blockIdx.x;
    int kg = blk % 13;
    int c  = (blk / 13) % CC;
    int b  = blk / (13 * CC);
    int k0 = kg * 8;
    int t = threadIdx.x;
    int isO = (t >= 96);
    int u = isO ? t - 96 : t;
    u64 re2[4], im2[4];
    #pragma unroll
    for (int q = 0; q < 4; q++) { re2[q] = 0ull; im2[q] = 0ull; }
    const float* fR = g_fd + (size_t)(b*CH2 + 2*c)*HW2;
    const float* fI = g_fd + (size_t)(b*CH2 + 2*c + 1)*HW2;
    __shared__ __align__(8) float sre[32*8];
    __shared__ __align__(8) float sim[32*8];
    for (int mc = 0; mc < 6; mc++) {
        for (int i = threadIdx.x; i < 32*8; i += 192) {
            int mm = mc*32 + i/8, kk = i % 8;
            float2 v = make_float2(0.f, 0.f);
            if (k0 + kk < NW2) {
                v.x = fR[mm*NW2 + k0 + kk];
                v.y = fI[mm*NW2 + k0 + kk];
            }
            sre[i] = v.x; sim[i] = v.y;
        }
        __syncthreads();
        for (int mi = isO ? 1 : 0; mi < 32; mi += 2) {
            int mm = mc*32 + mi;
            int trow = isO ? (mm - 1) : mm;
            float tc = g_tabc[trow*HH + u], ts = g_tabs[trow*HH + u];
            u64 tcc = pk2(tc, tc), tss = pk2(ts, ts), mtss = pk2(-ts, -ts);
            const u64* pr = (const u64*)&sre[mi*8];
            const u64* pi = (const u64*)&sim[mi*8];
            #pragma unroll
            for (int q = 0; q < 4; q++) {
                u64 fx = pr[q], fy = pi[q];
                re2[q] = ffma2(fx, tcc,  re2[q]);
                re2[q] = ffma2(fy, tss,  re2[q]);
                im2[q] = ffma2(fy, tcc,  im2[q]);
                im2[q] = ffma2(fx, mtss, im2[q]);
            }
        }
        __syncthreads();
    }
    __shared__ float2 AB[192][8];
    #pragma unroll
    for (int q = 0; q < 4; q++) {
        float2 fr = upk2(re2[q]), fi = upk2(im2[q]);
        AB[t][2*q]   = make_float2(fr.x, fi.x);
        AB[t][2*q+1] = make_float2(fr.y, fi.y);
    }
    __syncthreads();
    float wc = g_tabc[HH + u], wsn = g_tabs[HH + u];
    float sgn = isO ? -1.f : 1.f;
    int h = t;
    for (int kk = 0; kk < 8; kk++) {
        int k = k0 + kk;
        if (k >= NW2) break;
        float2 A = AB[u][kk], Bv = AB[96 + u][kk];
        float brx = Bv.x*wc + Bv.y*wsn;
        float bry = Bv.y*wc - Bv.x*wsn;
        size_t o = (((size_t)(b*CC + c)*HH + h)*NW2 + k)*2;
        g_gh[o]   = A.x + sgn*brx;
        g_gh[o+1] = A.y + sgn*bry;
    }
}

// ---------------- irfft over W (packed float2 stage) + add xc ----------------
__global__ void k_final(float* __restrict__ out) {
    int blk = blockIdx.x;
    int hg = blk % 24;
    int c  = (blk / 24) % CC;
    int b  = blk / (24 * CC);
    int h0 = hg * 8;
    __shared__ float2 ghc[8][NW2];
    const float2* ghp = (const float2*)g_gh;
    for (int i = threadIdx.x; i < 8*NW2; i += 192) {
        int r = i / NW2, k = i % NW2;
        ghc[r][k] = ghp[((size_t)(b*CC + c)*HH + h0 + r)*NW2 + k];
    }
    __syncthreads();
    int w = threadIdx.x;
    u64 acc2[8];
    #pragma unroll
    for (int r = 0; r < 8; r++) acc2[r] = 0ull;
    for (int k = 1; k < 96; k++) {
        float tc = g_tabc[k*HH + w], ts = g_tabs[k*HH + w];
        u64 tt = pk2(tc, ts);
        const u64* gp = (const u64*)&ghc[0][0];
        #pragma unroll
        for (int r = 0; r < 8; r++)
            acc2[r] = ffma2(gp[r*NW2 + k], tt, acc2[r]);
    }
    float par = (w & 1) ? -1.0f : 1.0f;
    const float* xcb2 = g_xn + ((size_t)b*CC + c)*HWP + (size_t)h0*WWD + w;
    #pragma unroll
    for (int r = 0; r < 8; r++) {
        float2 f = upk2(acc2[r]);
        float of = (ghc[r][0].x + ghc[r][96].x*par + 2.0f*(f.x + f.y)) * (1.0f/192.0f);
        out[((size_t)b*CC + c)*HWP + (size_t)(h0 + r)*WWD + w] = xcb2[r*WWD] + of;
    }
}

// ---------------- launch ----------------
extern "C" void kernel_launch(void* const* d_in, const int* in_sizes, int n_in,
                              void* d_out, int out_size) {
    const float* x    = (const float*)d_in[0];
    const float* cdw  = (const float*)d_in[1];
    const float* lng  = (const float*)d_in[2];
    const float* lnb  = (const float*)d_in[3];
    const float* qw   = (const float*)d_in[4];
    const float* kw   = (const float*)d_in[5];
    const float* vw   = (const float*)d_in[6];
    const float* spw  = (const float*)d_in[7];
    const float* lw   = (const float*)d_in[8];
    const float* lb   = (const float*)d_in[9];
    const float* bng  = (const float*)d_in[10];
    const float* bnb  = (const float*)d_in[11];
    const float* fpew = (const float*)d_in[12];
    const float* fpeb = (const float*)d_in[13];
    const float* fdcw = (const float*)d_in[16];
    const float* fdcb = (const float*)d_in[17];
    const float* xcw  = (const float*)d_in[18];
    const float* xcb  = (const float*)d_in[19];
    const float* bn2g = (const float*)d_in[20];
    const float* bn2b = (const float*)d_in[21];
    float* out = (float*)d_out;

    k_tab<<<144, 256>>>();
    k_cdsum<<<16, 256>>>(cdw);
    k_nop<<<1, 32>>>();                       // keep ncu slot on k_contrast
    k_contrast<<<BB*4*96, 192>>>(x, cdw);
    k_centinit<<<144, 256>>>(x);
    k_centsq<<<5, 128>>>();
    k_dist<<<288, 256>>>(x);
    k_asum<<<36, 256>>>();
    k_centupd<<<144, 256>>>(x);
    k_centsq<<<5, 128>>>();
    k_dist<<<288, 256>>>(x);
    k_asum<<<36, 256>>>();
    k_lnorm<<<288, 256>>>(x, lng, lnb);
    k_stoken<<<72, 256>>>();
    k_stokmm<<<72, 256>>>(spw);
    k_qkv<<<BB*12*72, 256>>>(qw, kw, vw);
    k_lepe<<<BB*576, 256>>>(lw, lb);
    k_sattn<<<BB*NHD*(NSS/STILE), 256>>>();
    k_xattn<<<BB*NHD*144, 256>>>(x);
    k_xc<<<BB*4*72, 256>>>(xcw, xcb, bn2g, bn2b);
    k_fftw<<<BB*CC*12, 192>>>();
    k_ffth<<<BB*CC*13, 192>>>(bng, bnb);
    k_fpe<<<(BB*CH2*HW2 + 255)/256, 256>>>(fpew, fpeb);
    k_fdc<<<BB*8*37, 256>>>(fdcw, fdcb);
    k_invh<<<BB*CC*13, 192>>>();
    k_final<<<BB*CC*24, 192>>>(out);
}

// round 16
// speedup vs baseline: 1.9301x; 1.0446x over previous
#include <cuda_runtime.h>
#include <math.h>

#define BB 2
#define CC 64
#define HH 192
#define WWD 192
#define HWP 36864
#define NHD 4
#define DDIM 16
#define NSS 144
#define NHSS 12
#define SHH 16
#define NW2 97
#define HW2 18624
#define CH2 128
#define THETA 0.7f
#define ATTNSCALE 0.25f
#define BNINV 0.9999950000374997f

typedef unsigned long long u64;
__device__ __forceinline__ u64 pk2(float lo, float hi) {
    u64 r; asm("mov.b64 %0,{%1,%2};" : "=l"(r) : "f"(lo), "f"(hi)); return r;
}
__device__ __forceinline__ float2 upk2(u64 v) {
    float2 f; asm("mov.b64 {%0,%1},%2;" : "=f"(f.x), "=f"(f.y) : "l"(v)); return f;
}
__device__ __forceinline__ u64 ffma2(u64 a, u64 b, u64 c) {
    u64 d; asm("fma.rn.f32x2 %0,%1,%2,%3;" : "=l"(d) : "l"(a), "l"(b), "l"(c)); return d;
}

// ---------------- scratch ----------------
static __device__ float g_tabc[HH*HH];
static __device__ float g_tabs[HH*HH];
static __device__ float2 g_tab2[HH*HH];
static __device__ float g_cdsum[CC*CC];
static __device__ float g_contrast[BB*CC*HWP];
static __device__ float g_cent[BB*NSS*2*CC];   // layout [b][s][2C]
static __device__ float g_csq[BB*2*NSS];       // [b][half][s]
static __device__ float g_asum[BB*NSS];
static __device__ float g_aff[BB*9*HWP];
static __device__ float g_xn[BB*CC*HWP];       // after k_xattn: reused as xc-relu output
static __device__ float g_q[BB*CC*HWP];
static __device__ float g_k[BB*CC*HWP];
static __device__ float g_v[BB*CC*HWP];
static __device__ float g_lepe[BB*CC*HWP];
static __device__ float g_stoken[BB*NSS*CC];
static __device__ float g_stok[BB*CC*NSS];
static __device__ float g_sout[BB*CC*NSS];
static __device__ float g_x2[BB*CC*HWP];
static __device__ float g_fw[BB*CC*HH*NW2*2];
static __device__ float g_frb[BB*CH2*HW2];
static __device__ float g_frb2[BB*CH2*HW2];
static __device__ float g_fd[BB*CH2*HW2];
static __device__ float g_gh[BB*CC*HH*NW2*2];
static __device__ float g_dummy;

// ---------------- nop: keeps ncu capture slot on k_contrast ----------------
__global__ void k_nop() { if (threadIdx.x == 1024) g_dummy = 0.f; }

// ---------------- twiddle table ----------------
__global__ void k_tab() {
    int t = blockIdx.x * blockDim.x + threadIdx.x;
    if (t >= HH*HH) return;
    int i = t / HH, j = t % HH;
    int r = (i * j) % HH;
    float s, c;
    sincospif(-(float)r / 96.0f, &s, &c);
    g_tabc[t] = c;
    g_tabs[t] = s;
    g_tab2[t] = make_float2(c, s);
}

__global__ void k_cdsum(const float* __restrict__ cdw) {
    int t = blockIdx.x * blockDim.x + threadIdx.x;
    if (t >= CC*CC) return;
    float s = 0.f;
    #pragma unroll
    for (int k = 0; k < 9; k++) s += cdw[t*9 + k];
    g_cdsum[t] = s;
}

// ---------------- contrast: row-pair blocks, folded center tap, LDS128 weights ----------------
__global__ void __launch_bounds__(192, 5) k_contrast(const float* __restrict__ x,
                                                     const float* __restrict__ cdw) {
    int blk = blockIdx.x;
    int hp = blk % 96;
    int og = (blk / 96) % 4;
    int b  = blk / (96 * 4);
    __shared__ __align__(16) float ws[CC][9][16];
    for (int i = threadIdx.x; i < CC*9*16; i += 192) {
        int o = i % 16;
        int tap = (i / 16) % 9;
        int ci = i / 144;
        int oo = og*16 + o;
        float wv = cdw[((size_t)oo*CC + ci)*9 + tap];
        if (tap == 4) wv -= THETA * g_cdsum[oo*CC + ci];
        ws[ci][tap][o] = wv;
    }
    __syncthreads();
    int w = threadIdx.x;
    int h0 = hp * 2;
    u64 a2[2][8];
    #pragma unroll
    for (int px = 0; px < 2; px++)
        #pragma unroll
        for (int j = 0; j < 8; j++) a2[px][j] = 0ull;
    const float* xb = x + (size_t)b * CC * HWP;
    bool wl = (w > 0), wr = (w < WWD-1);
    for (int ci = 0; ci < CC; ci++) {
        const float* xc = xb + (size_t)ci * HWP;
        float rv[4][3];
        #pragma unroll
        for (int rr = 0; rr < 4; rr++) {
            int row = h0 - 1 + rr;
            bool rok = ((unsigned)row < HH);
            const float* rp = xc + row*WWD + w;
            rv[rr][0] = (rok && wl) ? rp[-1] : 0.f;
            rv[rr][1] = rok ? rp[0] : 0.f;
            rv[rr][2] = (rok && wr) ? rp[1] : 0.f;
        }
        #pragma unroll
        for (int tap = 0; tap < 9; tap++) {
            int ky = tap / 3, kx = tap % 3;
            u64 v0 = pk2(rv[ky][kx],   rv[ky][kx]);
            u64 v1 = pk2(rv[ky+1][kx], rv[ky+1][kx]);
            const ulonglong2* wp = (const ulonglong2*)&ws[ci][tap][0];
            #pragma unroll
            for (int q = 0; q < 4; q++) {
                ulonglong2 ww = wp[q];
                a2[0][2*q]   = ffma2(v0, ww.x, a2[0][2*q]);
                a2[0][2*q+1] = ffma2(v0, ww.y, a2[0][2*q+1]);
                a2[1][2*q]   = ffma2(v1, ww.x, a2[1][2*q]);
                a2[1][2*q+1] = ffma2(v1, ww.y, a2[1][2*q+1]);
            }
        }
    }
    #pragma unroll
    for (int px = 0; px < 2; px++) {
        int p = (h0 + px)*WWD + w;
        #pragma unroll
        for (int j = 0; j < 8; j++) {
            float2 f = upk2(a2[px][j]);
            g_contrast[((size_t)b*CC + og*16 + 2*j  )*HWP + p] = f.x;
            g_contrast[((size_t)b*CC + og*16 + 2*j+1)*HWP + p] = f.y;
        }
    }
}

// ---------------- cent init: ch-fastest, float4 gather, [b][s][2C] layout ----------------
__global__ void k_centinit(const float* __restrict__ x) {
    int t = blockIdx.x * 256 + threadIdx.x;
    if (t >= BB*2*CC*NSS) return;
    int ch = t % (2*CC);
    int s  = (t / (2*CC)) % NSS;
    int b  = t / (NSS * 2 * CC);
    const float* src = (ch < CC) ? (x + ((size_t)b*CC + ch)*HWP)
                                 : (g_contrast + ((size_t)b*CC + (ch-CC))*HWP);
    int r0 = s / NHSS, c0 = s % NHSS;
    const float4* sp = (const float4*)(src + (r0*SHH)*WWD + c0*SHH);
    float acc = 0.f;
    for (int i = 0; i < SHH; i++) {
        #pragma unroll
        for (int jj = 0; jj < 4; jj++) {
            float4 v = sp[i*48 + jj];
            acc += v.x; acc += v.y; acc += v.z; acc += v.w;
        }
    }
    g_cent[((size_t)b*NSS + s)*2*CC + ch] = acc * (1.0f/256.0f);
}

// ---------------- cent squared-norm per (b, half, s) ----------------
__global__ void k_centsq() {
    int t = blockIdx.x * 128 + threadIdx.x;
    if (t >= BB*2*NSS) return;
    int s = t % NSS;
    int half = (t / NSS) % 2;
    int b = t / (2*NSS);
    const float4* cb = (const float4*)(g_cent + ((size_t)b*NSS + s)*2*CC + half*CC);
    float acc = 0.f;
    #pragma unroll
    for (int i = 0; i < CC/4; i++) {
        float4 v = cb[i];
        acc += v.x*v.x; acc += v.y*v.y; acc += v.z*v.z; acc += v.w*v.w;
    }
    g_csq[((size_t)b*2 + half)*NSS + s] = acc;
}

// ---------------- distances via p2 - 2g + s2 (reference trick), packed pairs ----------------
__global__ void k_dist(const float* __restrict__ x) {
    int t = blockIdx.x * 256 + threadIdx.x;
    if (t >= BB*HWP) return;
    int p = t % HWP, b = t / HWP;
    int h = p / WWD, w = p % WWD;
    int r = h / SHH, c = w / SHH;
    int cs[9];
    int val[9];
    #pragma unroll
    for (int j = 0; j < 9; j++) {
        int dy = j/3 - 1, dx = j%3 - 1;
        int rr = r + dy, cc2 = c + dx;
        val[j] = (rr >= 0 && rr < NHSS && cc2 >= 0 && cc2 < NHSS);
        cs[j]  = val[j] ? rr*NHSS + cc2 : 0;
    }
    const float* ct = g_cent + (size_t)b*NSS*2*CC;
    const float* rowp[9];
    #pragma unroll
    for (int j = 0; j < 9; j++) rowp[j] = ct + (size_t)cs[j]*2*CC;

    u64 g2[9];
    #pragma unroll
    for (int j = 0; j < 9; j++) g2[j] = 0ull;
    float p2a = 0.f;
    const float* xb = x + (size_t)b*CC*HWP + p;
    for (int ch = 0; ch < CC; ch += 2) {
        float pix0 = xb[(size_t)ch*HWP];
        float pix1 = xb[(size_t)(ch+1)*HWP];
        p2a = fmaf(pix0, pix0, p2a);
        p2a = fmaf(pix1, pix1, p2a);
        u64 px = pk2(pix0, pix1);
        #pragma unroll
        for (int j = 0; j < 9; j++)
            g2[j] = ffma2(px, *(const u64*)(rowp[j] + ch), g2[j]);
    }
    const float* sqa = g_csq + (size_t)b*2*NSS;
    float d[9];
    #pragma unroll
    for (int j = 0; j < 9; j++) {
        float2 f = upk2(g2[j]);
        d[j] = p2a - 2.0f*(f.x + f.y) + sqa[cs[j]];
        g2[j] = 0ull;
    }
    float p2b = 0.f;
    const float* cbq = g_contrast + (size_t)b*CC*HWP + p;
    for (int ch = 0; ch < CC; ch += 2) {
        float pix0 = cbq[(size_t)ch*HWP];
        float pix1 = cbq[(size_t)(ch+1)*HWP];
        p2b = fmaf(pix0, pix0, p2b);
        p2b = fmaf(pix1, pix1, p2b);
        u64 px = pk2(pix0, pix1);
        #pragma unroll
        for (int j = 0; j < 9; j++)
            g2[j] = ffma2(px, *(const u64*)(rowp[j] + CC + ch), g2[j]);
    }
    const float* sqb = sqa + NSS;
    #pragma unroll
    for (int j = 0; j < 9; j++) {
        float2 f = upk2(g2[j]);
        d[j] += 10.0f * (p2b - 2.0f*(f.x + f.y) + sqb[cs[j]]);
    }
    float m = 3.0e38f;
    #pragma unroll
    for (int j = 0; j < 9; j++) if (val[j] && d[j] < m) m = d[j];
    float e[9], sum = 0.f;
    #pragma unroll
    for (int j = 0; j < 9; j++) {
        e[j] = val[j] ? __expf(m - d[j]) : 0.f;
        sum += e[j];
    }
    float inv = 1.0f / sum;
    #pragma unroll
    for (int j = 0; j < 9; j++)
        g_aff[((size_t)b*9 + j)*HWP + p] = e[j] * inv;
}

// ---------------- asum: one warp per (b,s), float4 + shfl ----------------
__global__ void k_asum() {
    int wid = (blockIdx.x * 256 + threadIdx.x) >> 5;
    int lane = threadIdx.x & 31;
    if (wid >= BB*NSS) return;
    int s = wid % NSS, b = wid / NSS;
    int r0 = s / NHSS, c0 = s % NHSS;
    float acc = 0.f;
    for (int dy = -1; dy <= 1; dy++) {
        int r = r0 - dy;
        if ((unsigned)r >= NHSS) continue;
        for (int dx = -1; dx <= 1; dx++) {
            int c = c0 - dx;
            if ((unsigned)c >= NHSS) continue;
            int j = (dy+1)*3 + (dx+1);
            const float4* ab = (const float4*)(g_aff + ((size_t)b*9 + j)*HWP
                                               + (r*SHH)*WWD + c*SHH);
            for (int idx = lane; idx < 64; idx += 32) {
                int i = idx >> 2, jj = idx & 3;
                float4 v = ab[i*48 + jj];
                acc += v.x; acc += v.y; acc += v.z; acc += v.w;
            }
        }
    }
    #pragma unroll
    for (int o = 16; o > 0; o >>= 1) acc += __shfl_down_sync(0xffffffffu, acc, o);
    if (lane == 0) g_asum[wid] = acc;
}

// ---------------- cent update: ch-fastest (aff broadcast), float4, [b][s][2C] write ----------------
__global__ void k_centupd(const float* __restrict__ x) {
    int t = blockIdx.x * 256 + threadIdx.x;
    if (t >= BB*2*CC*NSS) return;
    int ch = t % (2*CC);
    int s  = (t / (2*CC)) % NSS;
    int b  = t / (NSS * 2 * CC);
    const float* src = (ch < CC) ? (x + ((size_t)b*CC + ch)*HWP)
                                 : (g_contrast + ((size_t)b*CC + (ch-CC))*HWP);
    int r0 = s / NHSS, c0 = s % NHSS;
    float acc = 0.f;
    for (int dy = -1; dy <= 1; dy++) {
        int r = r0 - dy;
        if ((unsigned)r >= NHSS) continue;
        for (int dx = -1; dx <= 1; dx++) {
            int c = c0 - dx;
            if ((unsigned)c >= NHSS) continue;
            int j = (dy+1)*3 + (dx+1);
            int pb = (r*SHH)*WWD + c*SHH;
            const float4* ar = (const float4*)(g_aff + ((size_t)b*9 + j)*HWP + pb);
            const float4* sr = (const float4*)(src + pb);
            for (int i = 0; i < SHH; i++) {
                #pragma unroll
                for (int jj = 0; jj < 4; jj++) {
                    float4 a = ar[i*48 + jj];
                    float4 v = sr[i*48 + jj];
                    acc += a.x*v.x; acc += a.y*v.y; acc += a.z*v.z; acc += a.w*v.w;
                }
            }
        }
    }
    g_cent[((size_t)b*NSS + s)*2*CC + ch] = acc / (g_asum[(size_t)b*NSS + s] + 1e-16f);
}

// ---------------- LayerNorm ----------------
__global__ void k_lnorm(const float* __restrict__ x, const float* __restrict__ g,
                        const float* __restrict__ bta) {
    int t = blockIdx.x * 256 + threadIdx.x;
    if (t >= BB*HWP) return;
    int p = t % HWP, b = t / HWP;
    const float* xb = x + (size_t)b*CC*HWP + p;
    float sum = 0.f, sq = 0.f;
    for (int ch = 0; ch < CC; ch++) {
        float v = xb[(size_t)ch*HWP];
        sum += v; sq += v*v;
    }
    float mu = sum * (1.0f/CC);
    float var = sq * (1.0f/CC) - mu*mu;
    float rstd = rsqrtf(var + 1e-6f);
    float* ob = g_xn + (size_t)b*CC*HWP + p;
    for (int ch = 0; ch < CC; ch++) {
        float v = xb[(size_t)ch*HWP];
        ob[(size_t)ch*HWP] = (v - mu) * rstd * g[ch] + bta[ch];
    }
}

// ---------------- stoken gather: ch-fastest (aff broadcast), float4 ----------------
__global__ void k_stoken() {
    int t = blockIdx.x * 256 + threadIdx.x;
    if (t >= BB*NSS*CC) return;
    int ch = t % CC;
    int s  = (t / CC) % NSS;
    int b  = t / (CC * NSS);
    const float* src = g_xn + ((size_t)b*CC + ch)*HWP;
    int r0 = s / NHSS, c0 = s % NHSS;
    float acc = 0.f;
    for (int dy = -1; dy <= 1; dy++) {
        int r = r0 - dy;
        if ((unsigned)r >= NHSS) continue;
        for (int dx = -1; dx <= 1; dx++) {
            int c = c0 - dx;
            if ((unsigned)c >= NHSS) continue;
            int j = (dy+1)*3 + (dx+1);
            int pb = (r*SHH)*WWD + c*SHH;
            const float4* ar = (const float4*)(g_aff + ((size_t)b*9 + j)*HWP + pb);
            const float4* sr = (const float4*)(src + pb);
            for (int i = 0; i < SHH; i++) {
                #pragma unroll
                for (int jj = 0; jj < 4; jj++) {
                    float4 a = ar[i*48 + jj];
                    float4 v = sr[i*48 + jj];
                    acc += a.x*v.x; acc += a.y*v.y; acc += a.z*v.z; acc += a.w*v.w;
                }
            }
        }
    }
    g_stoken[((size_t)b*NSS + s)*CC + ch] = acc / (g_asum[(size_t)b*NSS + s] + 1e-16f);
}

// ---------------- stok = stoken @ sp_w^T ----------------
__global__ void k_stokmm(const float* __restrict__ spw) {
    int t = blockIdx.x * 256 + threadIdx.x;
    if (t >= BB*CC*NSS) return;
    int s = t % NSS;
    int o = (t / NSS) % CC;
    int b = t / (NSS * CC);
    const float* st = g_stoken + ((size_t)b*NSS + s)*CC;
    const float* w  = spw + o*CC;
    float acc = 0.f;
    #pragma unroll 8
    for (int c = 0; c < CC; c++) acc += w[c] * st[c];
    g_stok[((size_t)b*CC + o)*NSS + s] = acc;
}

// ---------------- q/k/v: 16 outs x 2 px per thread, LDS128 weights ----------------
__global__ void __launch_bounds__(256) k_qkv(const float* __restrict__ qw,
                                             const float* __restrict__ kw,
                                             const float* __restrict__ vw) {
    int blk = blockIdx.x;
    int chunk = blk % 72;
    int og = (blk / 72) % 12;
    int b  = blk / (72 * 12);
    __shared__ __align__(16) float ws[CC][16];
    for (int i = threadIdx.x; i < CC*16; i += 256) {
        int o = i % 16, ci = i / 16;
        int oo = og*16 + o;
        const float* wsrc = (oo < 64) ? (qw + oo*CC)
                          : (oo < 128 ? kw + (oo-64)*CC : vw + (oo-128)*CC);
        ws[ci][o] = wsrc[ci];
    }
    __syncthreads();
    int p = chunk*512 + threadIdx.x*2;
    const float* xb = g_xn + (size_t)b*CC*HWP + p;
    u64 a2[2][8];
    #pragma unroll
    for (int px = 0; px < 2; px++)
        #pragma unroll
        for (int j = 0; j < 8; j++) a2[px][j] = 0ull;
    for (int ci = 0; ci < CC; ci++) {
        float2 v = *(const float2*)(xb + (size_t)ci*HWP);
        u64 v0 = pk2(v.x, v.x), v1 = pk2(v.y, v.y);
        const ulonglong2* wp = (const ulonglong2*)&ws[ci][0];
        #pragma unroll
        for (int q = 0; q < 4; q++) {
            ulonglong2 ww = wp[q];
            a2[0][2*q]   = ffma2(v0, ww.x, a2[0][2*q]);
            a2[0][2*q+1] = ffma2(v0, ww.y, a2[0][2*q+1]);
            a2[1][2*q]   = ffma2(v1, ww.x, a2[1][2*q]);
            a2[1][2*q+1] = ffma2(v1, ww.y, a2[1][2*q+1]);
        }
    }
    #pragma unroll
    for (int j = 0; j < 8; j++) {
        float2 f0 = upk2(a2[0][j]), f1 = upk2(a2[1][j]);
        #pragma unroll
        for (int hlf = 0; hlf < 2; hlf++) {
            int oo = og*16 + 2*j + hlf;
            float lo = hlf ? f0.y : f0.x;
            float hi = hlf ? f1.y : f1.x;
            float* dst = (oo < 64) ? (g_q + ((size_t)b*64 + oo)*HWP)
                       : (oo < 128 ? (g_k + ((size_t)b*64 + oo-64)*HWP)
                                   : (g_v + ((size_t)b*64 + oo-128)*HWP));
            *(float2*)(dst + p) = make_float2(lo, hi);
        }
    }
}

// ---------------- lepe: coalesced Tflat write ----------------
__global__ void __launch_bounds__(256) k_lepe(const float* __restrict__ lw,
                                              const float* __restrict__ lb) {
    __shared__ float ws[CC*9];
    __shared__ float bs[CC];
    for (int i = threadIdx.x; i < CC*9; i += 256) ws[i] = lw[i];
    if (threadIdx.x < CC) bs[threadIdx.x] = lb[threadIdx.x];
    __syncthreads();
    int blk = blockIdx.x;
    int pblk = blk % 576;
    int b = blk / 576;
    int cg = threadIdx.x & 3;
    int pl = threadIdx.x >> 2;
    int p = pblk * 64 + pl;
    int h = p / WWD, w = p % WWD;
    int off[9];
    bool vld[9];
    #pragma unroll
    for (int tap = 0; tap < 9; tap++) {
        int ky = tap/3 - 1, kx = tap%3 - 1;
        int hh = h + ky, ww = w + kx;
        vld[tap] = ((unsigned)hh < HH) && ((unsigned)ww < WWD);
        off[tap] = hh*WWD + ww;
    }
    const float* vb = g_v + (size_t)b*CC*HWP;
    float o[16];
    #pragma unroll
    for (int j = 0; j < 16; j++) {
        int c = cg*16 + j;
        const float* vc = vb + (size_t)c*HWP;
        float acc = bs[c];
        #pragma unroll
        for (int tap = 0; tap < 9; tap++)
            if (vld[tap]) acc += vc[off[tap]] * ws[c*9 + tap];
        o[j] = acc;
    }
    float4* dst = (float4*)(g_lepe + (size_t)b*CC*HWP + (size_t)p*CC + cg*16);
    #pragma unroll
    for (int q = 0; q < 4; q++)
        dst[q] = make_float4(o[q*4], o[q*4+1], o[q*4+2], o[q*4+3]);
}

// ---------------- s_attn: packed, STILE=8, LDS128 stok ----------------
#define STILE 8
__global__ void __launch_bounds__(256) k_sattn() {
    int blk = blockIdx.x;
    int sg = blk % (NSS/STILE);
    int hh = (blk / (NSS/STILE)) % NHD;
    int b  = blk / ((NSS/STILE) * NHD);
    int s0 = sg * STILE;
    int tid = threadIdx.x;
    __shared__ __align__(16) u64 stks2[STILE][8];
    if (tid < STILE*8) {
        int si = tid / 8, j = tid % 8;
        size_t base = (size_t)(b*NHD + hh)*DDIM;
        stks2[si][j] = pk2(g_stok[(base + 2*j  )*NSS + s0 + si],
                           g_stok[(base + 2*j+1)*NSS + s0 + si]);
    }
    __syncthreads();
    float l[STILE];
    u64 acc2[STILE][8];
    #pragma unroll
    for (int si = 0; si < STILE; si++) {
        l[si] = 0.f;
        #pragma unroll
        for (int j = 0; j < 8; j++) acc2[si][j] = 0ull;
    }
    const float* kb = g_k + (size_t)(b*NHD + hh)*DDIM*HWP;
    const float* vb = g_v + (size_t)(b*NHD + hh)*DDIM*HWP;
    for (int p = tid; p < HWP; p += 256) {
        u64 kd2[8], vd2[8];
        #pragma unroll
        for (int j = 0; j < 8; j++)
            kd2[j] = pk2(kb[(size_t)(2*j)*HWP + p], kb[(size_t)(2*j+1)*HWP + p]);
        #pragma unroll
        for (int j = 0; j < 8; j++)
            vd2[j] = pk2(vb[(size_t)(2*j)*HWP + p], vb[(size_t)(2*j+1)*HWP + p]);
        #pragma unroll
        for (int si = 0; si < STILE; si++) {
            const ulonglong2* sp = (const ulonglong2*)&stks2[si][0];
            u64 dp = 0ull;
            #pragma unroll
            for (int q = 0; q < 4; q++) {
                ulonglong2 ss = sp[q];
                dp = ffma2(kd2[2*q],   ss.x, dp);
                dp = ffma2(kd2[2*q+1], ss.y, dp);
            }
            float2 f = upk2(dp);
            float e = __expf((f.x + f.y) * ATTNSCALE);
            l[si] += e;
            u64 ee = pk2(e, e);
            #pragma unroll
            for (int j = 0; j < 8; j++) acc2[si][j] = ffma2(ee, vd2[j], acc2[si][j]);
        }
    }
    __shared__ float rl[256], ra[DDIM*256];
    for (int si = 0; si < STILE; si++) {
        rl[tid] = l[si];
        #pragma unroll
        for (int j = 0; j < 8; j++) {
            float2 f = upk2(acc2[si][j]);
            ra[(2*j  )*256 + tid] = f.x;
            ra[(2*j+1)*256 + tid] = f.y;
        }
        __syncthreads();
        for (int str = 128; str > 0; str >>= 1) {
            if (tid < str) {
                rl[tid] += rl[tid + str];
                #pragma unroll
                for (int d = 0; d < DDIM; d++)
                    ra[d*256 + tid] += ra[d*256 + tid + str];
            }
            __syncthreads();
        }
        if (tid < DDIM)
            g_sout[((size_t)(b*NHD + hh)*DDIM + tid)*NSS + s0 + si] = ra[tid*256] / rl[0];
        __syncthreads();
    }
}

// ---------------- x_attn: packed single-pass, LDS128 tables ----------------
__global__ void __launch_bounds__(256) k_xattn(const float* __restrict__ x) {
    int blk = blockIdx.x;
    int chunk = blk % 144;
    int hh = (blk / 144) % NHD;
    int b  = blk / (144 * NHD);
    int tid = threadIdx.x;
    __shared__ __align__(16) u64 stp[NSS*10];
    __shared__ __align__(16) u64 sop[NSS*10];
    size_t base = (size_t)(b*NHD + hh)*DDIM*NSS;
    for (int i = tid; i < NSS*8; i += 256) {
        int j = i / NSS, s = i % NSS;
        stp[s*10 + j] = pk2(g_stok[base + (2*j)*NSS + s], g_stok[base + (2*j+1)*NSS + s]);
        sop[s*10 + j] = pk2(g_sout[base + (2*j)*NSS + s], g_sout[base + (2*j+1)*NSS + s]);
    }
    __syncthreads();
    int p = chunk * 256 + tid;
    u64 qd2[8];
    #pragma unroll
    for (int j = 0; j < 8; j++)
        qd2[j] = pk2(g_q[((size_t)(b*NHD + hh)*DDIM + 2*j  )*HWP + p],
                     g_q[((size_t)(b*NHD + hh)*DDIM + 2*j+1)*HWP + p]);
    float l = 0.f;
    u64 acc2[8];
    #pragma unroll
    for (int j = 0; j < 8; j++) acc2[j] = 0ull;
    for (int s = 0; s < NSS; s++) {
        const ulonglong2* sp = (const ulonglong2*)&stp[s*10];
        u64 dp = 0ull;
        #pragma unroll
        for (int q = 0; q < 4; q++) {
            ulonglong2 ss = sp[q];
            dp = ffma2(qd2[2*q],   ss.x, dp);
            dp = ffma2(qd2[2*q+1], ss.y, dp);
        }
        float2 f = upk2(dp);
        float e = __expf((f.x + f.y) * ATTNSCALE);
        l += e;
        u64 ee = pk2(e, e);
        const ulonglong2* op = (const ulonglong2*)&sop[s*10];
        #pragma unroll
        for (int q = 0; q < 4; q++) {
            ulonglong2 oo = op[q];
            acc2[2*q]   = ffma2(ee, oo.x, acc2[2*q]);
            acc2[2*q+1] = ffma2(ee, oo.y, acc2[2*q+1]);
        }
    }
    float invl = 1.0f / l;
    #pragma unroll
    for (int j = 0; j < 8; j++) {
        float2 f = upk2(acc2[j]);
        #pragma unroll
        for (int hlf = 0; hlf < 2; hlf++) {
            int cch = hh*DDIM + 2*j + hlf;
            size_t o = ((size_t)b*CC + cch)*HWP + p;
            g_x2[o] = x[o] + (hlf ? f.y : f.x)*invl + g_lepe[o];
        }
    }
}

// ---------------- xc: 16 outs x 2 px, LDS128 weights, relu'd into g_xn ----------------
__global__ void __launch_bounds__(256) k_xc(const float* __restrict__ xcw,
                                            const float* __restrict__ xcb,
                                            const float* __restrict__ bn2g,
                                            const float* __restrict__ bn2b) {
    int blk = blockIdx.x;
    int chunk = blk % 72;
    int og = (blk / 72) % 4;
    int b  = blk / (72 * 4);
    __shared__ __align__(16) float ws[CC][16];
    for (int i = threadIdx.x; i < CC*16; i += 256) {
        int o = i % 16, ci = i / 16;
        ws[ci][o] = xcw[(size_t)(og*16 + o)*CC + ci];
    }
    __syncthreads();
    int p = chunk*512 + threadIdx.x*2;
    const float* xb = g_x2 + (size_t)b*CC*HWP + p;
    u64 a2[2][8];
    #pragma unroll
    for (int px = 0; px < 2; px++)
        #pragma unroll
        for (int j = 0; j < 8; j++) a2[px][j] = 0ull;
    for (int ci = 0; ci < CC; ci++) {
        float2 v = *(const float2*)(xb + (size_t)ci*HWP);
        u64 v0 = pk2(v.x, v.x), v1 = pk2(v.y, v.y);
        const ulonglong2* wp = (const ulonglong2*)&ws[ci][0];
        #pragma unroll
        for (int q = 0; q < 4; q++) {
            ulonglong2 ww = wp[q];
            a2[0][2*q]   = ffma2(v0, ww.x, a2[0][2*q]);
            a2[0][2*q+1] = ffma2(v0, ww.y, a2[0][2*q+1]);
            a2[1][2*q]   = ffma2(v1, ww.x, a2[1][2*q]);
            a2[1][2*q+1] = ffma2(v1, ww.y, a2[1][2*q+1]);
        }
    }
    #pragma unroll
    for (int j = 0; j < 8; j++) {
        float2 f0 = upk2(a2[0][j]), f1 = upk2(a2[1][j]);
        #pragma unroll
        for (int hlf = 0; hlf < 2; hlf++) {
            int oo = og*16 + 2*j + hlf;
            float gbn = BNINV * bn2g[oo], bbn = bn2b[oo], bias = xcb[oo];
            float lo = ((hlf ? f0.y : f0.x) + bias) * gbn + bbn;
            float hi = ((hlf ? f1.y : f1.x) + bias) * gbn + bbn;
            *(float2*)(g_xn + ((size_t)b*CC + oo)*HWP + p) =
                make_float2(fmaxf(lo, 0.0f), fmaxf(hi, 0.0f));
        }
    }
}

// ---------------- W-dim rfft: even/odd DIT over w, 192 threads ----------------
__global__ void __launch_bounds__(192) k_fftw() {
    int blk = blockIdx.x;
    int hg = blk % 12;
    int c  = (blk / 12) % CC;
    int b  = blk / (12 * CC);
    int h0 = hg * 16;
    __shared__ float rows[WWD][18];
    for (int i = threadIdx.x; i < 16*WWD; i += 192) {
        int r = i / WWD, w = i % WWD;
        rows[w][r] = g_x2[((size_t)b*CC + c)*HWP + (size_t)(h0 + r)*WWD + w];
    }
    __syncthreads();
    int t = threadIdx.x;
    int isO = (t >= 96);
    int u = isO ? t - 96 : t;
    u64 re2[8], im2[8];
    #pragma unroll
    for (int j = 0; j < 8; j++) { re2[j] = 0ull; im2[j] = 0ull; }
    for (int wi = 0; wi < 96; wi++) {
        int w = 2*wi + isO;
        float tc = g_tabc[(2*wi)*HH + u], ts = g_tabs[(2*wi)*HH + u];
        u64 tcc = pk2(tc, tc), tss = pk2(ts, ts);
        const u64* vp = (const u64*)&rows[w][0];
        #pragma unroll
        for (int j = 0; j < 8; j++) {
            u64 v2 = vp[j];
            re2[j] = ffma2(v2, tcc, re2[j]);
            im2[j] = ffma2(v2, tss, im2[j]);
        }
    }
    __shared__ u64 Er[192][8];
    __shared__ u64 Ei[192][8];
    #pragma unroll
    for (int j = 0; j < 8; j++) { Er[t][j] = re2[j]; Ei[t][j] = im2[j]; }
    __syncthreads();
    if (t > 96) return;
    int u2 = (t == 96) ? 0 : t;
    float wc = g_tabc[HH + t], wsn = g_tabs[HH + t];   // w^t
    u64 wcc = pk2(wc, wc), wss = pk2(wsn, wsn), mwss = pk2(-wsn, -wsn);
    float2* fwp = (float2*)g_fw;
    #pragma unroll
    for (int j = 0; j < 8; j++) {
        u64 er = Er[u2][j], ei = Ei[u2][j];
        u64 orr = Er[96 + u2][j], oi = Ei[96 + u2][j];
        u64 xr = ffma2(orr, wcc, er);  xr = ffma2(oi,  mwss, xr);
        u64 xi = ffma2(oi,  wcc, ei);  xi = ffma2(orr, wss,  xi);
        float2 fr = upk2(xr), fi = upk2(xi);
        fwp[((size_t)(b*CC + c)*HH + h0 + 2*j  )*NW2 + t] = make_float2(fr.x, fi.x);
        fwp[((size_t)(b*CC + c)*HH + h0 + 2*j+1)*NW2 + t] = make_float2(fr.y, fi.y);
    }
}

// ---------------- H-dim FFT: radix-4 (two-level DIT), SoA stage, packed kk-pairs + BN ----------------
__global__ void k_ffth(const float* __restrict__ bng, const float* __restrict__ bnb) {
    int blk = blockIdx.x;
    int kg = blk % 13;
    int c  = (blk / 13) % CC;
    int b  = blk / (13 * CC);
    int k0 = kg * 8;
    int t = threadIdx.x;  // 0..191
    int g = t / 48;       // 0:EE(h%4==0) 1:EO(h%4==2) 2:OE(h%4==1) 3:OO(h%4==3)
    int u48 = t % 48;
    int res = (g == 0) ? 0 : (g == 1) ? 2 : (g == 2) ? 1 : 3;
    u64 re2[4], im2[4];
    #pragma unroll
    for (int q = 0; q < 4; q++) { re2[q] = 0ull; im2[q] = 0ull; }
    __shared__ __align__(8) float sre[32*8];
    __shared__ __align__(8) float sim[32*8];
    for (int hc = 0; hc < 6; hc++) {
        for (int i = threadIdx.x; i < 32*8; i += 192) {
            int hh2 = hc*32 + i/8, kk = i % 8;
            float2 v = make_float2(0.f, 0.f);
            if (k0 + kk < NW2) {
                size_t o = (((size_t)(b*CC + c)*HH + hh2)*NW2 + k0 + kk)*2;
                v.x = g_fw[o]; v.y = g_fw[o+1];
            }
            sre[i] = v.x; sim[i] = v.y;
        }
        __syncthreads();
        for (int hi = res; hi < 32; hi += 4) {
            int h = hc*32 + hi;
            int trow = h - res;          // = 4*i
            float tc = g_tabc[trow*HH + u48], ts = g_tabs[trow*HH + u48];
            u64 tcc = pk2(tc, tc), tss = pk2(ts, ts), mtss = pk2(-ts, -ts);
            const u64* pr = (const u64*)&sre[hi*8];
            const u64* pi = (const u64*)&sim[hi*8];
            #pragma unroll
            for (int q = 0; q < 4; q++) {
                u64 fx = pr[q], fy = pi[q];
                re2[q] = ffma2(fx, tcc,  re2[q]);
                re2[q] = ffma2(fy, mtss, re2[q]);
                im2[q] = ffma2(fx, tss,  im2[q]);
                im2[q] = ffma2(fy, tcc,  im2[q]);
            }
        }
        __syncthreads();
    }
    __shared__ float2 S[192][8];  // [g*48+u48][kk]
    #pragma unroll
    for (int q = 0; q < 4; q++) {
        float2 fr = upk2(re2[q]), fi = upk2(im2[q]);
        S[t][2*q]   = make_float2(fr.x, fi.x);
        S[t][2*q+1] = make_float2(fr.y, fi.y);
    }
    __syncthreads();
    int m = t;
    int isO = (m >= 96);
    int u = isO ? m - 96 : m;
    int us = (u < 48) ? u : u - 48;
    float w96c = g_tabc[2*HH + u], w96s = g_tabs[2*HH + u];
    float w1c  = g_tabc[HH + u],   w1s  = g_tabs[HH + u];
    float sgn = isO ? -1.f : 1.f;
    const float sc = 1.0f / 192.0f;
    int chR = 2*c, chI = 2*c + 1;
    float gr = BNINV * bng[chR], br = bnb[chR];
    float gi = BNINV * bng[chI], bi = bnb[chI];
    for (int kk = 0; kk < 8; kk++) {
        int k = k0 + kk;
        if (k >= NW2) break;
        float2 EE = S[us][kk], EO = S[48+us][kk], OE = S[96+us][kk], OO = S[144+us][kk];
        float Ex = EE.x + (EO.x*w96c - EO.y*w96s);
        float Ey = EE.y + (EO.x*w96s + EO.y*w96c);
        float Ox = OE.x + (OO.x*w96c - OO.y*w96s);
        float Oy = OE.y + (OO.x*w96s + OO.y*w96c);
        float Xr = Ex + sgn*(Ox*w1c - Oy*w1s);
        float Xi = Ey + sgn*(Ox*w1s + Oy*w1c);
        g_frb[((size_t)(b*CH2 + chR)*HH + m)*NW2 + k] = Xr*sc*gr + br;
        g_frb[((size_t)(b*CH2 + chI)*HH + m)*NW2 + k] = Xi*sc*gi + bi;
    }
}

// ---------------- fpe: smem strip tiling, depthwise 3x3 + residual ----------------
__global__ void __launch_bounds__(256) k_fpe(const float* __restrict__ fw,
                                             const float* __restrict__ fb) {
    int blk = blockIdx.x;
    int strip = blk % 6;
    int plane = blk / 6;           // b*CH2 + ch
    int ch = plane % CH2;
    int m0 = strip * 32;
    __shared__ float tile[34][NW2+1];
    const float* base = g_frb + (size_t)plane*HW2;
    for (int i = threadIdx.x; i < 34*NW2; i += 256) {
        int r = i / NW2, k = i % NW2;
        int m = m0 - 1 + r;
        tile[r][k] = ((unsigned)m < HH) ? base[m*NW2 + k] : 0.f;
    }
    __syncthreads();
    float wreg[9];
    #pragma unroll
    for (int q = 0; q < 9; q++) wreg[q] = fw[ch*9 + q];
    float bias = fb[ch];
    float* outp = g_frb2 + (size_t)plane*HW2;
    for (int i = threadIdx.x; i < 32*NW2; i += 256) {
        int r = i / NW2, k = i % NW2;
        float acc = bias;
        #pragma unroll
        for (int ky = 0; ky < 3; ky++) {
            #pragma unroll
            for (int kx = -1; kx <= 1; kx++) {
                int kk2 = k + kx;
                if ((unsigned)kk2 < NW2)
                    acc += tile[r+ky][kk2] * wreg[ky*3 + kx + 1];
            }
        }
        outp[(m0 + r)*NW2 + k] = acc + tile[r+1][k];
    }
}

// ---------------- fdc: 16 outs x 2 px, LDS128 weights + GELU ----------------
__global__ void __launch_bounds__(256) k_fdc(const float* __restrict__ fw,
                                             const float* __restrict__ fb) {
    int blk = blockIdx.x;
    int chunk = blk % 37;
    int og = (blk / 37) % 8;
    int b  = blk / (37 * 8);
    __shared__ __align__(16) float ws[CH2][16];
    for (int i = threadIdx.x; i < CH2*16; i += 256) {
        int o = i % 16, ci = i / 16;
        ws[ci][o] = fw[(size_t)(og*16 + o)*CH2 + ci];
    }
    __syncthreads();
    int p = chunk*512 + threadIdx.x*2;
    if (p >= HW2) return;
    const float* xb = g_frb2 + (size_t)b*CH2*HW2 + p;
    u64 a2[2][8];
    #pragma unroll
    for (int j = 0; j < 8; j++) {
        u64 bb = pk2(fb[og*16 + 2*j], fb[og*16 + 2*j+1]);
        a2[0][j] = bb; a2[1][j] = bb;
    }
    for (int ci = 0; ci < CH2; ci++) {
        float2 v = *(const float2*)(xb + (size_t)ci*HW2);
        u64 v0 = pk2(v.x, v.x), v1 = pk2(v.y, v.y);
        const ulonglong2* wp = (const ulonglong2*)&ws[ci][0];
        #pragma unroll
        for (int q = 0; q < 4; q++) {
            ulonglong2 ww = wp[q];
            a2[0][2*q]   = ffma2(v0, ww.x, a2[0][2*q]);
            a2[0][2*q+1] = ffma2(v0, ww.y, a2[0][2*q+1]);
            a2[1][2*q]   = ffma2(v1, ww.x, a2[1][2*q]);
            a2[1][2*q+1] = ffma2(v1, ww.y, a2[1][2*q+1]);
        }
    }
    #pragma unroll
    for (int j = 0; j < 8; j++) {
        float2 f0 = upk2(a2[0][j]), f1 = upk2(a2[1][j]);
        #pragma unroll
        for (int hlf = 0; hlf < 2; hlf++) {
            int oo = og*16 + 2*j + hlf;
            float a = hlf ? f0.y : f0.x;
            float bq = hlf ? f1.y : f1.x;
            float g0 = 0.5f * a  * (1.0f + erff(a  * 0.70710678118654752f));
            float g1 = 0.5f * bq * (1.0f + erff(bq * 0.70710678118654752f));
            *(float2*)(g_fd + ((size_t)b*CH2 + oo)*HW2 + p) = make_float2(g0, g1);
        }
    }
}

// ---------------- inverse H-dim FFT: radix-4 (two-level DIT), conj twiddles ----------------
__global__ void k_invh() {
    int blk = blockIdx.x;
    int kg = blk % 13;
    int c  = (blk / 13) % CC;
    int b  = blk / (13 * CC);
    int k0 = kg * 8;
    int t = threadIdx.x;
    int g = t / 48;
    int u48 = t % 48;
    int res = (g == 0) ? 0 : (g == 1) ? 2 : (g == 2) ? 1 : 3;
    u64 re2[4], im2[4];
    #pragma unroll
    for (int q = 0; q < 4; q++) { re2[q] = 0ull; im2[q] = 0ull; }
    const float* fR = g_fd + (size_t)(b*CH2 + 2*c)*HW2;
    const float* fI = g_fd + (size_t)(b*CH2 + 2*c + 1)*HW2;
    __shared__ __align__(8) float sre[32*8];
    __shared__ __align__(8) float sim[32*8];
    for (int mc = 0; mc < 6; mc++) {
        for (int i = threadIdx.x; i < 32*8; i += 192) {
            int mm = mc*32 + i/8, kk = i % 8;
            float2 v = make_float2(0.f, 0.f);
            if (k0 + kk < NW2) {
                v.x = fR[mm*NW2 + k0 + kk];
                v.y = fI[mm*NW2 + k0 + kk];
            }
            sre[i] = v.x; sim[i] = v.y;
        }
        __syncthreads();
        for (int mi = res; mi < 32; mi += 4) {
            int mm = mc*32 + mi;
            int trow = mm - res;
            float tc = g_tabc[trow*HH + u48], ts = g_tabs[trow*HH + u48];
            u64 tcc = pk2(tc, tc), tss = pk2(ts, ts), mtss = pk2(-ts, -ts);
            const u64* pr = (const u64*)&sre[mi*8];
            const u64* pi = (const u64*)&sim[mi*8];
            #pragma unroll
            for (int q = 0; q < 4; q++) {
                u64 fx = pr[q], fy = pi[q];
                re2[q] = ffma2(fx, tcc,  re2[q]);
                re2[q] = ffma2(fy, tss,  re2[q]);
                im2[q] = ffma2(fy, tcc,  im2[q]);
                im2[q] = ffma2(fx, mtss, im2[q]);
            }
        }
        __syncthreads();
    }
    __shared__ float2 S[192][8];
    #pragma unroll
    for (int q = 0; q < 4; q++) {
        float2 fr = upk2(re2[q]), fi = upk2(im2[q]);
        S[t][2*q]   = make_float2(fr.x, fi.x);
        S[t][2*q+1] = make_float2(fr.y, fi.y);
    }
    __syncthreads();
    int m = t;
    int isO = (m >= 96);
    int u = isO ? m - 96 : m;
    int us = (u < 48) ? u : u - 48;
    float w96c = g_tabc[2*HH + u], w96s = g_tabs[2*HH + u];
    float w1c  = g_tabc[HH + u],   w1s  = g_tabs[HH + u];
    float sgn = isO ? -1.f : 1.f;
    for (int kk = 0; kk < 8; kk++) {
        int k = k0 + kk;
        if (k >= NW2) break;
        float2 EE = S[us][kk], EO = S[48+us][kk], OE = S[96+us][kk], OO = S[144+us][kk];
        // conj(w96): (c, -s)
        float Ex = EE.x + (EO.x*w96c + EO.y*w96s);
        float Ey = EE.y + (EO.y*w96c - EO.x*w96s);
        float Ox = OE.x + (OO.x*w96c + OO.y*w96s);
        float Oy = OE.y + (OO.y*w96c - OO.x*w96s);
        float Xr = Ex + sgn*(Ox*w1c + Oy*w1s);
        float Xi = Ey + sgn*(Oy*w1c - Ox*w1s);
        size_t o = (((size_t)(b*CC + c)*HH + m)*NW2 + k)*2;
        g_gh[o]   = Xr;
        g_gh[o+1] = Xi;
    }
}

// ---------------- irfft over W (packed float2 stage, packed twiddle) + add xc ----------------
__global__ void k_final(float* __restrict__ out) {
    int blk = blockIdx.x;
    int hg = blk % 24;
    int c  = (blk / 24) % CC;
    int b  = blk / (24 * CC);
    int h0 = hg * 8;
    __shared__ float2 ghc[8][NW2];
    const float2* ghp = (const float2*)g_gh;
    for (int i = threadIdx.x; i < 8*NW2; i += 192) {
        int r = i / NW2, k = i % NW2;
        ghc[r][k] = ghp[((size_t)(b*CC + c)*HH + h0 + r)*NW2 + k];
    }
    __syncthreads();
    int w = threadIdx.x;
    u64 acc2[8];
    #pragma unroll
    for (int r = 0; r < 8; r++) acc2[r] = 0ull;
    const u64* t2 = (const u64*)g_tab2;
    for (int k = 1; k < 96; k++) {
        u64 tt = t2[k*HH + w];
        const u64* gp = (const u64*)&ghc[0][0];
        #pragma unroll
        for (int r = 0; r < 8; r++)
            acc2[r] = ffma2(gp[r*NW2 + k], tt, acc2[r]);
    }
    float par = (w & 1) ? -1.0f : 1.0f;
    const float* xcb2 = g_xn + ((size_t)b*CC + c)*HWP + (size_t)h0*WWD + w;
    #pragma unroll
    for (int r = 0; r < 8; r++) {
        float2 f = upk2(acc2[r]);
        float of = (ghc[r][0].x + ghc[r][96].x*par + 2.0f*(f.x + f.y)) * (1.0f/192.0f);
        out[((size_t)b*CC + c)*HWP + (size_t)(h0 + r)*WWD + w] = xcb2[r*WWD] + of;
    }
}

// ---------------- launch ----------------
extern "C" void kernel_launch(void* const* d_in, const int* in_sizes, int n_in,
                              void* d_out, int out_size) {
    const float* x    = (const float*)d_in[0];
    const float* cdw  = (const float*)d_in[1];
    const float* lng  = (const float*)d_in[2];
    const float* lnb  = (const float*)d_in[3];
    const float* qw   = (const float*)d_in[4];
    const float* kw   = (const float*)d_in[5];
    const float* vw   = (const float*)d_in[6];
    const float* spw  = (const float*)d_in[7];
    const float* lw   = (const float*)d_in[8];
    const float* lb   = (const float*)d_in[9];
    const float* bng  = (const float*)d_in[10];
    const float* bnb  = (const float*)d_in[11];
    const float* fpew = (const float*)d_in[12];
    const float* fpeb = (const float*)d_in[13];
    const float* fdcw = (const float*)d_in[16];
    const float* fdcb = (const float*)d_in[17];
    const float* xcw  = (const float*)d_in[18];
    const float* xcb  = (const float*)d_in[19];
    const float* bn2g = (const float*)d_in[20];
    const float* bn2b = (const float*)d_in[21];
    float* out = (float*)d_out;

    k_tab<<<144, 256>>>();
    k_cdsum<<<16, 256>>>(cdw);
    k_nop<<<1, 32>>>();                       // keep ncu slot on k_contrast
    k_contrast<<<BB*4*96, 192>>>(x, cdw);
    k_centinit<<<144, 256>>>(x);
    k_centsq<<<5, 128>>>();
    k_dist<<<288, 256>>>(x);
    k_asum<<<36, 256>>>();
    k_centupd<<<144, 256>>>(x);
    k_centsq<<<5, 128>>>();
    k_dist<<<288, 256>>>(x);
    k_asum<<<36, 256>>>();
    k_lnorm<<<288, 256>>>(x, lng, lnb);
    k_stoken<<<72, 256>>>();
    k_stokmm<<<72, 256>>>(spw);
    k_qkv<<<BB*12*72, 256>>>(qw, kw, vw);
    k_lepe<<<BB*576, 256>>>(lw, lb);
    k_sattn<<<BB*NHD*(NSS/STILE), 256>>>();
    k_xattn<<<BB*NHD*144, 256>>>(x);
    k_xc<<<BB*4*72, 256>>>(xcw, xcb, bn2g, bn2b);
    k_fftw<<<BB*CC*12, 192>>>();
    k_ffth<<<BB*CC*13, 192>>>(bng, bnb);
    k_fpe<<<BB*CH2*6, 256>>>(fpew, fpeb);
    k_fdc<<<BB*8*37, 256>>>(fdcw, fdcb);
    k_invh<<<BB*CC*13, 192>>>();
    k_final<<<BB*CC*24, 192>>>(out);
}

// round 17
// speedup vs baseline: 1.9302x; 1.0000x over previous
#include <cuda_runtime.h>
#include <math.h>

#define BB 2
#define CC 64
#define HH 192
#define WWD 192
#define HWP 36864
#define NHD 4
#define DDIM 16
#define NSS 144
#define NHSS 12
#define SHH 16
#define NW2 97
#define HW2 18624
#define CH2 128
#define THETA 0.7f
#define ATTNSCALE 0.25f
#define BNINV 0.9999950000374997f

typedef unsigned long long u64;
__device__ __forceinline__ u64 pk2(float lo, float hi) {
    u64 r; asm("mov.b64 %0,{%1,%2};" : "=l"(r) : "f"(lo), "f"(hi)); return r;
}
__device__ __forceinline__ float2 upk2(u64 v) {
    float2 f; asm("mov.b64 {%0,%1},%2;" : "=f"(f.x), "=f"(f.y) : "l"(v)); return f;
}
__device__ __forceinline__ u64 ffma2(u64 a, u64 b, u64 c) {
    u64 d; asm("fma.rn.f32x2 %0,%1,%2,%3;" : "=l"(d) : "l"(a), "l"(b), "l"(c)); return d;
}

// ---------------- scratch ----------------
static __device__ float g_tabc[HH*HH];
static __device__ float g_tabs[HH*HH];
static __device__ float2 g_tab2[HH*HH];
static __device__ float g_cdsum[CC*CC];
static __device__ float g_contrast[BB*CC*HWP];
static __device__ float g_cent[BB*NSS*2*CC];   // layout [b][s][2C]
static __device__ float g_csq[BB*2*NSS];       // [b][half][s]
static __device__ float g_asum[BB*NSS];
static __device__ float g_aff[BB*9*HWP];
static __device__ float g_xn[BB*CC*HWP];       // after k_xattn: reused as xc-relu output
static __device__ float g_q[BB*CC*HWP];
static __device__ float g_k[BB*CC*HWP];
static __device__ float g_v[BB*CC*HWP];
static __device__ float g_lepe[BB*CC*HWP];
static __device__ float g_stoken[BB*NSS*CC];
static __device__ float g_stok[BB*CC*NSS];
static __device__ float g_sout[BB*CC*NSS];
static __device__ float g_x2[BB*CC*HWP];
static __device__ float g_fw[BB*CC*HH*NW2*2];
static __device__ float g_frb[BB*CH2*HW2];
static __device__ float g_frb2[BB*CH2*HW2];
static __device__ float g_fd[BB*CH2*HW2];
static __device__ float g_gh[BB*CC*HH*NW2*2];
static __device__ float g_dummy;

// ---------------- nop: keeps ncu capture slot on k_contrast ----------------
__global__ void k_nop() { if (threadIdx.x == 1024) g_dummy = 0.f; }

// ---------------- twiddle table ----------------
__global__ void k_tab() {
    int t = blockIdx.x * blockDim.x + threadIdx.x;
    if (t >= HH*HH) return;
    int i = t / HH, j = t % HH;
    int r = (i * j) % HH;
    float s, c;
    sincospif(-(float)r / 96.0f, &s, &c);
    g_tabc[t] = c;
    g_tabs[t] = s;
    g_tab2[t] = make_float2(c, s);
}

__global__ void k_cdsum(const float* __restrict__ cdw) {
    int t = blockIdx.x * blockDim.x + threadIdx.x;
    if (t >= CC*CC) return;
    float s = 0.f;
    #pragma unroll
    for (int k = 0; k < 9; k++) s += cdw[t*9 + k];
    g_cdsum[t] = s;
}

// ---------------- contrast: row-pair blocks, folded center tap, LDS128 weights ----------------
__global__ void __launch_bounds__(192, 6) k_contrast(const float* __restrict__ x,
                                                     const float* __restrict__ cdw) {
    int blk = blockIdx.x;
    int hp = blk % 96;
    int og = (blk / 96) % 4;
    int b  = blk / (96 * 4);
    __shared__ __align__(16) float ws[CC][9][16];
    for (int i = threadIdx.x; i < CC*9*16; i += 192) {
        int o = i % 16;
        int tap = (i / 16) % 9;
        int ci = i / 144;
        int oo = og*16 + o;
        float wv = cdw[((size_t)oo*CC + ci)*9 + tap];
        if (tap == 4) wv -= THETA * g_cdsum[oo*CC + ci];
        ws[ci][tap][o] = wv;
    }
    __syncthreads();
    int w = threadIdx.x;
    int h0 = hp * 2;
    u64 a2[2][8];
    #pragma unroll
    for (int px = 0; px < 2; px++)
        #pragma unroll
        for (int j = 0; j < 8; j++) a2[px][j] = 0ull;
    const float* xb = x + (size_t)b * CC * HWP;
    bool wl = (w > 0), wr = (w < WWD-1);
    for (int ci = 0; ci < CC; ci++) {
        const float* xc = xb + (size_t)ci * HWP;
        float rv[4][3];
        #pragma unroll
        for (int rr = 0; rr < 4; rr++) {
            int row = h0 - 1 + rr;
            bool rok = ((unsigned)row < HH);
            const float* rp = xc + row*WWD + w;
            rv[rr][0] = (rok && wl) ? rp[-1] : 0.f;
            rv[rr][1] = rok ? rp[0] : 0.f;
            rv[rr][2] = (rok && wr) ? rp[1] : 0.f;
        }
        #pragma unroll
        for (int tap = 0; tap < 9; tap++) {
            int ky = tap / 3, kx = tap % 3;
            u64 v0 = pk2(rv[ky][kx],   rv[ky][kx]);
            u64 v1 = pk2(rv[ky+1][kx], rv[ky+1][kx]);
            const ulonglong2* wp = (const ulonglong2*)&ws[ci][tap][0];
            #pragma unroll
            for (int q = 0; q < 4; q++) {
                ulonglong2 ww = wp[q];
                a2[0][2*q]   = ffma2(v0, ww.x, a2[0][2*q]);
                a2[0][2*q+1] = ffma2(v0, ww.y, a2[0][2*q+1]);
                a2[1][2*q]   = ffma2(v1, ww.x, a2[1][2*q]);
                a2[1][2*q+1] = ffma2(v1, ww.y, a2[1][2*q+1]);
            }
        }
    }
    #pragma unroll
    for (int px = 0; px < 2; px++) {
        int p = (h0 + px)*WWD + w;
        #pragma unroll
        for (int j = 0; j < 8; j++) {
            float2 f = upk2(a2[px][j]);
            g_contrast[((size_t)b*CC + og*16 + 2*j  )*HWP + p] = f.x;
            g_contrast[((size_t)b*CC + og*16 + 2*j+1)*HWP + p] = f.y;
        }
    }
}

// ---------------- cent init: ch-fastest, float4 gather, [b][s][2C] layout ----------------
__global__ void k_centinit(const float* __restrict__ x) {
    int t = blockIdx.x * 256 + threadIdx.x;
    if (t >= BB*2*CC*NSS) return;
    int ch = t % (2*CC);
    int s  = (t / (2*CC)) % NSS;
    int b  = t / (NSS * 2 * CC);
    const float* src = (ch < CC) ? (x + ((size_t)b*CC + ch)*HWP)
                                 : (g_contrast + ((size_t)b*CC + (ch-CC))*HWP);
    int r0 = s / NHSS, c0 = s % NHSS;
    const float4* sp = (const float4*)(src + (r0*SHH)*WWD + c0*SHH);
    float acc = 0.f;
    for (int i = 0; i < SHH; i++) {
        #pragma unroll
        for (int jj = 0; jj < 4; jj++) {
            float4 v = sp[i*48 + jj];
            acc += v.x; acc += v.y; acc += v.z; acc += v.w;
        }
    }
    g_cent[((size_t)b*NSS + s)*2*CC + ch] = acc * (1.0f/256.0f);
}

// ---------------- cent squared-norm per (b, half, s) ----------------
__global__ void k_centsq() {
    int t = blockIdx.x * 128 + threadIdx.x;
    if (t >= BB*2*NSS) return;
    int s = t % NSS;
    int half = (t / NSS) % 2;
    int b = t / (2*NSS);
    const float4* cb = (const float4*)(g_cent + ((size_t)b*NSS + s)*2*CC + half*CC);
    float acc = 0.f;
    #pragma unroll
    for (int i = 0; i < CC/4; i++) {
        float4 v = cb[i];
        acc += v.x*v.x; acc += v.y*v.y; acc += v.z*v.z; acc += v.w*v.w;
    }
    g_csq[((size_t)b*2 + half)*NSS + s] = acc;
}

// ---------------- distances via p2 - 2g + s2 (reference trick), packed pairs ----------------
__global__ void k_dist(const float* __restrict__ x) {
    int t = blockIdx.x * 256 + threadIdx.x;
    if (t >= BB*HWP) return;
    int p = t % HWP, b = t / HWP;
    int h = p / WWD, w = p % WWD;
    int r = h / SHH, c = w / SHH;
    int cs[9];
    int val[9];
    #pragma unroll
    for (int j = 0; j < 9; j++) {
        int dy = j/3 - 1, dx = j%3 - 1;
        int rr = r + dy, cc2 = c + dx;
        val[j] = (rr >= 0 && rr < NHSS && cc2 >= 0 && cc2 < NHSS);
        cs[j]  = val[j] ? rr*NHSS + cc2 : 0;
    }
    const float* ct = g_cent + (size_t)b*NSS*2*CC;
    const float* rowp[9];
    #pragma unroll
    for (int j = 0; j < 9; j++) rowp[j] = ct + (size_t)cs[j]*2*CC;

    u64 g2[9];
    #pragma unroll
    for (int j = 0; j < 9; j++) g2[j] = 0ull;
    float p2a = 0.f;
    const float* xb = x + (size_t)b*CC*HWP + p;
    for (int ch = 0; ch < CC; ch += 2) {
        float pix0 = xb[(size_t)ch*HWP];
        float pix1 = xb[(size_t)(ch+1)*HWP];
        p2a = fmaf(pix0, pix0, p2a);
        p2a = fmaf(pix1, pix1, p2a);
        u64 px = pk2(pix0, pix1);
        #pragma unroll
        for (int j = 0; j < 9; j++)
            g2[j] = ffma2(px, *(const u64*)(rowp[j] + ch), g2[j]);
    }
    const float* sqa = g_csq + (size_t)b*2*NSS;
    float d[9];
    #pragma unroll
    for (int j = 0; j < 9; j++) {
        float2 f = upk2(g2[j]);
        d[j] = p2a - 2.0f*(f.x + f.y) + sqa[cs[j]];
        g2[j] = 0ull;
    }
    float p2b = 0.f;
    const float* cbq = g_contrast + (size_t)b*CC*HWP + p;
    for (int ch = 0; ch < CC; ch += 2) {
        float pix0 = cbq[(size_t)ch*HWP];
        float pix1 = cbq[(size_t)(ch+1)*HWP];
        p2b = fmaf(pix0, pix0, p2b);
        p2b = fmaf(pix1, pix1, p2b);
        u64 px = pk2(pix0, pix1);
        #pragma unroll
        for (int j = 0; j < 9; j++)
            g2[j] = ffma2(px, *(const u64*)(rowp[j] + CC + ch), g2[j]);
    }
    const float* sqb = sqa + NSS;
    #pragma unroll
    for (int j = 0; j < 9; j++) {
        float2 f = upk2(g2[j]);
        d[j] += 10.0f * (p2b - 2.0f*(f.x + f.y) + sqb[cs[j]]);
    }
    float m = 3.0e38f;
    #pragma unroll
    for (int j = 0; j < 9; j++) if (val[j] && d[j] < m) m = d[j];
    float e[9], sum = 0.f;
    #pragma unroll
    for (int j = 0; j < 9; j++) {
        e[j] = val[j] ? __expf(m - d[j]) : 0.f;
        sum += e[j];
    }
    float inv = 1.0f / sum;
    #pragma unroll
    for (int j = 0; j < 9; j++)
        g_aff[((size_t)b*9 + j)*HWP + p] = e[j] * inv;
}

// ---------------- asum: one warp per (b,s), float4 + shfl ----------------
__global__ void k_asum() {
    int wid = (blockIdx.x * 256 + threadIdx.x) >> 5;
    int lane = threadIdx.x & 31;
    if (wid >= BB*NSS) return;
    int s = wid % NSS, b = wid / NSS;
    int r0 = s / NHSS, c0 = s % NHSS;
    float acc = 0.f;
    for (int dy = -1; dy <= 1; dy++) {
        int r = r0 - dy;
        if ((unsigned)r >= NHSS) continue;
        for (int dx = -1; dx <= 1; dx++) {
            int c = c0 - dx;
            if ((unsigned)c >= NHSS) continue;
            int j = (dy+1)*3 + (dx+1);
            const float4* ab = (const float4*)(g_aff + ((size_t)b*9 + j)*HWP
                                               + (r*SHH)*WWD + c*SHH);
            for (int idx = lane; idx < 64; idx += 32) {
                int i = idx >> 2, jj = idx & 3;
                float4 v = ab[i*48 + jj];
                acc += v.x; acc += v.y; acc += v.z; acc += v.w;
            }
        }
    }
    #pragma unroll
    for (int o = 16; o > 0; o >>= 1) acc += __shfl_down_sync(0xffffffffu, acc, o);
    if (lane == 0) g_asum[wid] = acc;
}

// ---------------- cent update: ch-fastest (aff broadcast), float4, [b][s][2C] write ----------------
__global__ void k_centupd(const float* __restrict__ x) {
    int t = blockIdx.x * 256 + threadIdx.x;
    if (t >= BB*2*CC*NSS) return;
    int ch = t % (2*CC);
    int s  = (t / (2*CC)) % NSS;
    int b  = t / (NSS * 2 * CC);
    const float* src = (ch < CC) ? (x + ((size_t)b*CC + ch)*HWP)
                                 : (g_contrast + ((size_t)b*CC + (ch-CC))*HWP);
    int r0 = s / NHSS, c0 = s % NHSS;
    float acc = 0.f;
    for (int dy = -1; dy <= 1; dy++) {
        int r = r0 - dy;
        if ((unsigned)r >= NHSS) continue;
        for (int dx = -1; dx <= 1; dx++) {
            int c = c0 - dx;
            if ((unsigned)c >= NHSS) continue;
            int j = (dy+1)*3 + (dx+1);
            int pb = (r*SHH)*WWD + c*SHH;
            const float4* ar = (const float4*)(g_aff + ((size_t)b*9 + j)*HWP + pb);
            const float4* sr = (const float4*)(src + pb);
            for (int i = 0; i < SHH; i++) {
                #pragma unroll
                for (int jj = 0; jj < 4; jj++) {
                    float4 a = ar[i*48 + jj];
                    float4 v = sr[i*48 + jj];
                    acc += a.x*v.x; acc += a.y*v.y; acc += a.z*v.z; acc += a.w*v.w;
                }
            }
        }
    }
    g_cent[((size_t)b*NSS + s)*2*CC + ch] = acc / (g_asum[(size_t)b*NSS + s] + 1e-16f);
}

// ---------------- LayerNorm: 2 px/thread, float2 ----------------
__global__ void k_lnorm(const float* __restrict__ x, const float* __restrict__ g,
                        const float* __restrict__ bta) {
    int t = blockIdx.x * 256 + threadIdx.x;
    if (t >= BB*HWP/2) return;
    int p = (t % (HWP/2)) * 2, b = t / (HWP/2);
    const float* xb = x + (size_t)b*CC*HWP + p;
    float s0 = 0.f, s1 = 0.f, q0 = 0.f, q1 = 0.f;
    for (int ch = 0; ch < CC; ch++) {
        float2 v = *(const float2*)(xb + (size_t)ch*HWP);
        s0 += v.x; q0 = fmaf(v.x, v.x, q0);
        s1 += v.y; q1 = fmaf(v.y, v.y, q1);
    }
    float mu0 = s0 * (1.0f/CC), mu1 = s1 * (1.0f/CC);
    float r0 = rsqrtf(q0*(1.0f/CC) - mu0*mu0 + 1e-6f);
    float r1 = rsqrtf(q1*(1.0f/CC) - mu1*mu1 + 1e-6f);
    float* ob = g_xn + (size_t)b*CC*HWP + p;
    for (int ch = 0; ch < CC; ch++) {
        float2 v = *(const float2*)(xb + (size_t)ch*HWP);
        float gg = g[ch], bb = bta[ch];
        *(float2*)(ob + (size_t)ch*HWP) =
            make_float2((v.x - mu0)*r0*gg + bb, (v.y - mu1)*r1*gg + bb);
    }
}

// ---------------- stoken gather: ch-fastest (aff broadcast), float4 ----------------
__global__ void k_stoken() {
    int t = blockIdx.x * 256 + threadIdx.x;
    if (t >= BB*NSS*CC) return;
    int ch = t % CC;
    int s  = (t / CC) % NSS;
    int b  = t / (CC * NSS);
    const float* src = g_xn + ((size_t)b*CC + ch)*HWP;
    int r0 = s / NHSS, c0 = s % NHSS;
    float acc = 0.f;
    for (int dy = -1; dy <= 1; dy++) {
        int r = r0 - dy;
        if ((unsigned)r >= NHSS) continue;
        for (int dx = -1; dx <= 1; dx++) {
            int c = c0 - dx;
            if ((unsigned)c >= NHSS) continue;
            int j = (dy+1)*3 + (dx+1);
            int pb = (r*SHH)*WWD + c*SHH;
            const float4* ar = (const float4*)(g_aff + ((size_t)b*9 + j)*HWP + pb);
            const float4* sr = (const float4*)(src + pb);
            for (int i = 0; i < SHH; i++) {
                #pragma unroll
                for (int jj = 0; jj < 4; jj++) {
                    float4 a = ar[i*48 + jj];
                    float4 v = sr[i*48 + jj];
                    acc += a.x*v.x; acc += a.y*v.y; acc += a.z*v.z; acc += a.w*v.w;
                }
            }
        }
    }
    g_stoken[((size_t)b*NSS + s)*CC + ch] = acc / (g_asum[(size_t)b*NSS + s] + 1e-16f);
}

// ---------------- stok = stoken @ sp_w^T ----------------
__global__ void k_stokmm(const float* __restrict__ spw) {
    int t = blockIdx.x * 256 + threadIdx.x;
    if (t >= BB*CC*NSS) return;
    int s = t % NSS;
    int o = (t / NSS) % CC;
    int b = t / (NSS * CC);
    const float* st = g_stoken + ((size_t)b*NSS + s)*CC;
    const float* w  = spw + o*CC;
    float acc = 0.f;
    #pragma unroll 8
    for (int c = 0; c < CC; c++) acc += w[c] * st[c];
    g_stok[((size_t)b*CC + o)*NSS + s] = acc;
}

// ---------------- q/k/v: 16 outs x 2 px per thread, LDS128 weights ----------------
__global__ void __launch_bounds__(256) k_qkv(const float* __restrict__ qw,
                                             const float* __restrict__ kw,
                                             const float* __restrict__ vw) {
    int blk = blockIdx.x;
    int chunk = blk % 72;
    int og = (blk / 72) % 12;
    int b  = blk / (72 * 12);
    __shared__ __align__(16) float ws[CC][16];
    for (int i = threadIdx.x; i < CC*16; i += 256) {
        int o = i % 16, ci = i / 16;
        int oo = og*16 + o;
        const float* wsrc = (oo < 64) ? (qw + oo*CC)
                          : (oo < 128 ? kw + (oo-64)*CC : vw + (oo-128)*CC);
        ws[ci][o] = wsrc[ci];
    }
    __syncthreads();
    int p = chunk*512 + threadIdx.x*2;
    const float* xb = g_xn + (size_t)b*CC*HWP + p;
    u64 a2[2][8];
    #pragma unroll
    for (int px = 0; px < 2; px++)
        #pragma unroll
        for (int j = 0; j < 8; j++) a2[px][j] = 0ull;
    for (int ci = 0; ci < CC; ci++) {
        float2 v = *(const float2*)(xb + (size_t)ci*HWP);
        u64 v0 = pk2(v.x, v.x), v1 = pk2(v.y, v.y);
        const ulonglong2* wp = (const ulonglong2*)&ws[ci][0];
        #pragma unroll
        for (int q = 0; q < 4; q++) {
            ulonglong2 ww = wp[q];
            a2[0][2*q]   = ffma2(v0, ww.x, a2[0][2*q]);
            a2[0][2*q+1] = ffma2(v0, ww.y, a2[0][2*q+1]);
            a2[1][2*q]   = ffma2(v1, ww.x, a2[1][2*q]);
            a2[1][2*q+1] = ffma2(v1, ww.y, a2[1][2*q+1]);
        }
    }
    #pragma unroll
    for (int j = 0; j < 8; j++) {
        float2 f0 = upk2(a2[0][j]), f1 = upk2(a2[1][j]);
        #pragma unroll
        for (int hlf = 0; hlf < 2; hlf++) {
            int oo = og*16 + 2*j + hlf;
            float lo = hlf ? f0.y : f0.x;
            float hi = hlf ? f1.y : f1.x;
            float* dst = (oo < 64) ? (g_q + ((size_t)b*64 + oo)*HWP)
                       : (oo < 128 ? (g_k + ((size_t)b*64 + oo-64)*HWP)
                                   : (g_v + ((size_t)b*64 + oo-128)*HWP));
            *(float2*)(dst + p) = make_float2(lo, hi);
        }
    }
}

// ---------------- lepe: coalesced Tflat write ----------------
__global__ void __launch_bounds__(256) k_lepe(const float* __restrict__ lw,
                                              const float* __restrict__ lb) {
    __shared__ float ws[CC*9];
    __shared__ float bs[CC];
    for (int i = threadIdx.x; i < CC*9; i += 256) ws[i] = lw[i];
    if (threadIdx.x < CC) bs[threadIdx.x] = lb[threadIdx.x];
    __syncthreads();
    int blk = blockIdx.x;
    int pblk = blk % 576;
    int b = blk / 576;
    int cg = threadIdx.x & 3;
    int pl = threadIdx.x >> 2;
    int p = pblk * 64 + pl;
    int h = p / WWD, w = p % WWD;
    int off[9];
    bool vld[9];
    #pragma unroll
    for (int tap = 0; tap < 9; tap++) {
        int ky = tap/3 - 1, kx = tap%3 - 1;
        int hh = h + ky, ww = w + kx;
        vld[tap] = ((unsigned)hh < HH) && ((unsigned)ww < WWD);
        off[tap] = hh*WWD + ww;
    }
    const float* vb = g_v + (size_t)b*CC*HWP;
    float o[16];
    #pragma unroll
    for (int j = 0; j < 16; j++) {
        int c = cg*16 + j;
        const float* vc = vb + (size_t)c*HWP;
        float acc = bs[c];
        #pragma unroll
        for (int tap = 0; tap < 9; tap++)
            if (vld[tap]) acc += vc[off[tap]] * ws[c*9 + tap];
        o[j] = acc;
    }
    float4* dst = (float4*)(g_lepe + (size_t)b*CC*HWP + (size_t)p*CC + cg*16);
    #pragma unroll
    for (int q = 0; q < 4; q++)
        dst[q] = make_float4(o[q*4], o[q*4+1], o[q*4+2], o[q*4+3]);
}

// ---------------- s_attn: packed, STILE=8, LDS128 stok ----------------
#define STILE 8
__global__ void __launch_bounds__(256) k_sattn() {
    int blk = blockIdx.x;
    int sg = blk % (NSS/STILE);
    int hh = (blk / (NSS/STILE)) % NHD;
    int b  = blk / ((NSS/STILE) * NHD);
    int s0 = sg * STILE;
    int tid = threadIdx.x;
    __shared__ __align__(16) u64 stks2[STILE][8];
    if (tid < STILE*8) {
        int si = tid / 8, j = tid % 8;
        size_t base = (size_t)(b*NHD + hh)*DDIM;
        stks2[si][j] = pk2(g_stok[(base + 2*j  )*NSS + s0 + si],
                           g_stok[(base + 2*j+1)*NSS + s0 + si]);
    }
    __syncthreads();
    float l[STILE];
    u64 acc2[STILE][8];
    #pragma unroll
    for (int si = 0; si < STILE; si++) {
        l[si] = 0.f;
        #pragma unroll
        for (int j = 0; j < 8; j++) acc2[si][j] = 0ull;
    }
    const float* kb = g_k + (size_t)(b*NHD + hh)*DDIM*HWP;
    const float* vb = g_v + (size_t)(b*NHD + hh)*DDIM*HWP;
    for (int p = tid; p < HWP; p += 256) {
        u64 kd2[8], vd2[8];
        #pragma unroll
        for (int j = 0; j < 8; j++)
            kd2[j] = pk2(kb[(size_t)(2*j)*HWP + p], kb[(size_t)(2*j+1)*HWP + p]);
        #pragma unroll
        for (int j = 0; j < 8; j++)
            vd2[j] = pk2(vb[(size_t)(2*j)*HWP + p], vb[(size_t)(2*j+1)*HWP + p]);
        #pragma unroll
        for (int si = 0; si < STILE; si++) {
            const ulonglong2* sp = (const ulonglong2*)&stks2[si][0];
            u64 dp = 0ull;
            #pragma unroll
            for (int q = 0; q < 4; q++) {
                ulonglong2 ss = sp[q];
                dp = ffma2(kd2[2*q],   ss.x, dp);
                dp = ffma2(kd2[2*q+1], ss.y, dp);
            }
            float2 f = upk2(dp);
            float e = __expf((f.x + f.y) * ATTNSCALE);
            l[si] += e;
            u64 ee = pk2(e, e);
            #pragma unroll
            for (int j = 0; j < 8; j++) acc2[si][j] = ffma2(ee, vd2[j], acc2[si][j]);
        }
    }
    __shared__ float rl[256], ra[DDIM*256];
    for (int si = 0; si < STILE; si++) {
        rl[tid] = l[si];
        #pragma unroll
        for (int j = 0; j < 8; j++) {
            float2 f = upk2(acc2[si][j]);
            ra[(2*j  )*256 + tid] = f.x;
            ra[(2*j+1)*256 + tid] = f.y;
        }
        __syncthreads();
        for (int str = 128; str > 0; str >>= 1) {
            if (tid < str) {
                rl[tid] += rl[tid + str];
                #pragma unroll
                for (int d = 0; d < DDIM; d++)
                    ra[d*256 + tid] += ra[d*256 + tid + str];
            }
            __syncthreads();
        }
        if (tid < DDIM)
            g_sout[((size_t)(b*NHD + hh)*DDIM + tid)*NSS + s0 + si] = ra[tid*256] / rl[0];
        __syncthreads();
    }
}

// ---------------- x_attn: packed single-pass, 2 px/thread, LDS128 tables ----------------
__global__ void __launch_bounds__(256) k_xattn(const float* __restrict__ x) {
    int blk = blockIdx.x;
    int chunk = blk % 72;
    int hh = (blk / 72) % NHD;
    int b  = blk / (72 * NHD);
    int tid = threadIdx.x;
    __shared__ __align__(16) u64 stp[NSS*10];
    __shared__ __align__(16) u64 sop[NSS*10];
    size_t base = (size_t)(b*NHD + hh)*DDIM*NSS;
    for (int i = tid; i < NSS*8; i += 256) {
        int j = i / NSS, s = i % NSS;
        stp[s*10 + j] = pk2(g_stok[base + (2*j)*NSS + s], g_stok[base + (2*j+1)*NSS + s]);
        sop[s*10 + j] = pk2(g_sout[base + (2*j)*NSS + s], g_sout[base + (2*j+1)*NSS + s]);
    }
    __syncthreads();
    int p = chunk*512 + tid*2;
    u64 qa2[8], qb2[8];
    #pragma unroll
    for (int j = 0; j < 8; j++) {
        float2 va = *(const float2*)(g_q + ((size_t)(b*NHD + hh)*DDIM + 2*j  )*HWP + p);
        float2 vbq = *(const float2*)(g_q + ((size_t)(b*NHD + hh)*DDIM + 2*j+1)*HWP + p);
        qa2[j] = pk2(va.x, vbq.x);   // pixel p:   dims (2j, 2j+1)
        qb2[j] = pk2(va.y, vbq.y);   // pixel p+1: dims (2j, 2j+1)
    }
    float la = 0.f, lb2 = 0.f;
    u64 aa2[8], ab2[8];
    #pragma unroll
    for (int j = 0; j < 8; j++) { aa2[j] = 0ull; ab2[j] = 0ull; }
    for (int s = 0; s < NSS; s++) {
        const ulonglong2* sp = (const ulonglong2*)&stp[s*10];
        u64 dpa = 0ull, dpb = 0ull;
        #pragma unroll
        for (int q = 0; q < 4; q++) {
            ulonglong2 ss = sp[q];
            dpa = ffma2(qa2[2*q],   ss.x, dpa);
            dpa = ffma2(qa2[2*q+1], ss.y, dpa);
            dpb = ffma2(qb2[2*q],   ss.x, dpb);
            dpb = ffma2(qb2[2*q+1], ss.y, dpb);
        }
        float2 fa = upk2(dpa), fb = upk2(dpb);
        float ea = __expf((fa.x + fa.y) * ATTNSCALE);
        float eb = __expf((fb.x + fb.y) * ATTNSCALE);
        la += ea; lb2 += eb;
        u64 eea = pk2(ea, ea), eeb = pk2(eb, eb);
        const ulonglong2* op = (const ulonglong2*)&sop[s*10];
        #pragma unroll
        for (int q = 0; q < 4; q++) {
            ulonglong2 oo = op[q];
            aa2[2*q]   = ffma2(eea, oo.x, aa2[2*q]);
            aa2[2*q+1] = ffma2(eea, oo.y, aa2[2*q+1]);
            ab2[2*q]   = ffma2(eeb, oo.x, ab2[2*q]);
            ab2[2*q+1] = ffma2(eeb, oo.y, ab2[2*q+1]);
        }
    }
    float inva = 1.0f / la, invb = 1.0f / lb2;
    #pragma unroll
    for (int j = 0; j < 8; j++) {
        float2 fa = upk2(aa2[j]), fb = upk2(ab2[j]);
        #pragma unroll
        for (int hlf = 0; hlf < 2; hlf++) {
            int cch = hh*DDIM + 2*j + hlf;
            size_t o = ((size_t)b*CC + cch)*HWP + p;
            float2 xv = *(const float2*)(x + o);
            float2 lv = *(const float2*)(g_lepe + o);
            float oa = (hlf ? fa.y : fa.x)*inva;
            float ob = (hlf ? fb.y : fb.x)*invb;
            *(float2*)(g_x2 + o) = make_float2(xv.x + oa + lv.x, xv.y + ob + lv.y);
        }
    }
}

// ---------------- xc: 16 outs x 2 px, LDS128 weights, relu'd into g_xn ----------------
__global__ void __launch_bounds__(256) k_xc(const float* __restrict__ xcw,
                                            const float* __restrict__ xcb,
                                            const float* __restrict__ bn2g,
                                            const float* __restrict__ bn2b) {
    int blk = blockIdx.x;
    int chunk = blk % 72;
    int og = (blk / 72) % 4;
    int b  = blk / (72 * 4);
    __shared__ __align__(16) float ws[CC][16];
    for (int i = threadIdx.x; i < CC*16; i += 256) {
        int o = i % 16, ci = i / 16;
        ws[ci][o] = xcw[(size_t)(og*16 + o)*CC + ci];
    }
    __syncthreads();
    int p = chunk*512 + threadIdx.x*2;
    const float* xb = g_x2 + (size_t)b*CC*HWP + p;
    u64 a2[2][8];
    #pragma unroll
    for (int px = 0; px < 2; px++)
        #pragma unroll
        for (int j = 0; j < 8; j++) a2[px][j] = 0ull;
    for (int ci = 0; ci < CC; ci++) {
        float2 v = *(const float2*)(xb + (size_t)ci*HWP);
        u64 v0 = pk2(v.x, v.x), v1 = pk2(v.y, v.y);
        const ulonglong2* wp = (const ulonglong2*)&ws[ci][0];
        #pragma unroll
        for (int q = 0; q < 4; q++) {
            ulonglong2 ww = wp[q];
            a2[0][2*q]   = ffma2(v0, ww.x, a2[0][2*q]);
            a2[0][2*q+1] = ffma2(v0, ww.y, a2[0][2*q+1]);
            a2[1][2*q]   = ffma2(v1, ww.x, a2[1][2*q]);
            a2[1][2*q+1] = ffma2(v1, ww.y, a2[1][2*q+1]);
        }
    }
    #pragma unroll
    for (int j = 0; j < 8; j++) {
        float2 f0 = upk2(a2[0][j]), f1 = upk2(a2[1][j]);
        #pragma unroll
        for (int hlf = 0; hlf < 2; hlf++) {
            int oo = og*16 + 2*j + hlf;
            float gbn = BNINV * bn2g[oo], bbn = bn2b[oo], bias = xcb[oo];
            float lo = ((hlf ? f0.y : f0.x) + bias) * gbn + bbn;
            float hi = ((hlf ? f1.y : f1.x) + bias) * gbn + bbn;
            *(float2*)(g_xn + ((size_t)b*CC + oo)*HWP + p) =
                make_float2(fmaxf(lo, 0.0f), fmaxf(hi, 0.0f));
        }
    }
}

// ---------------- W-dim rfft: even/odd DIT over w, 192 threads ----------------
__global__ void __launch_bounds__(192) k_fftw() {
    int blk = blockIdx.x;
    int hg = blk % 12;
    int c  = (blk / 12) % CC;
    int b  = blk / (12 * CC);
    int h0 = hg * 16;
    __shared__ float rows[WWD][18];
    for (int i = threadIdx.x; i < 16*WWD; i += 192) {
        int r = i / WWD, w = i % WWD;
        rows[w][r] = g_x2[((size_t)b*CC + c)*HWP + (size_t)(h0 + r)*WWD + w];
    }
    __syncthreads();
    int t = threadIdx.x;
    int isO = (t >= 96);
    int u = isO ? t - 96 : t;
    u64 re2[8], im2[8];
    #pragma unroll
    for (int j = 0; j < 8; j++) { re2[j] = 0ull; im2[j] = 0ull; }
    for (int wi = 0; wi < 96; wi++) {
        int w = 2*wi + isO;
        float tc = g_tabc[(2*wi)*HH + u], ts = g_tabs[(2*wi)*HH + u];
        u64 tcc = pk2(tc, tc), tss = pk2(ts, ts);
        const u64* vp = (const u64*)&rows[w][0];
        #pragma unroll
        for (int j = 0; j < 8; j++) {
            u64 v2 = vp[j];
            re2[j] = ffma2(v2, tcc, re2[j]);
            im2[j] = ffma2(v2, tss, im2[j]);
        }
    }
    __shared__ u64 Er[192][8];
    __shared__ u64 Ei[192][8];
    #pragma unroll
    for (int j = 0; j < 8; j++) { Er[t][j] = re2[j]; Ei[t][j] = im2[j]; }
    __syncthreads();
    if (t > 96) return;
    int u2 = (t == 96) ? 0 : t;
    float wc = g_tabc[HH + t], wsn = g_tabs[HH + t];   // w^t
    u64 wcc = pk2(wc, wc), wss = pk2(wsn, wsn), mwss = pk2(-wsn, -wsn);
    float2* fwp = (float2*)g_fw;
    #pragma unroll
    for (int j = 0; j < 8; j++) {
        u64 er = Er[u2][j], ei = Ei[u2][j];
        u64 orr = Er[96 + u2][j], oi = Ei[96 + u2][j];
        u64 xr = ffma2(orr, wcc, er);  xr = ffma2(oi,  mwss, xr);
        u64 xi = ffma2(oi,  wcc, ei);  xi = ffma2(orr, wss,  xi);
        float2 fr = upk2(xr), fi = upk2(xi);
        fwp[((size_t)(b*CC + c)*HH + h0 + 2*j  )*NW2 + t] = make_float2(fr.x, fi.x);
        fwp[((size_t)(b*CC + c)*HH + h0 + 2*j+1)*NW2 + t] = make_float2(fr.y, fi.y);
    }
}

// ---------------- H-dim FFT: radix-4 (two-level DIT), SoA stage, packed kk-pairs + BN ----------------
__global__ void k_ffth(const float* __restrict__ bng, const float* __restrict__ bnb) {
    int blk = blockIdx.x;
    int kg = blk % 13;
    int c  = (blk / 13) % CC;
    int b  = blk / (13 * CC);
    int k0 = kg * 8;
    int t = threadIdx.x;  // 0..191
    int g = t / 48;       // 0:EE(h%4==0) 1:EO(h%4==2) 2:OE(h%4==1) 3:OO(h%4==3)
    int u48 = t % 48;
    int res = (g == 0) ? 0 : (g == 1) ? 2 : (g == 2) ? 1 : 3;
    u64 re2[4], im2[4];
    #pragma unroll
    for (int q = 0; q < 4; q++) { re2[q] = 0ull; im2[q] = 0ull; }
    __shared__ __align__(8) float sre[32*8];
    __shared__ __align__(8) float sim[32*8];
    for (int hc = 0; hc < 6; hc++) {
        for (int i = threadIdx.x; i < 32*8; i += 192) {
            int hh2 = hc*32 + i/8, kk = i % 8;
            float2 v = make_float2(0.f, 0.f);
            if (k0 + kk < NW2) {
                size_t o = (((size_t)(b*CC + c)*HH + hh2)*NW2 + k0 + kk)*2;
                v.x = g_fw[o]; v.y = g_fw[o+1];
            }
            sre[i] = v.x; sim[i] = v.y;
        }
        __syncthreads();
        for (int hi = res; hi < 32; hi += 4) {
            int h = hc*32 + hi;
            int trow = h - res;          // = 4*i
            float tc = g_tabc[trow*HH + u48], ts = g_tabs[trow*HH + u48];
            u64 tcc = pk2(tc, tc), tss = pk2(ts, ts), mtss = pk2(-ts, -ts);
            const u64* pr = (const u64*)&sre[hi*8];
            const u64* pi = (const u64*)&sim[hi*8];
            #pragma unroll
            for (int q = 0; q < 4; q++) {
                u64 fx = pr[q], fy = pi[q];
                re2[q] = ffma2(fx, tcc,  re2[q]);
                re2[q] = ffma2(fy, mtss, re2[q]);
                im2[q] = ffma2(fx, tss,  im2[q]);
                im2[q] = ffma2(fy, tcc,  im2[q]);
            }
        }
        __syncthreads();
    }
    __shared__ float2 S[192][8];  // [g*48+u48][kk]
    #pragma unroll
    for (int q = 0; q < 4; q++) {
        float2 fr = upk2(re2[q]), fi = upk2(im2[q]);
        S[t][2*q]   = make_float2(fr.x, fi.x);
        S[t][2*q+1] = make_float2(fr.y, fi.y);
    }
    __syncthreads();
    int m = t;
    int isO = (m >= 96);
    int u = isO ? m - 96 : m;
    int us = (u < 48) ? u : u - 48;
    float w96c = g_tabc[2*HH + u], w96s = g_tabs[2*HH + u];
    float w1c  = g_tabc[HH + u],   w1s  = g_tabs[HH + u];
    float sgn = isO ? -1.f : 1.f;
    const float sc = 1.0f / 192.0f;
    int chR = 2*c, chI = 2*c + 1;
    float gr = BNINV * bng[chR], br = bnb[chR];
    float gi = BNINV * bng[chI], bi = bnb[chI];
    for (int kk = 0; kk < 8; kk++) {
        int k = k0 + kk;
        if (k >= NW2) break;
        float2 EE = S[us][kk], EO = S[48+us][kk], OE = S[96+us][kk], OO = S[144+us][kk];
        float Ex = EE.x + (EO.x*w96c - EO.y*w96s);
        float Ey = EE.y + (EO.x*w96s + EO.y*w96c);
        float Ox = OE.x + (OO.x*w96c - OO.y*w96s);
        float Oy = OE.y + (OO.x*w96s + OO.y*w96c);
        float Xr = Ex + sgn*(Ox*w1c - Oy*w1s);
        float Xi = Ey + sgn*(Ox*w1s + Oy*w1c);
        g_frb[((size_t)(b*CH2 + chR)*HH + m)*NW2 + k] = Xr*sc*gr + br;
        g_frb[((size_t)(b*CH2 + chI)*HH + m)*NW2 + k] = Xi*sc*gi + bi;
    }
}

// ---------------- fpe: smem strip tiling, depthwise 3x3 + residual ----------------
__global__ void __launch_bounds__(256) k_fpe(const float* __restrict__ fw,
                                             const float* __restrict__ fb) {
    int blk = blockIdx.x;
    int strip = blk % 6;
    int plane = blk / 6;           // b*CH2 + ch
    int ch = plane % CH2;
    int m0 = strip * 32;
    __shared__ float tile[34][NW2+1];
    const float* base = g_frb + (size_t)plane*HW2;
    for (int i = threadIdx.x; i < 34*NW2; i += 256) {
        int r = i / NW2, k = i % NW2;
        int m = m0 - 1 + r;
        tile[r][k] = ((unsigned)m < HH) ? base[m*NW2 + k] : 0.f;
    }
    __syncthreads();
    float wreg[9];
    #pragma unroll
    for (int q = 0; q < 9; q++) wreg[q] = fw[ch*9 + q];
    float bias = fb[ch];
    float* outp = g_frb2 + (size_t)plane*HW2;
    for (int i = threadIdx.x; i < 32*NW2; i += 256) {
        int r = i / NW2, k = i % NW2;
        float acc = bias;
        #pragma unroll
        for (int ky = 0; ky < 3; ky++) {
            #pragma unroll
            for (int kx = -1; kx <= 1; kx++) {
                int kk2 = k + kx;
                if ((unsigned)kk2 < NW2)
                    acc += tile[r+ky][kk2] * wreg[ky*3 + kx + 1];
            }
        }
        outp[(m0 + r)*NW2 + k] = acc + tile[r+1][k];
    }
}

// ---------------- fdc: 16 outs x 2 px, LDS128 weights + GELU ----------------
__global__ void __launch_bounds__(256) k_fdc(const float* __restrict__ fw,
                                             const float* __restrict__ fb) {
    int blk = blockIdx.x;
    int chunk = blk % 37;
    int og = (blk / 37) % 8;
    int b  = blk / (37 * 8);
    __shared__ __align__(16) float ws[CH2][16];
    for (int i = threadIdx.x; i < CH2*16; i += 256) {
        int o = i % 16, ci = i / 16;
        ws[ci][o] = fw[(size_t)(og*16 + o)*CH2 + ci];
    }
    __syncthreads();
    int p = chunk*512 + threadIdx.x*2;
    if (p >= HW2) return;
    const float* xb = g_frb2 + (size_t)b*CH2*HW2 + p;
    u64 a2[2][8];
    #pragma unroll
    for (int j = 0; j < 8; j++) {
        u64 bb = pk2(fb[og*16 + 2*j], fb[og*16 + 2*j+1]);
        a2[0][j] = bb; a2[1][j] = bb;
    }
    for (int ci = 0; ci < CH2; ci++) {
        float2 v = *(const float2*)(xb + (size_t)ci*HW2);
        u64 v0 = pk2(v.x, v.x), v1 = pk2(v.y, v.y);
        const ulonglong2* wp = (const ulonglong2*)&ws[ci][0];
        #pragma unroll
        for (int q = 0; q < 4; q++) {
            ulonglong2 ww = wp[q];
            a2[0][2*q]   = ffma2(v0, ww.x, a2[0][2*q]);
            a2[0][2*q+1] = ffma2(v0, ww.y, a2[0][2*q+1]);
            a2[1][2*q]   = ffma2(v1, ww.x, a2[1][2*q]);
            a2[1][2*q+1] = ffma2(v1, ww.y, a2[1][2*q+1]);
        }
    }
    #pragma unroll
    for (int j = 0; j < 8; j++) {
        float2 f0 = upk2(a2[0][j]), f1 = upk2(a2[1][j]);
        #pragma unroll
        for (int hlf = 0; hlf < 2; hlf++) {
            int oo = og*16 + 2*j + hlf;
            float a = hlf ? f0.y : f0.x;
            float bq = hlf ? f1.y : f1.x;
            float g0 = 0.5f * a  * (1.0f + erff(a  * 0.70710678118654752f));
            float g1 = 0.5f * bq * (1.0f + erff(bq * 0.70710678118654752f));
            *(float2*)(g_fd + ((size_t)b*CH2 + oo)*HW2 + p) = make_float2(g0, g1);
        }
    }
}

// ---------------- inverse H-dim FFT: radix-4 (two-level DIT), conj twiddles ----------------
__global__ void k_invh() {
    int blk = blockIdx.x;
    int kg = blk % 13;
    int c  = (blk / 13) % CC;
    int b  = blk / (13 * CC);
    int k0 = kg * 8;
    int t = threadIdx.x;
    int g = t / 48;
    int u48 = t % 48;
    int res = (g == 0) ? 0 : (g == 1) ? 2 : (g == 2) ? 1 : 3;
    u64 re2[4], im2[4];
    #pragma unroll
    for (int q = 0; q < 4; q++) { re2[q] = 0ull; im2[q] = 0ull; }
    const float* fR = g_fd + (size_t)(b*CH2 + 2*c)*HW2;
    const float* fI = g_fd + (size_t)(b*CH2 + 2*c + 1)*HW2;
    __shared__ __align__(8) float sre[32*8];
    __shared__ __align__(8) float sim[32*8];
    for (int mc = 0; mc < 6; mc++) {
        for (int i = threadIdx.x; i < 32*8; i += 192) {
            int mm = mc*32 + i/8, kk = i % 8;
            float2 v = make_float2(0.f, 0.f);
            if (k0 + kk < NW2) {
                v.x = fR[mm*NW2 + k0 + kk];
                v.y = fI[mm*NW2 + k0 + kk];
            }
            sre[i] = v.x; sim[i] = v.y;
        }
        __syncthreads();
        for (int mi = res; mi < 32; mi += 4) {
            int mm = mc*32 + mi;
            int trow = mm - res;
            float tc = g_tabc[trow*HH + u48], ts = g_tabs[trow*HH + u48];
            u64 tcc = pk2(tc, tc), tss = pk2(ts, ts), mtss = pk2(-ts, -ts);
            const u64* pr = (const u64*)&sre[mi*8];
            const u64* pi = (const u64*)&sim[mi*8];
            #pragma unroll
            for (int q = 0; q < 4; q++) {
                u64 fx = pr[q], fy = pi[q];
                re2[q] = ffma2(fx, tcc,  re2[q]);
                re2[q] = ffma2(fy, tss,  re2[q]);
                im2[q] = ffma2(fy, tcc,  im2[q]);
                im2[q] = ffma2(fx, mtss, im2[q]);
            }
        }
        __syncthreads();
    }
    __shared__ float2 S[192][8];
    #pragma unroll
    for (int q = 0; q < 4; q++) {
        float2 fr = upk2(re2[q]), fi = upk2(im2[q]);
        S[t][2*q]   = make_float2(fr.x, fi.x);
        S[t][2*q+1] = make_float2(fr.y, fi.y);
    }
    __syncthreads();
    int m = t;
    int isO = (m >= 96);
    int u = isO ? m - 96 : m;
    int us = (u < 48) ? u : u - 48;
    float w96c = g_tabc[2*HH + u], w96s = g_tabs[2*HH + u];
    float w1c  = g_tabc[HH + u],   w1s  = g_tabs[HH + u];
    float sgn = isO ? -1.f : 1.f;
    for (int kk = 0; kk < 8; kk++) {
        int k = k0 + kk;
        if (k >= NW2) break;
        float2 EE = S[us][kk], EO = S[48+us][kk], OE = S[96+us][kk], OO = S[144+us][kk];
        // conj(w96): (c, -s)
        float Ex = EE.x + (EO.x*w96c + EO.y*w96s);
        float Ey = EE.y + (EO.y*w96c - EO.x*w96s);
        float Ox = OE.x + (OO.x*w96c + OO.y*w96s);
        float Oy = OE.y + (OO.y*w96c - OO.x*w96s);
        float Xr = Ex + sgn*(Ox*w1c + Oy*w1s);
        float Xi = Ey + sgn*(Oy*w1c - Ox*w1s);
        size_t o = (((size_t)(b*CC + c)*HH + m)*NW2 + k)*2;
        g_gh[o]   = Xr;
        g_gh[o+1] = Xi;
    }
}

// ---------------- irfft over W: transposed smem stage [k][r], packed twiddle + add xc ----------------
__global__ void k_final(float* __restrict__ out) {
    int blk = blockIdx.x;
    int hg = blk % 24;
    int c  = (blk / 24) % CC;
    int b  = blk / (24 * CC);
    int h0 = hg * 8;
    __shared__ __align__(16) float2 ghd[NW2][10];   // [k][r], pitch 10 (16B aligned)
    const float2* ghp = (const float2*)g_gh;
    for (int i = threadIdx.x; i < 8*NW2; i += 192) {
        int r = i / NW2, k = i % NW2;
        ghd[k][r] = ghp[((size_t)(b*CC + c)*HH + h0 + r)*NW2 + k];
    }
    __syncthreads();
    int w = threadIdx.x;
    u64 acc2[8];
    #pragma unroll
    for (int r = 0; r < 8; r++) acc2[r] = 0ull;
    const u64* t2 = (const u64*)g_tab2;
    for (int k = 1; k < 96; k++) {
        u64 tt = t2[k*HH + w];
        const ulonglong2* gp = (const ulonglong2*)&ghd[k][0];
        #pragma unroll
        for (int q = 0; q < 4; q++) {
            ulonglong2 gg = gp[q];
            acc2[2*q]   = ffma2(gg.x, tt, acc2[2*q]);
            acc2[2*q+1] = ffma2(gg.y, tt, acc2[2*q+1]);
        }
    }
    float par = (w & 1) ? -1.0f : 1.0f;
    const float* xcb2 = g_xn + ((size_t)b*CC + c)*HWP + (size_t)h0*WWD + w;
    #pragma unroll
    for (int r = 0; r < 8; r++) {
        float2 f = upk2(acc2[r]);
        float of = (ghd[0][r].x + ghd[96][r].x*par + 2.0f*(f.x + f.y)) * (1.0f/192.0f);
        out[((size_t)b*CC + c)*HWP + (size_t)(h0 + r)*WWD + w] = xcb2[r*WWD] + of;
    }
}

// ---------------- launch ----------------
extern "C" void kernel_launch(void* const* d_in, const int* in_sizes, int n_in,
                              void* d_out, int out_size) {
    const float* x    = (const float*)d_in[0];
    const float* cdw  = (const float*)d_in[1];
    const float* lng  = (const float*)d_in[2];
    const float* lnb  = (const float*)d_in[3];
    const float* qw   = (const float*)d_in[4];
    const float* kw   = (const float*)d_in[5];
    const float* vw   = (const float*)d_in[6];
    const float* spw  = (const float*)d_in[7];
    const float* lw   = (const float*)d_in[8];
    const float* lb   = (const float*)d_in[9];
    const float* bng  = (const float*)d_in[10];
    const float* bnb  = (const float*)d_in[11];
    const float* fpew = (const float*)d_in[12];
    const float* fpeb = (const float*)d_in[13];
    const float* fdcw = (const float*)d_in[16];
    const float* fdcb = (const float*)d_in[17];
    const float* xcw  = (const float*)d_in[18];
    const float* xcb  = (const float*)d_in[19];
    const float* bn2g = (const float*)d_in[20];
    const float* bn2b = (const float*)d_in[21];
    float* out = (float*)d_out;

    k_tab<<<144, 256>>>();
    k_cdsum<<<16, 256>>>(cdw);
    k_nop<<<1, 32>>>();                       // keep ncu slot on k_contrast
    k_contrast<<<BB*4*96, 192>>>(x, cdw);
    k_centinit<<<144, 256>>>(x);
    k_centsq<<<5, 128>>>();
    k_dist<<<288, 256>>>(x);
    k_asum<<<36, 256>>>();
    k_centupd<<<144, 256>>>(x);
    k_centsq<<<5, 128>>>();
    k_dist<<<288, 256>>>(x);
    k_asum<<<36, 256>>>();
    k_lnorm<<<144, 256>>>(x, lng, lnb);
    k_stoken<<<72, 256>>>();
    k_stokmm<<<72, 256>>>(spw);
    k_qkv<<<BB*12*72, 256>>>(qw, kw, vw);
    k_lepe<<<BB*576, 256>>>(lw, lb);
    k_sattn<<<BB*NHD*(NSS/STILE), 256>>>();
    k_xattn<<<BB*NHD*72, 256>>>(x);
    k_xc<<<BB*4*72, 256>>>(xcw, xcb, bn2g, bn2b);
    k_fftw<<<BB*CC*12, 192>>>();
    k_ffth<<<BB*CC*13, 192>>>(bng, bnb);
    k_fpe<<<BB*CH2*6, 256>>>(fpew, fpeb);
    k_fdc<<<BB*8*37, 256>>>(fdcw, fdcb);
    k_invh<<<BB*CC*13, 192>>>();
    k_final<<<BB*CC*24, 192>>>(out);
}